// round 9
// baseline (speedup 1.0000x reference)
#include <cuda_runtime.h>
#include <math.h>

// ---------------- problem constants ----------------
#define NN   50000
#define NE   1600000
#define EPAD (NE + NN)
#define NF   512
#define H1   8
#define C1   16
#define HC1  128
#define C2   16

// ---------------- scratch (device globals) ----------------
__device__ float g_h1[NN * HC1];
__device__ float g_as1[NN * H1];
__device__ float g_ad1[NN * H1];
__device__ float g_out1[NN * HC1];
__device__ float g_h2[NN * C2];
__device__ float g_as2[NN];
__device__ float g_ad2[NN];
__device__ float g_out2[NN * C2];
__device__ int   g_cnt[NN];
__device__ int   g_rowptr[NN + 1];
__device__ int   g_cursor[NN];
__device__ int   g_col[EPAD];

// ================= CSR build =================
__global__ void fill_int(int* p, int v, int n) {
    int i = blockIdx.x * blockDim.x + threadIdx.x;
    if (i < n) p[i] = v;
}

__global__ void count_dst(const int* __restrict__ ei, int* __restrict__ cnt, int E) {
    int e = blockIdx.x * blockDim.x + threadIdx.x;
    if (e < E) atomicAdd(&cnt[ei[E + e]], 1);
}

// single-block exclusive scan over NN counts -> rowptr[NN+1] and cursor[NN]
__global__ void scan_rowptr(const int* __restrict__ cnt, int* __restrict__ rowptr,
                            int* __restrict__ cursor) {
    __shared__ int ssum[1024];
    const int T = 1024;
    const int PER = (NN + T - 1) / T;
    int tid = threadIdx.x;
    int start = tid * PER;
    int local = 0;
    for (int i = 0; i < PER; i++) {
        int idx = start + i;
        if (idx < NN) local += cnt[idx];
    }
    ssum[tid] = local;
    __syncthreads();
    for (int off = 1; off < T; off <<= 1) {
        int v = (tid >= off) ? ssum[tid - off] : 0;
        __syncthreads();
        ssum[tid] += v;
        __syncthreads();
    }
    int run = (tid == 0) ? 0 : ssum[tid - 1];
    for (int i = 0; i < PER; i++) {
        int idx = start + i;
        if (idx < NN) { rowptr[idx] = run; cursor[idx] = run; run += cnt[idx]; }
    }
    if (tid == T - 1) rowptr[NN] = ssum[T - 1];
}

__global__ void scatter_edges(const int* __restrict__ ei, int* __restrict__ cursor,
                              int* __restrict__ col, int E) {
    int i = blockIdx.x * blockDim.x + threadIdx.x;
    int tot = E + NN;
    if (i >= tot) return;
    int s, d;
    if (i < E) { s = ei[i]; d = ei[E + i]; } else { s = d = i - E; }
    int pos = atomicAdd(&cursor[d], 1);
    col[pos] = s;
}

// ================= SGEMM (NT) with register prefetch =================
#define GBM 128
#define GBN 128
#define GBK 8

__global__ __launch_bounds__(256, 2)
void gemm_nt(const float* __restrict__ A, const float* __restrict__ B,
             float* __restrict__ C, int M, int Nn, int K) {
    __shared__ float As[GBK][GBM];
    __shared__ float Bs[GBK][GBN];
    int t = threadIdx.x;
    int tx = t & 15, ty = t >> 4;
    int m0 = blockIdx.y * GBM, n0 = blockIdx.x * GBN;
    int lrow = t >> 1;
    int lk = (t & 1) * 4;

    float acc[8][8];
    #pragma unroll
    for (int i = 0; i < 8; i++)
        #pragma unroll
        for (int j = 0; j < 8; j++) acc[i][j] = 0.f;

    int am = m0 + lrow;
    int bn = n0 + lrow;
    const float* Ap = (am < M) ? &A[(size_t)am * K + lk] : nullptr;
    const float* Bp = (bn < Nn) ? &B[(size_t)bn * K + lk] : nullptr;

    float4 av = Ap ? *reinterpret_cast<const float4*>(Ap) : make_float4(0,0,0,0);
    float4 bv = Bp ? *reinterpret_cast<const float4*>(Bp) : make_float4(0,0,0,0);

    for (int k0 = 0; k0 < K; k0 += GBK) {
        As[lk + 0][lrow] = av.x; As[lk + 1][lrow] = av.y;
        As[lk + 2][lrow] = av.z; As[lk + 3][lrow] = av.w;
        Bs[lk + 0][lrow] = bv.x; Bs[lk + 1][lrow] = bv.y;
        Bs[lk + 2][lrow] = bv.z; Bs[lk + 3][lrow] = bv.w;
        __syncthreads();
        // prefetch next tile
        if (k0 + GBK < K) {
            av = Ap ? *reinterpret_cast<const float4*>(Ap + k0 + GBK) : make_float4(0,0,0,0);
            bv = Bp ? *reinterpret_cast<const float4*>(Bp + k0 + GBK) : make_float4(0,0,0,0);
        }
        #pragma unroll
        for (int k = 0; k < GBK; k++) {
            float a[8], b[8];
            float4 a0 = *reinterpret_cast<const float4*>(&As[k][ty * 8]);
            float4 a1 = *reinterpret_cast<const float4*>(&As[k][ty * 8 + 4]);
            float4 b0 = *reinterpret_cast<const float4*>(&Bs[k][tx * 8]);
            float4 b1 = *reinterpret_cast<const float4*>(&Bs[k][tx * 8 + 4]);
            a[0]=a0.x;a[1]=a0.y;a[2]=a0.z;a[3]=a0.w;a[4]=a1.x;a[5]=a1.y;a[6]=a1.z;a[7]=a1.w;
            b[0]=b0.x;b[1]=b0.y;b[2]=b0.z;b[3]=b0.w;b[4]=b1.x;b[5]=b1.y;b[6]=b1.z;b[7]=b1.w;
            #pragma unroll
            for (int i = 0; i < 8; i++)
                #pragma unroll
                for (int j = 0; j < 8; j++) acc[i][j] += a[i] * b[j];
        }
        __syncthreads();
    }
    #pragma unroll
    for (int i = 0; i < 8; i++) {
        int m = m0 + ty * 8 + i;
        if (m >= M) continue;
        #pragma unroll
        for (int j = 0; j < 8; j++) {
            int n = n0 + tx * 8 + j;
            if (n < Nn) C[(size_t)m * Nn + n] = acc[i][j];
        }
    }
}

// ================= attention coefficients (C=16, float4) =================
template<int H>
__global__ void att_kernel(const float* __restrict__ h, const float* __restrict__ att_s,
                           const float* __restrict__ att_d, float* __restrict__ as_,
                           float* __restrict__ ad_) {
    int idx = blockIdx.x * blockDim.x + threadIdx.x;
    if (idx >= NN * H) return;
    int hh = idx & (H - 1);
    const float4* hp = reinterpret_cast<const float4*>(h) + (size_t)idx * 4;
    const float4* sp = reinterpret_cast<const float4*>(att_s) + hh * 4;
    const float4* dp = reinterpret_cast<const float4*>(att_d) + hh * 4;
    float s = 0.f, d = 0.f;
    #pragma unroll
    for (int q = 0; q < 4; q++) {
        float4 v = hp[q], a = sp[q], b = dp[q];
        s += v.x * a.x + v.y * a.y + v.z * a.z + v.w * a.w;
        d += v.x * b.x + v.y * b.y + v.z * b.z + v.w * b.w;
    }
    as_[idx] = s;
    ad_[idx] = d;
}

// ================= layer-1 fused aggregate: one warp per dst, all 8 heads =================
__global__ __launch_bounds__(256)
void gat_aggregate_l1(const int* __restrict__ rowptr, const int* __restrict__ col,
                      const float* __restrict__ as_, const float* __restrict__ ad_,
                      const float* __restrict__ hfeat, const float* __restrict__ bias,
                      float* __restrict__ out) {
    int warp = (blockIdx.x * blockDim.x + threadIdx.x) >> 5;
    int lane = threadIdx.x & 31;
    if (warp >= NN) return;
    int dst = warp;
    int beg = rowptr[dst], end = rowptr[dst + 1];

    // per-dst attention offsets (uniform across warp)
    const float4* ad4 = reinterpret_cast<const float4*>(ad_) + (size_t)dst * 2;
    float4 adl = ad4[0], adh = ad4[1];
    float ad[8] = {adl.x, adl.y, adl.z, adl.w, adh.x, adh.y, adh.z, adh.w};

    const float4* as4 = reinterpret_cast<const float4*>(as_);

    // ---- sweep 1: online softmax (m, s) for all 8 heads ----
    float m[8], s[8];
    #pragma unroll
    for (int h = 0; h < 8; h++) { m[h] = -INFINITY; s[h] = 0.f; }

    for (int i = beg + lane; i < end; i += 32) {
        int src = col[i];
        float4 a0 = as4[(size_t)src * 2];
        float4 a1 = as4[(size_t)src * 2 + 1];
        float av[8] = {a0.x, a0.y, a0.z, a0.w, a1.x, a1.y, a1.z, a1.w};
        #pragma unroll
        for (int h = 0; h < 8; h++) {
            float v = av[h] + ad[h];
            v = v > 0.f ? v : 0.2f * v;
            float nm = fmaxf(m[h], v);
            s[h] = s[h] * __expf(m[h] - nm) + __expf(v - nm);  // m=-inf -> exp(-inf)=0, safe
            m[h] = nm;
        }
    }
    // warp butterfly combine (nan-safe for empty lanes)
    #pragma unroll
    for (int o = 16; o > 0; o >>= 1) {
        #pragma unroll
        for (int h = 0; h < 8; h++) {
            float om = __shfl_xor_sync(0xffffffffu, m[h], o);
            float os = __shfl_xor_sync(0xffffffffu, s[h], o);
            float nm = fmaxf(m[h], om);
            float e1 = (m[h] == nm) ? 1.f : __expf(m[h] - nm);
            float e2 = (om == nm)   ? 1.f : __expf(om - nm);
            s[h] = s[h] * e1 + os * e2;
            m[h] = nm;
        }
    }

    // lane-specific head selection (unrolled predicated, avoids spill)
    int myh = lane >> 2;
    float mh = m[0], sh = s[0], adhd = ad[0];
    #pragma unroll
    for (int h = 1; h < 8; h++)
        if (myh == h) { mh = m[h]; sh = s[h]; adhd = ad[h]; }
    float inv = 1.f / (sh + 1e-16f);

    // ---- sweep 2: weighted aggregate, lane owns channels [lane*4, lane*4+4) ----
    const float4* h4 = reinterpret_cast<const float4*>(hfeat);
    float4 acc = make_float4(0.f, 0.f, 0.f, 0.f);
    for (int i = beg; i < end; i++) {
        int src = col[i];
        float v = as_[src * 8 + myh] + adhd;
        v = v > 0.f ? v : 0.2f * v;
        float w = __expf(v - mh);
        float4 hv = h4[(size_t)src * 32 + lane];
        acc.x += w * hv.x; acc.y += w * hv.y; acc.z += w * hv.z; acc.w += w * hv.w;
    }
    const float4* b4 = reinterpret_cast<const float4*>(bias);
    float4 bb = b4[lane];
    float4 r;
    r.x = acc.x * inv + bb.x; r.y = acc.y * inv + bb.y;
    r.z = acc.z * inv + bb.z; r.w = acc.w * inv + bb.w;
    r.x = r.x > 0.f ? r.x : expm1f(r.x);
    r.y = r.y > 0.f ? r.y : expm1f(r.y);
    r.z = r.z > 0.f ? r.z : expm1f(r.z);
    r.w = r.w > 0.f ? r.w : expm1f(r.w);
    reinterpret_cast<float4*>(out)[(size_t)dst * 32 + lane] = r;
}

// ================= layer-2 aggregate: one warp per dst, H=1, C=16 =================
__global__ __launch_bounds__(256)
void gat_aggregate_l2(const int* __restrict__ rowptr, const int* __restrict__ col,
                      const float* __restrict__ as_, const float* __restrict__ ad_,
                      const float* __restrict__ hfeat, float* __restrict__ out) {
    int warp = (blockIdx.x * blockDim.x + threadIdx.x) >> 5;
    int lane = threadIdx.x & 31;
    if (warp >= NN) return;
    int dst = warp;
    int beg = rowptr[dst], end = rowptr[dst + 1];
    float adv = ad_[dst];

    // online softmax
    float m = -INFINITY, s = 0.f;
    for (int i = beg + lane; i < end; i += 32) {
        float v = as_[col[i]] + adv;
        v = v > 0.f ? v : 0.2f * v;
        float nm = fmaxf(m, v);
        s = s * __expf(m - nm) + __expf(v - nm);
        m = nm;
    }
    #pragma unroll
    for (int o = 16; o > 0; o >>= 1) {
        float om = __shfl_xor_sync(0xffffffffu, m, o);
        float os = __shfl_xor_sync(0xffffffffu, s, o);
        float nm = fmaxf(m, om);
        float e1 = (m == nm) ? 1.f : __expf(m - nm);
        float e2 = (om == nm) ? 1.f : __expf(om - nm);
        s = s * e1 + os * e2;
        m = nm;
    }
    float inv = 1.f / (s + 1e-16f);

    // aggregate: 2 edges/iter, 16 channels
    int c = lane & 15;
    int sub = lane >> 4;
    float acc = 0.f;
    for (int i = beg + sub; i < end; i += 2) {
        int src = col[i];
        float v = as_[src] + adv;
        v = v > 0.f ? v : 0.2f * v;
        float w = __expf(v - m);
        acc += w * hfeat[(size_t)src * 16 + c];
    }
    acc += __shfl_down_sync(0xffffffffu, acc, 16);
    if (lane < 16) out[(size_t)dst * 16 + c] = acc * inv;
}

// ================= final bias + log_softmax =================
__global__ void final_lsm(const float* __restrict__ in, const float* __restrict__ b,
                          float* __restrict__ out, int N) {
    int n = blockIdx.x * blockDim.x + threadIdx.x;
    if (n >= N) return;
    float v[C2];
    float m = -INFINITY;
    #pragma unroll
    for (int c = 0; c < C2; c++) {
        v[c] = in[(size_t)n * C2 + c] + b[c];
        m = fmaxf(m, v[c]);
    }
    float s = 0.f;
    #pragma unroll
    for (int c = 0; c < C2; c++) s += __expf(v[c] - m);
    float l = __logf(s);
    #pragma unroll
    for (int c = 0; c < C2; c++) out[(size_t)n * C2 + c] = v[c] - m - l;
}

// ================= launch =================
extern "C" void kernel_launch(void* const* d_in, const int* in_sizes, int n_in,
                              void* d_out, int out_size) {
    const float* x    = (const float*)d_in[0];
    const int*   ei   = (const int*)d_in[1];
    const float* W1   = (const float*)d_in[2];
    const float* at1s = (const float*)d_in[3];
    const float* at1d = (const float*)d_in[4];
    const float* b1   = (const float*)d_in[5];
    const float* W2   = (const float*)d_in[6];
    const float* at2s = (const float*)d_in[7];
    const float* at2d = (const float*)d_in[8];
    const float* b2   = (const float*)d_in[9];
    float* out = (float*)d_out;

    int E = in_sizes[1] / 2;

    static float *p_h1 = nullptr, *p_as1, *p_ad1, *p_out1, *p_h2, *p_as2, *p_ad2, *p_out2;
    static int *p_cnt, *p_rowptr, *p_cursor, *p_col;
    if (!p_h1) {
        cudaGetSymbolAddress((void**)&p_h1, g_h1);
        cudaGetSymbolAddress((void**)&p_as1, g_as1);
        cudaGetSymbolAddress((void**)&p_ad1, g_ad1);
        cudaGetSymbolAddress((void**)&p_out1, g_out1);
        cudaGetSymbolAddress((void**)&p_h2, g_h2);
        cudaGetSymbolAddress((void**)&p_as2, g_as2);
        cudaGetSymbolAddress((void**)&p_ad2, g_ad2);
        cudaGetSymbolAddress((void**)&p_out2, g_out2);
        cudaGetSymbolAddress((void**)&p_cnt, g_cnt);
        cudaGetSymbolAddress((void**)&p_rowptr, g_rowptr);
        cudaGetSymbolAddress((void**)&p_cursor, g_cursor);
        cudaGetSymbolAddress((void**)&p_col, g_col);
    }

    const int TB = 256;
    auto blocks = [](int n, int tb) { return (n + tb - 1) / tb; };

    // ---- CSR build ----
    fill_int<<<blocks(NN, TB), TB>>>(p_cnt, 1, NN);
    count_dst<<<blocks(E, TB), TB>>>(ei, p_cnt, E);
    scan_rowptr<<<1, 1024>>>(p_cnt, p_rowptr, p_cursor);
    scatter_edges<<<blocks(E + NN, TB), TB>>>(ei, p_cursor, p_col, E);

    // ---- layer 1 ----
    {
        dim3 grid((HC1 + GBN - 1) / GBN, (NN + GBM - 1) / GBM);
        gemm_nt<<<grid, 256>>>(x, W1, p_h1, NN, HC1, NF);
    }
    att_kernel<H1><<<blocks(NN * H1, TB), TB>>>(p_h1, at1s, at1d, p_as1, p_ad1);
    gat_aggregate_l1<<<blocks(NN * 32, TB), TB>>>(p_rowptr, p_col, p_as1, p_ad1, p_h1, b1, p_out1);

    // ---- layer 2 ----
    {
        dim3 grid((C2 + GBN - 1) / GBN, (NN + GBM - 1) / GBM);
        gemm_nt<<<grid, 256>>>(p_out1, W2, p_h2, NN, C2, HC1);
    }
    att_kernel<1><<<blocks(NN, TB), TB>>>(p_h2, at2s, at2d, p_as2, p_ad2);
    gat_aggregate_l2<<<blocks(NN * 32, TB), TB>>>(p_rowptr, p_col, p_as2, p_ad2, p_h2, p_out2);

    // ---- log_softmax ----
    final_lsm<<<blocks(NN, TB), TB>>>(p_out2, b2, out, NN);
}

// round 10
// speedup vs baseline: 1.0011x; 1.0011x over previous
#include <cuda_runtime.h>
#include <math.h>

// ---------------- problem constants ----------------
#define NN   50000
#define NE   1600000
#define EPAD (NE + NN)
#define NF   512
#define H1   8
#define C1   16
#define HC1  128
#define C2   16

// ---------------- scratch (device globals) ----------------
__device__ float g_h1[NN * HC1];
__device__ float g_as1[NN * H1];
__device__ float g_ad1[NN * H1];
__device__ float g_out1[NN * HC1];
__device__ float g_h2[NN * C2];
__device__ float g_as2[NN];
__device__ float g_ad2[NN];
__device__ float g_out2[NN * C2];
__device__ int   g_cnt[NN];
__device__ int   g_rowptr[NN + 1];
__device__ int   g_cursor[NN];
__device__ int   g_col[EPAD];

// ================= CSR build =================
__global__ void fill_int(int* p, int v, int n) {
    int i = blockIdx.x * blockDim.x + threadIdx.x;
    if (i < n) p[i] = v;
}

__global__ void count_dst(const int* __restrict__ ei, int* __restrict__ cnt, int E) {
    int e = blockIdx.x * blockDim.x + threadIdx.x;
    if (e < E) atomicAdd(&cnt[ei[E + e]], 1);
}

// single-block exclusive scan over NN counts -> rowptr[NN+1] and cursor[NN]
__global__ void scan_rowptr(const int* __restrict__ cnt, int* __restrict__ rowptr,
                            int* __restrict__ cursor) {
    __shared__ int ssum[1024];
    const int T = 1024;
    const int PER = (NN + T - 1) / T;
    int tid = threadIdx.x;
    int start = tid * PER;
    int local = 0;
    for (int i = 0; i < PER; i++) {
        int idx = start + i;
        if (idx < NN) local += cnt[idx];
    }
    ssum[tid] = local;
    __syncthreads();
    for (int off = 1; off < T; off <<= 1) {
        int v = (tid >= off) ? ssum[tid - off] : 0;
        __syncthreads();
        ssum[tid] += v;
        __syncthreads();
    }
    int run = (tid == 0) ? 0 : ssum[tid - 1];
    for (int i = 0; i < PER; i++) {
        int idx = start + i;
        if (idx < NN) { rowptr[idx] = run; cursor[idx] = run; run += cnt[idx]; }
    }
    if (tid == T - 1) rowptr[NN] = ssum[T - 1];
}

__global__ void scatter_edges(const int* __restrict__ ei, int* __restrict__ cursor,
                              int* __restrict__ col, int E) {
    int i = blockIdx.x * blockDim.x + threadIdx.x;
    int tot = E + NN;
    if (i >= tot) return;
    int s, d;
    if (i < E) { s = ei[i]; d = ei[E + i]; } else { s = d = i - E; }
    int pos = atomicAdd(&cursor[d], 1);
    col[pos] = s;
}

// ================= SGEMM (NT) with register prefetch =================
#define GBM 128
#define GBN 128
#define GBK 8

__global__ __launch_bounds__(256, 2)
void gemm_nt(const float* __restrict__ A, const float* __restrict__ B,
             float* __restrict__ C, int M, int Nn, int K) {
    __shared__ float As[GBK][GBM];
    __shared__ float Bs[GBK][GBN];
    int t = threadIdx.x;
    int tx = t & 15, ty = t >> 4;
    int m0 = blockIdx.y * GBM, n0 = blockIdx.x * GBN;
    int lrow = t >> 1;
    int lk = (t & 1) * 4;

    float acc[8][8];
    #pragma unroll
    for (int i = 0; i < 8; i++)
        #pragma unroll
        for (int j = 0; j < 8; j++) acc[i][j] = 0.f;

    int am = m0 + lrow;
    int bn = n0 + lrow;
    const float* Ap = (am < M) ? &A[(size_t)am * K + lk] : nullptr;
    const float* Bp = (bn < Nn) ? &B[(size_t)bn * K + lk] : nullptr;

    float4 av = Ap ? *reinterpret_cast<const float4*>(Ap) : make_float4(0,0,0,0);
    float4 bv = Bp ? *reinterpret_cast<const float4*>(Bp) : make_float4(0,0,0,0);

    for (int k0 = 0; k0 < K; k0 += GBK) {
        As[lk + 0][lrow] = av.x; As[lk + 1][lrow] = av.y;
        As[lk + 2][lrow] = av.z; As[lk + 3][lrow] = av.w;
        Bs[lk + 0][lrow] = bv.x; Bs[lk + 1][lrow] = bv.y;
        Bs[lk + 2][lrow] = bv.z; Bs[lk + 3][lrow] = bv.w;
        __syncthreads();
        // prefetch next tile
        if (k0 + GBK < K) {
            av = Ap ? *reinterpret_cast<const float4*>(Ap + k0 + GBK) : make_float4(0,0,0,0);
            bv = Bp ? *reinterpret_cast<const float4*>(Bp + k0 + GBK) : make_float4(0,0,0,0);
        }
        #pragma unroll
        for (int k = 0; k < GBK; k++) {
            float a[8], b[8];
            float4 a0 = *reinterpret_cast<const float4*>(&As[k][ty * 8]);
            float4 a1 = *reinterpret_cast<const float4*>(&As[k][ty * 8 + 4]);
            float4 b0 = *reinterpret_cast<const float4*>(&Bs[k][tx * 8]);
            float4 b1 = *reinterpret_cast<const float4*>(&Bs[k][tx * 8 + 4]);
            a[0]=a0.x;a[1]=a0.y;a[2]=a0.z;a[3]=a0.w;a[4]=a1.x;a[5]=a1.y;a[6]=a1.z;a[7]=a1.w;
            b[0]=b0.x;b[1]=b0.y;b[2]=b0.z;b[3]=b0.w;b[4]=b1.x;b[5]=b1.y;b[6]=b1.z;b[7]=b1.w;
            #pragma unroll
            for (int i = 0; i < 8; i++)
                #pragma unroll
                for (int j = 0; j < 8; j++) acc[i][j] += a[i] * b[j];
        }
        __syncthreads();
    }
    #pragma unroll
    for (int i = 0; i < 8; i++) {
        int m = m0 + ty * 8 + i;
        if (m >= M) continue;
        #pragma unroll
        for (int j = 0; j < 8; j++) {
            int n = n0 + tx * 8 + j;
            if (n < Nn) C[(size_t)m * Nn + n] = acc[i][j];
        }
    }
}

// ================= attention coefficients (C=16, float4) =================
template<int H>
__global__ void att_kernel(const float* __restrict__ h, const float* __restrict__ att_s,
                           const float* __restrict__ att_d, float* __restrict__ as_,
                           float* __restrict__ ad_) {
    int idx = blockIdx.x * blockDim.x + threadIdx.x;
    if (idx >= NN * H) return;
    int hh = idx & (H - 1);
    const float4* hp = reinterpret_cast<const float4*>(h) + (size_t)idx * 4;
    const float4* sp = reinterpret_cast<const float4*>(att_s) + hh * 4;
    const float4* dp = reinterpret_cast<const float4*>(att_d) + hh * 4;
    float s = 0.f, d = 0.f;
    #pragma unroll
    for (int q = 0; q < 4; q++) {
        float4 v = hp[q], a = sp[q], b = dp[q];
        s += v.x * a.x + v.y * a.y + v.z * a.z + v.w * a.w;
        d += v.x * b.x + v.y * b.y + v.z * b.z + v.w * b.w;
    }
    as_[idx] = s;
    ad_[idx] = d;
}

// ================= layer-1 fused aggregate: one warp per dst, all 8 heads =================
__global__ __launch_bounds__(256)
void gat_aggregate_l1(const int* __restrict__ rowptr, const int* __restrict__ col,
                      const float* __restrict__ as_, const float* __restrict__ ad_,
                      const float* __restrict__ hfeat, const float* __restrict__ bias,
                      float* __restrict__ out) {
    int warp = (blockIdx.x * blockDim.x + threadIdx.x) >> 5;
    int lane = threadIdx.x & 31;
    if (warp >= NN) return;
    int dst = warp;
    int beg = rowptr[dst], end = rowptr[dst + 1];

    // per-dst attention offsets (uniform across warp)
    const float4* ad4 = reinterpret_cast<const float4*>(ad_) + (size_t)dst * 2;
    float4 adl = ad4[0], adh = ad4[1];
    float ad[8] = {adl.x, adl.y, adl.z, adl.w, adh.x, adh.y, adh.z, adh.w};

    const float4* as4 = reinterpret_cast<const float4*>(as_);

    // ---- sweep 1: online softmax (m, s) for all 8 heads ----
    float m[8], s[8];
    #pragma unroll
    for (int h = 0; h < 8; h++) { m[h] = -INFINITY; s[h] = 0.f; }

    for (int i = beg + lane; i < end; i += 32) {
        int src = col[i];
        float4 a0 = as4[(size_t)src * 2];
        float4 a1 = as4[(size_t)src * 2 + 1];
        float av[8] = {a0.x, a0.y, a0.z, a0.w, a1.x, a1.y, a1.z, a1.w};
        #pragma unroll
        for (int h = 0; h < 8; h++) {
            float v = av[h] + ad[h];
            v = v > 0.f ? v : 0.2f * v;
            float nm = fmaxf(m[h], v);
            s[h] = s[h] * __expf(m[h] - nm) + __expf(v - nm);  // m=-inf -> exp(-inf)=0, safe
            m[h] = nm;
        }
    }
    // warp butterfly combine (nan-safe for empty lanes)
    #pragma unroll
    for (int o = 16; o > 0; o >>= 1) {
        #pragma unroll
        for (int h = 0; h < 8; h++) {
            float om = __shfl_xor_sync(0xffffffffu, m[h], o);
            float os = __shfl_xor_sync(0xffffffffu, s[h], o);
            float nm = fmaxf(m[h], om);
            float e1 = (m[h] == nm) ? 1.f : __expf(m[h] - nm);
            float e2 = (om == nm)   ? 1.f : __expf(om - nm);
            s[h] = s[h] * e1 + os * e2;
            m[h] = nm;
        }
    }

    // lane-specific head selection (unrolled predicated, avoids spill)
    int myh = lane >> 2;
    float mh = m[0], sh = s[0], adhd = ad[0];
    #pragma unroll
    for (int h = 1; h < 8; h++)
        if (myh == h) { mh = m[h]; sh = s[h]; adhd = ad[h]; }
    float inv = 1.f / (sh + 1e-16f);

    // ---- sweep 2: weighted aggregate, lane owns channels [lane*4, lane*4+4) ----
    const float4* h4 = reinterpret_cast<const float4*>(hfeat);
    float4 acc = make_float4(0.f, 0.f, 0.f, 0.f);
    for (int i = beg; i < end; i++) {
        int src = col[i];
        float v = as_[src * 8 + myh] + adhd;
        v = v > 0.f ? v : 0.2f * v;
        float w = __expf(v - mh);
        float4 hv = h4[(size_t)src * 32 + lane];
        acc.x += w * hv.x; acc.y += w * hv.y; acc.z += w * hv.z; acc.w += w * hv.w;
    }
    const float4* b4 = reinterpret_cast<const float4*>(bias);
    float4 bb = b4[lane];
    float4 r;
    r.x = acc.x * inv + bb.x; r.y = acc.y * inv + bb.y;
    r.z = acc.z * inv + bb.z; r.w = acc.w * inv + bb.w;
    r.x = r.x > 0.f ? r.x : expm1f(r.x);
    r.y = r.y > 0.f ? r.y : expm1f(r.y);
    r.z = r.z > 0.f ? r.z : expm1f(r.z);
    r.w = r.w > 0.f ? r.w : expm1f(r.w);
    reinterpret_cast<float4*>(out)[(size_t)dst * 32 + lane] = r;
}

// ================= layer-2 aggregate: one warp per dst, H=1, C=16 =================
__global__ __launch_bounds__(256)
void gat_aggregate_l2(const int* __restrict__ rowptr, const int* __restrict__ col,
                      const float* __restrict__ as_, const float* __restrict__ ad_,
                      const float* __restrict__ hfeat, float* __restrict__ out) {
    int warp = (blockIdx.x * blockDim.x + threadIdx.x) >> 5;
    int lane = threadIdx.x & 31;
    if (warp >= NN) return;
    int dst = warp;
    int beg = rowptr[dst], end = rowptr[dst + 1];
    float adv = ad_[dst];

    // online softmax
    float m = -INFINITY, s = 0.f;
    for (int i = beg + lane; i < end; i += 32) {
        float v = as_[col[i]] + adv;
        v = v > 0.f ? v : 0.2f * v;
        float nm = fmaxf(m, v);
        s = s * __expf(m - nm) + __expf(v - nm);
        m = nm;
    }
    #pragma unroll
    for (int o = 16; o > 0; o >>= 1) {
        float om = __shfl_xor_sync(0xffffffffu, m, o);
        float os = __shfl_xor_sync(0xffffffffu, s, o);
        float nm = fmaxf(m, om);
        float e1 = (m == nm) ? 1.f : __expf(m - nm);
        float e2 = (om == nm) ? 1.f : __expf(om - nm);
        s = s * e1 + os * e2;
        m = nm;
    }
    float inv = 1.f / (s + 1e-16f);

    // aggregate: 2 edges/iter, 16 channels
    int c = lane & 15;
    int sub = lane >> 4;
    float acc = 0.f;
    for (int i = beg + sub; i < end; i += 2) {
        int src = col[i];
        float v = as_[src] + adv;
        v = v > 0.f ? v : 0.2f * v;
        float w = __expf(v - m);
        acc += w * hfeat[(size_t)src * 16 + c];
    }
    acc += __shfl_down_sync(0xffffffffu, acc, 16);
    if (lane < 16) out[(size_t)dst * 16 + c] = acc * inv;
}

// ================= final bias + log_softmax =================
__global__ void final_lsm(const float* __restrict__ in, const float* __restrict__ b,
                          float* __restrict__ out, int N) {
    int n = blockIdx.x * blockDim.x + threadIdx.x;
    if (n >= N) return;
    float v[C2];
    float m = -INFINITY;
    #pragma unroll
    for (int c = 0; c < C2; c++) {
        v[c] = in[(size_t)n * C2 + c] + b[c];
        m = fmaxf(m, v[c]);
    }
    float s = 0.f;
    #pragma unroll
    for (int c = 0; c < C2; c++) s += __expf(v[c] - m);
    float l = __logf(s);
    #pragma unroll
    for (int c = 0; c < C2; c++) out[(size_t)n * C2 + c] = v[c] - m - l;
}

// ================= launch =================
extern "C" void kernel_launch(void* const* d_in, const int* in_sizes, int n_in,
                              void* d_out, int out_size) {
    const float* x    = (const float*)d_in[0];
    const int*   ei   = (const int*)d_in[1];
    const float* W1   = (const float*)d_in[2];
    const float* at1s = (const float*)d_in[3];
    const float* at1d = (const float*)d_in[4];
    const float* b1   = (const float*)d_in[5];
    const float* W2   = (const float*)d_in[6];
    const float* at2s = (const float*)d_in[7];
    const float* at2d = (const float*)d_in[8];
    const float* b2   = (const float*)d_in[9];
    float* out = (float*)d_out;

    int E = in_sizes[1] / 2;

    static float *p_h1 = nullptr, *p_as1, *p_ad1, *p_out1, *p_h2, *p_as2, *p_ad2, *p_out2;
    static int *p_cnt, *p_rowptr, *p_cursor, *p_col;
    if (!p_h1) {
        cudaGetSymbolAddress((void**)&p_h1, g_h1);
        cudaGetSymbolAddress((void**)&p_as1, g_as1);
        cudaGetSymbolAddress((void**)&p_ad1, g_ad1);
        cudaGetSymbolAddress((void**)&p_out1, g_out1);
        cudaGetSymbolAddress((void**)&p_h2, g_h2);
        cudaGetSymbolAddress((void**)&p_as2, g_as2);
        cudaGetSymbolAddress((void**)&p_ad2, g_ad2);
        cudaGetSymbolAddress((void**)&p_out2, g_out2);
        cudaGetSymbolAddress((void**)&p_cnt, g_cnt);
        cudaGetSymbolAddress((void**)&p_rowptr, g_rowptr);
        cudaGetSymbolAddress((void**)&p_cursor, g_cursor);
        cudaGetSymbolAddress((void**)&p_col, g_col);
    }

    const int TB = 256;
    auto blocks = [](int n, int tb) { return (n + tb - 1) / tb; };

    // ---- CSR build ----
    fill_int<<<blocks(NN, TB), TB>>>(p_cnt, 1, NN);
    count_dst<<<blocks(E, TB), TB>>>(ei, p_cnt, E);
    scan_rowptr<<<1, 1024>>>(p_cnt, p_rowptr, p_cursor);
    scatter_edges<<<blocks(E + NN, TB), TB>>>(ei, p_cursor, p_col, E);

    // ---- layer 1 ----
    {
        dim3 grid((HC1 + GBN - 1) / GBN, (NN + GBM - 1) / GBM);
        gemm_nt<<<grid, 256>>>(x, W1, p_h1, NN, HC1, NF);
    }
    att_kernel<H1><<<blocks(NN * H1, TB), TB>>>(p_h1, at1s, at1d, p_as1, p_ad1);
    gat_aggregate_l1<<<blocks(NN * 32, TB), TB>>>(p_rowptr, p_col, p_as1, p_ad1, p_h1, b1, p_out1);

    // ---- layer 2 ----
    {
        dim3 grid((C2 + GBN - 1) / GBN, (NN + GBM - 1) / GBM);
        gemm_nt<<<grid, 256>>>(p_out1, W2, p_h2, NN, C2, HC1);
    }
    att_kernel<1><<<blocks(NN, TB), TB>>>(p_h2, at2s, at2d, p_as2, p_ad2);
    gat_aggregate_l2<<<blocks(NN * 32, TB), TB>>>(p_rowptr, p_col, p_as2, p_ad2, p_h2, p_out2);

    // ---- log_softmax ----
    final_lsm<<<blocks(NN, TB), TB>>>(p_out2, b2, out, NN);
}

// round 11
// speedup vs baseline: 1.0034x; 1.0023x over previous
#include <cuda_runtime.h>
#include <math.h>

// ---------------- problem constants ----------------
#define NN   50000
#define NE   1600000
#define EPAD (NE + NN)
#define NF   512
#define H1   8
#define C1   16
#define HC1  128
#define C2   16

// ---------------- scratch (device globals) ----------------
__device__ float g_h1[NN * HC1];
__device__ float g_as1[NN * H1];
__device__ float g_ad1[NN * H1];
__device__ float g_out1[NN * HC1];
__device__ float g_h2[NN * C2];
__device__ float g_as2[NN];
__device__ float g_ad2[NN];
__device__ float g_out2[NN * C2];
__device__ int   g_cnt[NN];
__device__ int   g_rowptr[NN + 1];
__device__ int   g_cursor[NN];
__device__ int   g_col[EPAD];

// ================= CSR build =================
__global__ void fill_int(int* p, int v, int n) {
    int i = blockIdx.x * blockDim.x + threadIdx.x;
    if (i < n) p[i] = v;
}

__global__ void count_dst(const int* __restrict__ ei, int* __restrict__ cnt, int E) {
    int e = blockIdx.x * blockDim.x + threadIdx.x;
    if (e < E) atomicAdd(&cnt[ei[E + e]], 1);
}

// single-block exclusive scan over NN counts -> rowptr[NN+1] and cursor[NN]
__global__ void scan_rowptr(const int* __restrict__ cnt, int* __restrict__ rowptr,
                            int* __restrict__ cursor) {
    __shared__ int ssum[1024];
    const int T = 1024;
    const int PER = (NN + T - 1) / T;
    int tid = threadIdx.x;
    int start = tid * PER;
    int local = 0;
    for (int i = 0; i < PER; i++) {
        int idx = start + i;
        if (idx < NN) local += cnt[idx];
    }
    ssum[tid] = local;
    __syncthreads();
    for (int off = 1; off < T; off <<= 1) {
        int v = (tid >= off) ? ssum[tid - off] : 0;
        __syncthreads();
        ssum[tid] += v;
        __syncthreads();
    }
    int run = (tid == 0) ? 0 : ssum[tid - 1];
    for (int i = 0; i < PER; i++) {
        int idx = start + i;
        if (idx < NN) { rowptr[idx] = run; cursor[idx] = run; run += cnt[idx]; }
    }
    if (tid == T - 1) rowptr[NN] = ssum[T - 1];
}

__global__ void scatter_edges(const int* __restrict__ ei, int* __restrict__ cursor,
                              int* __restrict__ col, int E) {
    int i = blockIdx.x * blockDim.x + threadIdx.x;
    int tot = E + NN;
    if (i >= tot) return;
    int s, d;
    if (i < E) { s = ei[i]; d = ei[E + i]; } else { s = d = i - E; }
    int pos = atomicAdd(&cursor[d], 1);
    col[pos] = s;
}

// ================= SGEMM (NT) with register prefetch =================
#define GBM 128
#define GBN 128
#define GBK 8

__global__ __launch_bounds__(256, 2)
void gemm_nt(const float* __restrict__ A, const float* __restrict__ B,
             float* __restrict__ C, int M, int Nn, int K) {
    __shared__ float As[GBK][GBM];
    __shared__ float Bs[GBK][GBN];
    int t = threadIdx.x;
    int tx = t & 15, ty = t >> 4;
    int m0 = blockIdx.y * GBM, n0 = blockIdx.x * GBN;
    int lrow = t >> 1;
    int lk = (t & 1) * 4;

    float acc[8][8];
    #pragma unroll
    for (int i = 0; i < 8; i++)
        #pragma unroll
        for (int j = 0; j < 8; j++) acc[i][j] = 0.f;

    int am = m0 + lrow;
    int bn = n0 + lrow;
    const float* Ap = (am < M) ? &A[(size_t)am * K + lk] : nullptr;
    const float* Bp = (bn < Nn) ? &B[(size_t)bn * K + lk] : nullptr;

    float4 av = Ap ? *reinterpret_cast<const float4*>(Ap) : make_float4(0,0,0,0);
    float4 bv = Bp ? *reinterpret_cast<const float4*>(Bp) : make_float4(0,0,0,0);

    for (int k0 = 0; k0 < K; k0 += GBK) {
        As[lk + 0][lrow] = av.x; As[lk + 1][lrow] = av.y;
        As[lk + 2][lrow] = av.z; As[lk + 3][lrow] = av.w;
        Bs[lk + 0][lrow] = bv.x; Bs[lk + 1][lrow] = bv.y;
        Bs[lk + 2][lrow] = bv.z; Bs[lk + 3][lrow] = bv.w;
        __syncthreads();
        // prefetch next tile
        if (k0 + GBK < K) {
            av = Ap ? *reinterpret_cast<const float4*>(Ap + k0 + GBK) : make_float4(0,0,0,0);
            bv = Bp ? *reinterpret_cast<const float4*>(Bp + k0 + GBK) : make_float4(0,0,0,0);
        }
        #pragma unroll
        for (int k = 0; k < GBK; k++) {
            float a[8], b[8];
            float4 a0 = *reinterpret_cast<const float4*>(&As[k][ty * 8]);
            float4 a1 = *reinterpret_cast<const float4*>(&As[k][ty * 8 + 4]);
            float4 b0 = *reinterpret_cast<const float4*>(&Bs[k][tx * 8]);
            float4 b1 = *reinterpret_cast<const float4*>(&Bs[k][tx * 8 + 4]);
            a[0]=a0.x;a[1]=a0.y;a[2]=a0.z;a[3]=a0.w;a[4]=a1.x;a[5]=a1.y;a[6]=a1.z;a[7]=a1.w;
            b[0]=b0.x;b[1]=b0.y;b[2]=b0.z;b[3]=b0.w;b[4]=b1.x;b[5]=b1.y;b[6]=b1.z;b[7]=b1.w;
            #pragma unroll
            for (int i = 0; i < 8; i++)
                #pragma unroll
                for (int j = 0; j < 8; j++) acc[i][j] += a[i] * b[j];
        }
        __syncthreads();
    }
    #pragma unroll
    for (int i = 0; i < 8; i++) {
        int m = m0 + ty * 8 + i;
        if (m >= M) continue;
        #pragma unroll
        for (int j = 0; j < 8; j++) {
            int n = n0 + tx * 8 + j;
            if (n < Nn) C[(size_t)m * Nn + n] = acc[i][j];
        }
    }
}

// ================= attention coefficients (C=16, float4) =================
template<int H>
__global__ void att_kernel(const float* __restrict__ h, const float* __restrict__ att_s,
                           const float* __restrict__ att_d, float* __restrict__ as_,
                           float* __restrict__ ad_) {
    int idx = blockIdx.x * blockDim.x + threadIdx.x;
    if (idx >= NN * H) return;
    int hh = idx & (H - 1);
    const float4* hp = reinterpret_cast<const float4*>(h) + (size_t)idx * 4;
    const float4* sp = reinterpret_cast<const float4*>(att_s) + hh * 4;
    const float4* dp = reinterpret_cast<const float4*>(att_d) + hh * 4;
    float s = 0.f, d = 0.f;
    #pragma unroll
    for (int q = 0; q < 4; q++) {
        float4 v = hp[q], a = sp[q], b = dp[q];
        s += v.x * a.x + v.y * a.y + v.z * a.z + v.w * a.w;
        d += v.x * b.x + v.y * b.y + v.z * b.z + v.w * b.w;
    }
    as_[idx] = s;
    ad_[idx] = d;
}

// ================= layer-1 fused aggregate: one warp per dst, all 8 heads =================
__global__ __launch_bounds__(256)
void gat_aggregate_l1(const int* __restrict__ rowptr, const int* __restrict__ col,
                      const float* __restrict__ as_, const float* __restrict__ ad_,
                      const float* __restrict__ hfeat, const float* __restrict__ bias,
                      float* __restrict__ out) {
    int warp = (blockIdx.x * blockDim.x + threadIdx.x) >> 5;
    int lane = threadIdx.x & 31;
    if (warp >= NN) return;
    int dst = warp;
    int beg = rowptr[dst], end = rowptr[dst + 1];

    // per-dst attention offsets (uniform across warp)
    const float4* ad4 = reinterpret_cast<const float4*>(ad_) + (size_t)dst * 2;
    float4 adl = ad4[0], adh = ad4[1];
    float ad[8] = {adl.x, adl.y, adl.z, adl.w, adh.x, adh.y, adh.z, adh.w};

    const float4* as4 = reinterpret_cast<const float4*>(as_);

    // ---- sweep 1: online softmax (m, s) for all 8 heads ----
    float m[8], s[8];
    #pragma unroll
    for (int h = 0; h < 8; h++) { m[h] = -INFINITY; s[h] = 0.f; }

    for (int i = beg + lane; i < end; i += 32) {
        int src = col[i];
        float4 a0 = as4[(size_t)src * 2];
        float4 a1 = as4[(size_t)src * 2 + 1];
        float av[8] = {a0.x, a0.y, a0.z, a0.w, a1.x, a1.y, a1.z, a1.w};
        #pragma unroll
        for (int h = 0; h < 8; h++) {
            float v = av[h] + ad[h];
            v = v > 0.f ? v : 0.2f * v;
            float nm = fmaxf(m[h], v);
            s[h] = s[h] * __expf(m[h] - nm) + __expf(v - nm);  // m=-inf -> exp(-inf)=0, safe
            m[h] = nm;
        }
    }
    // warp butterfly combine (nan-safe for empty lanes)
    #pragma unroll
    for (int o = 16; o > 0; o >>= 1) {
        #pragma unroll
        for (int h = 0; h < 8; h++) {
            float om = __shfl_xor_sync(0xffffffffu, m[h], o);
            float os = __shfl_xor_sync(0xffffffffu, s[h], o);
            float nm = fmaxf(m[h], om);
            float e1 = (m[h] == nm) ? 1.f : __expf(m[h] - nm);
            float e2 = (om == nm)   ? 1.f : __expf(om - nm);
            s[h] = s[h] * e1 + os * e2;
            m[h] = nm;
        }
    }

    // lane-specific head selection (unrolled predicated, avoids spill)
    int myh = lane >> 2;
    float mh = m[0], sh = s[0], adhd = ad[0];
    #pragma unroll
    for (int h = 1; h < 8; h++)
        if (myh == h) { mh = m[h]; sh = s[h]; adhd = ad[h]; }
    float inv = 1.f / (sh + 1e-16f);

    // ---- sweep 2: weighted aggregate, lane owns channels [lane*4, lane*4+4) ----
    const float4* h4 = reinterpret_cast<const float4*>(hfeat);
    float4 acc = make_float4(0.f, 0.f, 0.f, 0.f);
    for (int i = beg; i < end; i++) {
        int src = col[i];
        float v = as_[src * 8 + myh] + adhd;
        v = v > 0.f ? v : 0.2f * v;
        float w = __expf(v - mh);
        float4 hv = h4[(size_t)src * 32 + lane];
        acc.x += w * hv.x; acc.y += w * hv.y; acc.z += w * hv.z; acc.w += w * hv.w;
    }
    const float4* b4 = reinterpret_cast<const float4*>(bias);
    float4 bb = b4[lane];
    float4 r;
    r.x = acc.x * inv + bb.x; r.y = acc.y * inv + bb.y;
    r.z = acc.z * inv + bb.z; r.w = acc.w * inv + bb.w;
    r.x = r.x > 0.f ? r.x : expm1f(r.x);
    r.y = r.y > 0.f ? r.y : expm1f(r.y);
    r.z = r.z > 0.f ? r.z : expm1f(r.z);
    r.w = r.w > 0.f ? r.w : expm1f(r.w);
    reinterpret_cast<float4*>(out)[(size_t)dst * 32 + lane] = r;
}

// ================= layer-2 aggregate: one warp per dst, H=1, C=16 =================
__global__ __launch_bounds__(256)
void gat_aggregate_l2(const int* __restrict__ rowptr, const int* __restrict__ col,
                      const float* __restrict__ as_, const float* __restrict__ ad_,
                      const float* __restrict__ hfeat, float* __restrict__ out) {
    int warp = (blockIdx.x * blockDim.x + threadIdx.x) >> 5;
    int lane = threadIdx.x & 31;
    if (warp >= NN) return;
    int dst = warp;
    int beg = rowptr[dst], end = rowptr[dst + 1];
    float adv = ad_[dst];

    // online softmax
    float m = -INFINITY, s = 0.f;
    for (int i = beg + lane; i < end; i += 32) {
        float v = as_[col[i]] + adv;
        v = v > 0.f ? v : 0.2f * v;
        float nm = fmaxf(m, v);
        s = s * __expf(m - nm) + __expf(v - nm);
        m = nm;
    }
    #pragma unroll
    for (int o = 16; o > 0; o >>= 1) {
        float om = __shfl_xor_sync(0xffffffffu, m, o);
        float os = __shfl_xor_sync(0xffffffffu, s, o);
        float nm = fmaxf(m, om);
        float e1 = (m == nm) ? 1.f : __expf(m - nm);
        float e2 = (om == nm) ? 1.f : __expf(om - nm);
        s = s * e1 + os * e2;
        m = nm;
    }
    float inv = 1.f / (s + 1e-16f);

    // aggregate: 2 edges/iter, 16 channels
    int c = lane & 15;
    int sub = lane >> 4;
    float acc = 0.f;
    for (int i = beg + sub; i < end; i += 2) {
        int src = col[i];
        float v = as_[src] + adv;
        v = v > 0.f ? v : 0.2f * v;
        float w = __expf(v - m);
        acc += w * hfeat[(size_t)src * 16 + c];
    }
    acc += __shfl_down_sync(0xffffffffu, acc, 16);
    if (lane < 16) out[(size_t)dst * 16 + c] = acc * inv;
}

// ================= final bias + log_softmax =================
__global__ void final_lsm(const float* __restrict__ in, const float* __restrict__ b,
                          float* __restrict__ out, int N) {
    int n = blockIdx.x * blockDim.x + threadIdx.x;
    if (n >= N) return;
    float v[C2];
    float m = -INFINITY;
    #pragma unroll
    for (int c = 0; c < C2; c++) {
        v[c] = in[(size_t)n * C2 + c] + b[c];
        m = fmaxf(m, v[c]);
    }
    float s = 0.f;
    #pragma unroll
    for (int c = 0; c < C2; c++) s += __expf(v[c] - m);
    float l = __logf(s);
    #pragma unroll
    for (int c = 0; c < C2; c++) out[(size_t)n * C2 + c] = v[c] - m - l;
}

// ================= launch =================
extern "C" void kernel_launch(void* const* d_in, const int* in_sizes, int n_in,
                              void* d_out, int out_size) {
    const float* x    = (const float*)d_in[0];
    const int*   ei   = (const int*)d_in[1];
    const float* W1   = (const float*)d_in[2];
    const float* at1s = (const float*)d_in[3];
    const float* at1d = (const float*)d_in[4];
    const float* b1   = (const float*)d_in[5];
    const float* W2   = (const float*)d_in[6];
    const float* at2s = (const float*)d_in[7];
    const float* at2d = (const float*)d_in[8];
    const float* b2   = (const float*)d_in[9];
    float* out = (float*)d_out;

    int E = in_sizes[1] / 2;

    static float *p_h1 = nullptr, *p_as1, *p_ad1, *p_out1, *p_h2, *p_as2, *p_ad2, *p_out2;
    static int *p_cnt, *p_rowptr, *p_cursor, *p_col;
    if (!p_h1) {
        cudaGetSymbolAddress((void**)&p_h1, g_h1);
        cudaGetSymbolAddress((void**)&p_as1, g_as1);
        cudaGetSymbolAddress((void**)&p_ad1, g_ad1);
        cudaGetSymbolAddress((void**)&p_out1, g_out1);
        cudaGetSymbolAddress((void**)&p_h2, g_h2);
        cudaGetSymbolAddress((void**)&p_as2, g_as2);
        cudaGetSymbolAddress((void**)&p_ad2, g_ad2);
        cudaGetSymbolAddress((void**)&p_out2, g_out2);
        cudaGetSymbolAddress((void**)&p_cnt, g_cnt);
        cudaGetSymbolAddress((void**)&p_rowptr, g_rowptr);
        cudaGetSymbolAddress((void**)&p_cursor, g_cursor);
        cudaGetSymbolAddress((void**)&p_col, g_col);
    }

    const int TB = 256;
    auto blocks = [](int n, int tb) { return (n + tb - 1) / tb; };

    // ---- CSR build ----
    fill_int<<<blocks(NN, TB), TB>>>(p_cnt, 1, NN);
    count_dst<<<blocks(E, TB), TB>>>(ei, p_cnt, E);
    scan_rowptr<<<1, 1024>>>(p_cnt, p_rowptr, p_cursor);
    scatter_edges<<<blocks(E + NN, TB), TB>>>(ei, p_cursor, p_col, E);

    // ---- layer 1 ----
    {
        dim3 grid((HC1 + GBN - 1) / GBN, (NN + GBM - 1) / GBM);
        gemm_nt<<<grid, 256>>>(x, W1, p_h1, NN, HC1, NF);
    }
    att_kernel<H1><<<blocks(NN * H1, TB), TB>>>(p_h1, at1s, at1d, p_as1, p_ad1);
    gat_aggregate_l1<<<blocks(NN * 32, TB), TB>>>(p_rowptr, p_col, p_as1, p_ad1, p_h1, b1, p_out1);

    // ---- layer 2 ----
    {
        dim3 grid((C2 + GBN - 1) / GBN, (NN + GBM - 1) / GBM);
        gemm_nt<<<grid, 256>>>(p_out1, W2, p_h2, NN, C2, HC1);
    }
    att_kernel<1><<<blocks(NN, TB), TB>>>(p_h2, at2s, at2d, p_as2, p_ad2);
    gat_aggregate_l2<<<blocks(NN * 32, TB), TB>>>(p_rowptr, p_col, p_as2, p_ad2, p_h2, p_out2);

    // ---- log_softmax ----
    final_lsm<<<blocks(NN, TB), TB>>>(p_out2, b2, out, NN);
}

// round 12
// speedup vs baseline: 1.3668x; 1.3622x over previous
#include <cuda_runtime.h>
#include <math.h>
#include <stdint.h>

// ---------------- problem constants ----------------
#define NN   50000
#define NE   1600000
#define EPAD (NE + NN)
#define NF   512
#define H1   8
#define C1   16
#define HC1  128
#define C2   16

// ---------------- scratch (device globals) ----------------
__device__ float g_h1[NN * HC1];
__device__ float g_as1[NN * H1];
__device__ float g_ad1[NN * H1];
__device__ float g_out1[NN * HC1];
__device__ float g_h2[NN * C2];
__device__ float g_as2[NN];
__device__ float g_ad2[NN];
__device__ float g_out2[NN * C2];
__device__ int   g_cnt[NN];
__device__ int   g_rowptr[NN + 1];
__device__ int   g_cursor[NN];
__device__ int   g_col[EPAD];

// ================= CSR build =================
__global__ void fill_int(int* p, int v, int n) {
    int i = blockIdx.x * blockDim.x + threadIdx.x;
    if (i < n) p[i] = v;
}

__global__ void count_dst(const int* __restrict__ ei, int* __restrict__ cnt, int E) {
    int e = blockIdx.x * blockDim.x + threadIdx.x;
    if (e < E) atomicAdd(&cnt[ei[E + e]], 1);
}

__global__ void scan_rowptr(const int* __restrict__ cnt, int* __restrict__ rowptr,
                            int* __restrict__ cursor) {
    __shared__ int ssum[1024];
    const int T = 1024;
    const int PER = (NN + T - 1) / T;
    int tid = threadIdx.x;
    int start = tid * PER;
    int local = 0;
    for (int i = 0; i < PER; i++) {
        int idx = start + i;
        if (idx < NN) local += cnt[idx];
    }
    ssum[tid] = local;
    __syncthreads();
    for (int off = 1; off < T; off <<= 1) {
        int v = (tid >= off) ? ssum[tid - off] : 0;
        __syncthreads();
        ssum[tid] += v;
        __syncthreads();
    }
    int run = (tid == 0) ? 0 : ssum[tid - 1];
    for (int i = 0; i < PER; i++) {
        int idx = start + i;
        if (idx < NN) { rowptr[idx] = run; cursor[idx] = run; run += cnt[idx]; }
    }
    if (tid == T - 1) rowptr[NN] = ssum[T - 1];
}

__global__ void scatter_edges(const int* __restrict__ ei, int* __restrict__ cursor,
                              int* __restrict__ col, int E) {
    int i = blockIdx.x * blockDim.x + threadIdx.x;
    int tot = E + NN;
    if (i >= tot) return;
    int s, d;
    if (i < E) { s = ei[i]; d = ei[E + i]; } else { s = d = i - E; }
    int pos = atomicAdd(&cursor[d], 1);
    col[pos] = s;
}

// ================= 3xTF32 tensor-core GEMM (NT): C[M,128] = A[M,K]*B[128,K]^T =================
// Block tile 128x64x16, 8 warps, warp tile 32x32 (2x4 mma tiles of m16n8).
// Requires Nn == 128 handled by grid.x = 2; K % 16 == 0.

__device__ __forceinline__ void split_tf32(float x, uint32_t& hi, uint32_t& lo) {
    uint32_t h;
    asm("cvt.rna.tf32.f32 %0, %1;" : "=r"(h) : "f"(x));
    float r = x - __uint_as_float(h);
    uint32_t l;
    asm("cvt.rna.tf32.f32 %0, %1;" : "=r"(l) : "f"(r));
    hi = h; lo = l;
}

__device__ __forceinline__ void mma_tf32(float* d, const uint32_t* a, const uint32_t* b) {
    asm volatile(
        "mma.sync.aligned.m16n8k8.row.col.f32.tf32.tf32.f32 "
        "{%0,%1,%2,%3}, {%4,%5,%6,%7}, {%8,%9}, {%0,%1,%2,%3};"
        : "+f"(d[0]), "+f"(d[1]), "+f"(d[2]), "+f"(d[3])
        : "r"(a[0]), "r"(a[1]), "r"(a[2]), "r"(a[3]), "r"(b[0]), "r"(b[1]));
}

#define TSTRIDE 20   // padded smem row stride (floats): conflict-free frag reads, 16B-aligned rows

__global__ __launch_bounds__(256, 2)
void gemm_tf32x3(const float* __restrict__ A, const float* __restrict__ B,
                 float* __restrict__ C, int M, int K) {
    __shared__ float As[128][TSTRIDE];
    __shared__ float Bs[64][TSTRIDE];

    const int Nn = 128;
    int t = threadIdx.x;
    int lane = t & 31;
    int warp = t >> 5;
    int wm = warp & 3;           // 0..3  -> m offset 32*wm
    int wn = warp >> 2;          // 0..1  -> n offset 32*wn
    int g  = lane >> 2;          // group 0..7
    int tg = lane & 3;           // 0..3

    int m0 = blockIdx.y * 128;
    int n0 = blockIdx.x * 64;

    // global load mapping: A tile 128x16 = 512 float4 -> 2/thread; B tile 64x16 -> 1/thread
    int f2 = t + 256;
    int ar1 = t >> 2,  ac1 = (t & 3) * 4;
    int ar2 = f2 >> 2, ac2 = (f2 & 3) * 4;
    int br  = t >> 2,  bc  = (t & 3) * 4;

    bool a1ok = (m0 + ar1) < M;
    bool a2ok = (m0 + ar2) < M;
    const float4* Ap1 = a1ok ? reinterpret_cast<const float4*>(&A[(size_t)(m0 + ar1) * K + ac1]) : nullptr;
    const float4* Ap2 = a2ok ? reinterpret_cast<const float4*>(&A[(size_t)(m0 + ar2) * K + ac2]) : nullptr;
    const float4* Bp  = reinterpret_cast<const float4*>(&B[(size_t)(n0 + br) * K + bc]);

    float4 pa1 = a1ok ? Ap1[0] : make_float4(0, 0, 0, 0);
    float4 pa2 = a2ok ? Ap2[0] : make_float4(0, 0, 0, 0);
    float4 pb  = Bp[0];

    float d[2][4][4];
    #pragma unroll
    for (int i = 0; i < 2; i++)
        #pragma unroll
        for (int j = 0; j < 4; j++)
            #pragma unroll
            for (int q = 0; q < 4; q++) d[i][j][q] = 0.f;

    for (int k0 = 0; k0 < K; k0 += 16) {
        *reinterpret_cast<float4*>(&As[ar1][ac1]) = pa1;
        *reinterpret_cast<float4*>(&As[ar2][ac2]) = pa2;
        *reinterpret_cast<float4*>(&Bs[br][bc])   = pb;
        __syncthreads();

        if (k0 + 16 < K) {
            int idx = (k0 + 16) >> 2;
            pa1 = a1ok ? Ap1[idx] : make_float4(0, 0, 0, 0);
            pa2 = a2ok ? Ap2[idx] : make_float4(0, 0, 0, 0);
            pb  = Bp[idx];
        }

        #pragma unroll
        for (int ks = 0; ks < 2; ks++) {
            int kb = ks * 8;
            uint32_t ah[2][4], al[2][4], bh[4][2], bl[4][2];
            #pragma unroll
            for (int mt = 0; mt < 2; mt++) {
                int r0 = wm * 32 + mt * 16 + g;
                split_tf32(As[r0][kb + tg],          ah[mt][0], al[mt][0]);
                split_tf32(As[r0 + 8][kb + tg],      ah[mt][1], al[mt][1]);
                split_tf32(As[r0][kb + tg + 4],      ah[mt][2], al[mt][2]);
                split_tf32(As[r0 + 8][kb + tg + 4],  ah[mt][3], al[mt][3]);
            }
            #pragma unroll
            for (int nt = 0; nt < 4; nt++) {
                int n = wn * 32 + nt * 8 + g;
                split_tf32(Bs[n][kb + tg],     bh[nt][0], bl[nt][0]);
                split_tf32(Bs[n][kb + tg + 4], bh[nt][1], bl[nt][1]);
            }
            #pragma unroll
            for (int mt = 0; mt < 2; mt++)
                #pragma unroll
                for (int nt = 0; nt < 4; nt++) {
                    mma_tf32(d[mt][nt], ah[mt], bh[nt]);
                    mma_tf32(d[mt][nt], ah[mt], bl[nt]);
                    mma_tf32(d[mt][nt], al[mt], bh[nt]);
                }
        }
        __syncthreads();
    }

    // epilogue
    #pragma unroll
    for (int mt = 0; mt < 2; mt++) {
        int r0 = m0 + wm * 32 + mt * 16 + g;
        #pragma unroll
        for (int nt = 0; nt < 4; nt++) {
            int c = n0 + wn * 32 + nt * 8 + tg * 2;
            if (r0 < M)
                *reinterpret_cast<float2*>(&C[(size_t)r0 * Nn + c]) =
                    make_float2(d[mt][nt][0], d[mt][nt][1]);
            if (r0 + 8 < M)
                *reinterpret_cast<float2*>(&C[(size_t)(r0 + 8) * Nn + c]) =
                    make_float2(d[mt][nt][2], d[mt][nt][3]);
        }
    }
}

// ================= SGEMM (NT) fallback for layer 2 =================
#define GBM 128
#define GBN 128
#define GBK 8

__global__ __launch_bounds__(256, 2)
void gemm_nt(const float* __restrict__ A, const float* __restrict__ B,
             float* __restrict__ C, int M, int Nn, int K) {
    __shared__ float As[GBK][GBM];
    __shared__ float Bs[GBK][GBN];
    int t = threadIdx.x;
    int tx = t & 15, ty = t >> 4;
    int m0 = blockIdx.y * GBM, n0 = blockIdx.x * GBN;
    int lrow = t >> 1;
    int lk = (t & 1) * 4;

    float acc[8][8];
    #pragma unroll
    for (int i = 0; i < 8; i++)
        #pragma unroll
        for (int j = 0; j < 8; j++) acc[i][j] = 0.f;

    int am = m0 + lrow;
    int bn = n0 + lrow;
    const float* Ap = (am < M) ? &A[(size_t)am * K + lk] : nullptr;
    const float* Bp = (bn < Nn) ? &B[(size_t)bn * K + lk] : nullptr;

    float4 av = Ap ? *reinterpret_cast<const float4*>(Ap) : make_float4(0,0,0,0);
    float4 bv = Bp ? *reinterpret_cast<const float4*>(Bp) : make_float4(0,0,0,0);

    for (int k0 = 0; k0 < K; k0 += GBK) {
        As[lk + 0][lrow] = av.x; As[lk + 1][lrow] = av.y;
        As[lk + 2][lrow] = av.z; As[lk + 3][lrow] = av.w;
        Bs[lk + 0][lrow] = bv.x; Bs[lk + 1][lrow] = bv.y;
        Bs[lk + 2][lrow] = bv.z; Bs[lk + 3][lrow] = bv.w;
        __syncthreads();
        if (k0 + GBK < K) {
            av = Ap ? *reinterpret_cast<const float4*>(Ap + k0 + GBK) : make_float4(0,0,0,0);
            bv = Bp ? *reinterpret_cast<const float4*>(Bp + k0 + GBK) : make_float4(0,0,0,0);
        }
        #pragma unroll
        for (int k = 0; k < GBK; k++) {
            float a[8], b[8];
            float4 a0 = *reinterpret_cast<const float4*>(&As[k][ty * 8]);
            float4 a1 = *reinterpret_cast<const float4*>(&As[k][ty * 8 + 4]);
            float4 b0 = *reinterpret_cast<const float4*>(&Bs[k][tx * 8]);
            float4 b1 = *reinterpret_cast<const float4*>(&Bs[k][tx * 8 + 4]);
            a[0]=a0.x;a[1]=a0.y;a[2]=a0.z;a[3]=a0.w;a[4]=a1.x;a[5]=a1.y;a[6]=a1.z;a[7]=a1.w;
            b[0]=b0.x;b[1]=b0.y;b[2]=b0.z;b[3]=b0.w;b[4]=b1.x;b[5]=b1.y;b[6]=b1.z;b[7]=b1.w;
            #pragma unroll
            for (int i = 0; i < 8; i++)
                #pragma unroll
                for (int j = 0; j < 8; j++) acc[i][j] += a[i] * b[j];
        }
        __syncthreads();
    }
    #pragma unroll
    for (int i = 0; i < 8; i++) {
        int m = m0 + ty * 8 + i;
        if (m >= M) continue;
        #pragma unroll
        for (int j = 0; j < 8; j++) {
            int n = n0 + tx * 8 + j;
            if (n < Nn) C[(size_t)m * Nn + n] = acc[i][j];
        }
    }
}

// ================= attention coefficients (C=16, float4) =================
template<int H>
__global__ void att_kernel(const float* __restrict__ h, const float* __restrict__ att_s,
                           const float* __restrict__ att_d, float* __restrict__ as_,
                           float* __restrict__ ad_) {
    int idx = blockIdx.x * blockDim.x + threadIdx.x;
    if (idx >= NN * H) return;
    int hh = idx & (H - 1);
    const float4* hp = reinterpret_cast<const float4*>(h) + (size_t)idx * 4;
    const float4* sp = reinterpret_cast<const float4*>(att_s) + hh * 4;
    const float4* dp = reinterpret_cast<const float4*>(att_d) + hh * 4;
    float s = 0.f, d = 0.f;
    #pragma unroll
    for (int q = 0; q < 4; q++) {
        float4 v = hp[q], a = sp[q], b = dp[q];
        s += v.x * a.x + v.y * a.y + v.z * a.z + v.w * a.w;
        d += v.x * b.x + v.y * b.y + v.z * b.z + v.w * b.w;
    }
    as_[idx] = s;
    ad_[idx] = d;
}

// ================= layer-1 fused aggregate: one warp per dst, all 8 heads =================
__global__ __launch_bounds__(256)
void gat_aggregate_l1(const int* __restrict__ rowptr, const int* __restrict__ col,
                      const float* __restrict__ as_, const float* __restrict__ ad_,
                      const float* __restrict__ hfeat, const float* __restrict__ bias,
                      float* __restrict__ out) {
    int warp = (blockIdx.x * blockDim.x + threadIdx.x) >> 5;
    int lane = threadIdx.x & 31;
    if (warp >= NN) return;
    int dst = warp;
    int beg = rowptr[dst], end = rowptr[dst + 1];

    const float4* ad4 = reinterpret_cast<const float4*>(ad_) + (size_t)dst * 2;
    float4 adl = ad4[0], adh = ad4[1];
    float ad[8] = {adl.x, adl.y, adl.z, adl.w, adh.x, adh.y, adh.z, adh.w};

    const float4* as4 = reinterpret_cast<const float4*>(as_);

    float m[8], s[8];
    #pragma unroll
    for (int h = 0; h < 8; h++) { m[h] = -INFINITY; s[h] = 0.f; }

    for (int i = beg + lane; i < end; i += 32) {
        int src = col[i];
        float4 a0 = as4[(size_t)src * 2];
        float4 a1 = as4[(size_t)src * 2 + 1];
        float av[8] = {a0.x, a0.y, a0.z, a0.w, a1.x, a1.y, a1.z, a1.w};
        #pragma unroll
        for (int h = 0; h < 8; h++) {
            float v = av[h] + ad[h];
            v = v > 0.f ? v : 0.2f * v;
            float nm = fmaxf(m[h], v);
            s[h] = s[h] * __expf(m[h] - nm) + __expf(v - nm);
            m[h] = nm;
        }
    }
    #pragma unroll
    for (int o = 16; o > 0; o >>= 1) {
        #pragma unroll
        for (int h = 0; h < 8; h++) {
            float om = __shfl_xor_sync(0xffffffffu, m[h], o);
            float os = __shfl_xor_sync(0xffffffffu, s[h], o);
            float nm = fmaxf(m[h], om);
            float e1 = (m[h] == nm) ? 1.f : __expf(m[h] - nm);
            float e2 = (om == nm)   ? 1.f : __expf(om - nm);
            s[h] = s[h] * e1 + os * e2;
            m[h] = nm;
        }
    }

    int myh = lane >> 2;
    float mh = m[0], sh = s[0], adhd = ad[0];
    #pragma unroll
    for (int h = 1; h < 8; h++)
        if (myh == h) { mh = m[h]; sh = s[h]; adhd = ad[h]; }
    float inv = 1.f / (sh + 1e-16f);

    const float4* h4 = reinterpret_cast<const float4*>(hfeat);
    float4 acc = make_float4(0.f, 0.f, 0.f, 0.f);
    for (int i = beg; i < end; i++) {
        int src = col[i];
        float v = as_[src * 8 + myh] + adhd;
        v = v > 0.f ? v : 0.2f * v;
        float w = __expf(v - mh);
        float4 hv = h4[(size_t)src * 32 + lane];
        acc.x += w * hv.x; acc.y += w * hv.y; acc.z += w * hv.z; acc.w += w * hv.w;
    }
    const float4* b4 = reinterpret_cast<const float4*>(bias);
    float4 bb = b4[lane];
    float4 r;
    r.x = acc.x * inv + bb.x; r.y = acc.y * inv + bb.y;
    r.z = acc.z * inv + bb.z; r.w = acc.w * inv + bb.w;
    r.x = r.x > 0.f ? r.x : expm1f(r.x);
    r.y = r.y > 0.f ? r.y : expm1f(r.y);
    r.z = r.z > 0.f ? r.z : expm1f(r.z);
    r.w = r.w > 0.f ? r.w : expm1f(r.w);
    reinterpret_cast<float4*>(out)[(size_t)dst * 32 + lane] = r;
}

// ================= layer-2 aggregate =================
__global__ __launch_bounds__(256)
void gat_aggregate_l2(const int* __restrict__ rowptr, const int* __restrict__ col,
                      const float* __restrict__ as_, const float* __restrict__ ad_,
                      const float* __restrict__ hfeat, float* __restrict__ out) {
    int warp = (blockIdx.x * blockDim.x + threadIdx.x) >> 5;
    int lane = threadIdx.x & 31;
    if (warp >= NN) return;
    int dst = warp;
    int beg = rowptr[dst], end = rowptr[dst + 1];
    float adv = ad_[dst];

    float m = -INFINITY, s = 0.f;
    for (int i = beg + lane; i < end; i += 32) {
        float v = as_[col[i]] + adv;
        v = v > 0.f ? v : 0.2f * v;
        float nm = fmaxf(m, v);
        s = s * __expf(m - nm) + __expf(v - nm);
        m = nm;
    }
    #pragma unroll
    for (int o = 16; o > 0; o >>= 1) {
        float om = __shfl_xor_sync(0xffffffffu, m, o);
        float os = __shfl_xor_sync(0xffffffffu, s, o);
        float nm = fmaxf(m, om);
        float e1 = (m == nm) ? 1.f : __expf(m - nm);
        float e2 = (om == nm) ? 1.f : __expf(om - nm);
        s = s * e1 + os * e2;
        m = nm;
    }
    float inv = 1.f / (s + 1e-16f);

    int c = lane & 15;
    int sub = lane >> 4;
    float acc = 0.f;
    for (int i = beg + sub; i < end; i += 2) {
        int src = col[i];
        float v = as_[src] + adv;
        v = v > 0.f ? v : 0.2f * v;
        float w = __expf(v - m);
        acc += w * hfeat[(size_t)src * 16 + c];
    }
    acc += __shfl_down_sync(0xffffffffu, acc, 16);
    if (lane < 16) out[(size_t)dst * 16 + c] = acc * inv;
}

// ================= final bias + log_softmax =================
__global__ void final_lsm(const float* __restrict__ in, const float* __restrict__ b,
                          float* __restrict__ out, int N) {
    int n = blockIdx.x * blockDim.x + threadIdx.x;
    if (n >= N) return;
    float v[C2];
    float m = -INFINITY;
    #pragma unroll
    for (int c = 0; c < C2; c++) {
        v[c] = in[(size_t)n * C2 + c] + b[c];
        m = fmaxf(m, v[c]);
    }
    float s = 0.f;
    #pragma unroll
    for (int c = 0; c < C2; c++) s += __expf(v[c] - m);
    float l = __logf(s);
    #pragma unroll
    for (int c = 0; c < C2; c++) out[(size_t)n * C2 + c] = v[c] - m - l;
}

// ================= launch =================
extern "C" void kernel_launch(void* const* d_in, const int* in_sizes, int n_in,
                              void* d_out, int out_size) {
    const float* x    = (const float*)d_in[0];
    const int*   ei   = (const int*)d_in[1];
    const float* W1   = (const float*)d_in[2];
    const float* at1s = (const float*)d_in[3];
    const float* at1d = (const float*)d_in[4];
    const float* b1   = (const float*)d_in[5];
    const float* W2   = (const float*)d_in[6];
    const float* at2s = (const float*)d_in[7];
    const float* at2d = (const float*)d_in[8];
    const float* b2   = (const float*)d_in[9];
    float* out = (float*)d_out;

    int E = in_sizes[1] / 2;

    static float *p_h1 = nullptr, *p_as1, *p_ad1, *p_out1, *p_h2, *p_as2, *p_ad2, *p_out2;
    static int *p_cnt, *p_rowptr, *p_cursor, *p_col;
    static cudaStream_t s2 = nullptr;
    static cudaEvent_t evF = nullptr, evJ = nullptr;
    if (!p_h1) {
        cudaGetSymbolAddress((void**)&p_h1, g_h1);
        cudaGetSymbolAddress((void**)&p_as1, g_as1);
        cudaGetSymbolAddress((void**)&p_ad1, g_ad1);
        cudaGetSymbolAddress((void**)&p_out1, g_out1);
        cudaGetSymbolAddress((void**)&p_h2, g_h2);
        cudaGetSymbolAddress((void**)&p_as2, g_as2);
        cudaGetSymbolAddress((void**)&p_ad2, g_ad2);
        cudaGetSymbolAddress((void**)&p_out2, g_out2);
        cudaGetSymbolAddress((void**)&p_cnt, g_cnt);
        cudaGetSymbolAddress((void**)&p_rowptr, g_rowptr);
        cudaGetSymbolAddress((void**)&p_cursor, g_cursor);
        cudaGetSymbolAddress((void**)&p_col, g_col);
        cudaStreamCreateWithFlags(&s2, cudaStreamNonBlocking);
        cudaEventCreateWithFlags(&evF, cudaEventDisableTiming);
        cudaEventCreateWithFlags(&evJ, cudaEventDisableTiming);
    }

    const int TB = 256;
    auto blocks = [](int n, int tb) { return (n + tb - 1) / tb; };

    // ---- fork: CSR build on side stream, concurrent with GEMM1/att1 ----
    cudaEventRecord(evF, 0);
    cudaStreamWaitEvent(s2, evF, 0);
    fill_int<<<blocks(NN, TB), TB, 0, s2>>>(p_cnt, 1, NN);
    count_dst<<<blocks(E, TB), TB, 0, s2>>>(ei, p_cnt, E);
    scan_rowptr<<<1, 1024, 0, s2>>>(p_cnt, p_rowptr, p_cursor);
    scatter_edges<<<blocks(E + NN, TB), TB, 0, s2>>>(ei, p_cursor, p_col, E);
    cudaEventRecord(evJ, s2);

    // ---- layer 1 GEMM (tensor, 3xTF32) + attention coefficients ----
    {
        dim3 grid(HC1 / 64, (NN + 127) / 128);
        gemm_tf32x3<<<grid, 256>>>(x, W1, p_h1, NN, NF);
    }
    att_kernel<H1><<<blocks(NN * H1, TB), TB>>>(p_h1, at1s, at1d, p_as1, p_ad1);

    // ---- join: aggregation needs the CSR ----
    cudaStreamWaitEvent(0, evJ, 0);
    gat_aggregate_l1<<<blocks(NN * 32, TB), TB>>>(p_rowptr, p_col, p_as1, p_ad1, p_h1, b1, p_out1);

    // ---- layer 2 ----
    {
        dim3 grid((C2 + GBN - 1) / GBN, (NN + GBM - 1) / GBM);
        gemm_nt<<<grid, 256>>>(p_out1, W2, p_h2, NN, C2, HC1);
    }
    att_kernel<1><<<blocks(NN, TB), TB>>>(p_h2, at2s, at2d, p_as2, p_ad2);
    gat_aggregate_l2<<<blocks(NN * 32, TB), TB>>>(p_rowptr, p_col, p_as2, p_ad2, p_h2, p_out2);

    // ---- log_softmax ----
    final_lsm<<<blocks(NN, TB), TB>>>(p_out2, b2, out, NN);
}

// round 13
// speedup vs baseline: 1.4801x; 1.0829x over previous
#include <cuda_runtime.h>
#include <math.h>
#include <stdint.h>

// ---------------- problem constants ----------------
#define NN   50000
#define NE   1600000
#define EPAD (NE + NN)
#define NF   512
#define H1   8
#define C1   16
#define HC1  128
#define C2   16

// ---------------- scratch (device globals) ----------------
__device__ float g_h1[NN * HC1];
__device__ float g_as1[NN * H1];
__device__ float g_ad1[NN * H1];
__device__ float g_out1[NN * HC1];
__device__ float g_h2[NN * C2];
__device__ float g_as2[NN];
__device__ float g_ad2[NN];
__device__ int   g_cnt[NN];
__device__ int   g_rowptr[NN + 1];
__device__ int   g_cursor[NN];
__device__ int   g_col[EPAD];

// ================= CSR build =================
__global__ void fill_int(int* p, int v, int n) {
    int i = blockIdx.x * blockDim.x + threadIdx.x;
    if (i < n) p[i] = v;
}

__global__ void count_dst(const int* __restrict__ ei, int* __restrict__ cnt, int E) {
    int e = blockIdx.x * blockDim.x + threadIdx.x;
    if (e < E) atomicAdd(&cnt[ei[E + e]], 1);
}

__global__ void scan_rowptr(const int* __restrict__ cnt, int* __restrict__ rowptr,
                            int* __restrict__ cursor) {
    __shared__ int ssum[1024];
    const int T = 1024;
    const int PER = (NN + T - 1) / T;
    int tid = threadIdx.x;
    int start = tid * PER;
    int local = 0;
    for (int i = 0; i < PER; i++) {
        int idx = start + i;
        if (idx < NN) local += cnt[idx];
    }
    ssum[tid] = local;
    __syncthreads();
    for (int off = 1; off < T; off <<= 1) {
        int v = (tid >= off) ? ssum[tid - off] : 0;
        __syncthreads();
        ssum[tid] += v;
        __syncthreads();
    }
    int run = (tid == 0) ? 0 : ssum[tid - 1];
    for (int i = 0; i < PER; i++) {
        int idx = start + i;
        if (idx < NN) { rowptr[idx] = run; cursor[idx] = run; run += cnt[idx]; }
    }
    if (tid == T - 1) rowptr[NN] = ssum[T - 1];
}

__global__ void scatter_edges(const int* __restrict__ ei, int* __restrict__ cursor,
                              int* __restrict__ col, int E) {
    int i = blockIdx.x * blockDim.x + threadIdx.x;
    int tot = E + NN;
    if (i >= tot) return;
    int s, d;
    if (i < E) { s = ei[i]; d = ei[E + i]; } else { s = d = i - E; }
    int pos = atomicAdd(&cursor[d], 1);
    col[pos] = s;
}

// ================= 3xTF32 tensor-core GEMM (NT): C[M,128] = A[M,K]*B[128,K]^T =================
__device__ __forceinline__ void split_tf32(float x, uint32_t& hi, uint32_t& lo) {
    uint32_t h;
    asm("cvt.rna.tf32.f32 %0, %1;" : "=r"(h) : "f"(x));
    float r = x - __uint_as_float(h);
    uint32_t l;
    asm("cvt.rna.tf32.f32 %0, %1;" : "=r"(l) : "f"(r));
    hi = h; lo = l;
}

__device__ __forceinline__ void mma_tf32(float* d, const uint32_t* a, const uint32_t* b) {
    asm volatile(
        "mma.sync.aligned.m16n8k8.row.col.f32.tf32.tf32.f32 "
        "{%0,%1,%2,%3}, {%4,%5,%6,%7}, {%8,%9}, {%0,%1,%2,%3};"
        : "+f"(d[0]), "+f"(d[1]), "+f"(d[2]), "+f"(d[3])
        : "r"(a[0]), "r"(a[1]), "r"(a[2]), "r"(a[3]), "r"(b[0]), "r"(b[1]));
}

#define TSTRIDE 20

__global__ __launch_bounds__(256, 2)
void gemm_tf32x3(const float* __restrict__ A, const float* __restrict__ B,
                 float* __restrict__ C, int M, int K) {
    __shared__ float As[128][TSTRIDE];
    __shared__ float Bs[64][TSTRIDE];

    const int Nn = 128;
    int t = threadIdx.x;
    int lane = t & 31;
    int warp = t >> 5;
    int wm = warp & 3;
    int wn = warp >> 2;
    int g  = lane >> 2;
    int tg = lane & 3;

    int m0 = blockIdx.y * 128;
    int n0 = blockIdx.x * 64;

    int f2 = t + 256;
    int ar1 = t >> 2,  ac1 = (t & 3) * 4;
    int ar2 = f2 >> 2, ac2 = (f2 & 3) * 4;
    int br  = t >> 2,  bc  = (t & 3) * 4;

    bool a1ok = (m0 + ar1) < M;
    bool a2ok = (m0 + ar2) < M;
    const float4* Ap1 = a1ok ? reinterpret_cast<const float4*>(&A[(size_t)(m0 + ar1) * K + ac1]) : nullptr;
    const float4* Ap2 = a2ok ? reinterpret_cast<const float4*>(&A[(size_t)(m0 + ar2) * K + ac2]) : nullptr;
    const float4* Bp  = reinterpret_cast<const float4*>(&B[(size_t)(n0 + br) * K + bc]);

    float4 pa1 = a1ok ? Ap1[0] : make_float4(0, 0, 0, 0);
    float4 pa2 = a2ok ? Ap2[0] : make_float4(0, 0, 0, 0);
    float4 pb  = Bp[0];

    float d[2][4][4];
    #pragma unroll
    for (int i = 0; i < 2; i++)
        #pragma unroll
        for (int j = 0; j < 4; j++)
            #pragma unroll
            for (int q = 0; q < 4; q++) d[i][j][q] = 0.f;

    for (int k0 = 0; k0 < K; k0 += 16) {
        *reinterpret_cast<float4*>(&As[ar1][ac1]) = pa1;
        *reinterpret_cast<float4*>(&As[ar2][ac2]) = pa2;
        *reinterpret_cast<float4*>(&Bs[br][bc])   = pb;
        __syncthreads();

        if (k0 + 16 < K) {
            int idx = (k0 + 16) >> 2;
            pa1 = a1ok ? Ap1[idx] : make_float4(0, 0, 0, 0);
            pa2 = a2ok ? Ap2[idx] : make_float4(0, 0, 0, 0);
            pb  = Bp[idx];
        }

        #pragma unroll
        for (int ks = 0; ks < 2; ks++) {
            int kb = ks * 8;
            uint32_t ah[2][4], al[2][4], bh[4][2], bl[4][2];
            #pragma unroll
            for (int mt = 0; mt < 2; mt++) {
                int r0 = wm * 32 + mt * 16 + g;
                split_tf32(As[r0][kb + tg],          ah[mt][0], al[mt][0]);
                split_tf32(As[r0 + 8][kb + tg],      ah[mt][1], al[mt][1]);
                split_tf32(As[r0][kb + tg + 4],      ah[mt][2], al[mt][2]);
                split_tf32(As[r0 + 8][kb + tg + 4],  ah[mt][3], al[mt][3]);
            }
            #pragma unroll
            for (int nt = 0; nt < 4; nt++) {
                int n = wn * 32 + nt * 8 + g;
                split_tf32(Bs[n][kb + tg],     bh[nt][0], bl[nt][0]);
                split_tf32(Bs[n][kb + tg + 4], bh[nt][1], bl[nt][1]);
            }
            #pragma unroll
            for (int mt = 0; mt < 2; mt++)
                #pragma unroll
                for (int nt = 0; nt < 4; nt++) {
                    mma_tf32(d[mt][nt], ah[mt], bh[nt]);
                    mma_tf32(d[mt][nt], ah[mt], bl[nt]);
                    mma_tf32(d[mt][nt], al[mt], bh[nt]);
                }
        }
        __syncthreads();
    }

    #pragma unroll
    for (int mt = 0; mt < 2; mt++) {
        int r0 = m0 + wm * 32 + mt * 16 + g;
        #pragma unroll
        for (int nt = 0; nt < 4; nt++) {
            int c = n0 + wn * 32 + nt * 8 + tg * 2;
            if (r0 < M)
                *reinterpret_cast<float2*>(&C[(size_t)r0 * Nn + c]) =
                    make_float2(d[mt][nt][0], d[mt][nt][1]);
            if (r0 + 8 < M)
                *reinterpret_cast<float2*>(&C[(size_t)(r0 + 8) * Nn + c]) =
                    make_float2(d[mt][nt][2], d[mt][nt][3]);
        }
    }
}

// ================= attention coefficients layer 1 (C=16, float4) =================
template<int H>
__global__ void att_kernel(const float* __restrict__ h, const float* __restrict__ att_s,
                           const float* __restrict__ att_d, float* __restrict__ as_,
                           float* __restrict__ ad_) {
    int idx = blockIdx.x * blockDim.x + threadIdx.x;
    if (idx >= NN * H) return;
    int hh = idx & (H - 1);
    const float4* hp = reinterpret_cast<const float4*>(h) + (size_t)idx * 4;
    const float4* sp = reinterpret_cast<const float4*>(att_s) + hh * 4;
    const float4* dp = reinterpret_cast<const float4*>(att_d) + hh * 4;
    float s = 0.f, d = 0.f;
    #pragma unroll
    for (int q = 0; q < 4; q++) {
        float4 v = hp[q], a = sp[q], b = dp[q];
        s += v.x * a.x + v.y * a.y + v.z * a.z + v.w * a.w;
        d += v.x * b.x + v.y * b.y + v.z * b.z + v.w * b.w;
    }
    as_[idx] = s;
    ad_[idx] = d;
}

// ================= layer-1 fused aggregate: one warp per dst, all 8 heads =================
__global__ __launch_bounds__(256)
void gat_aggregate_l1(const int* __restrict__ rowptr, const int* __restrict__ col,
                      const float* __restrict__ as_, const float* __restrict__ ad_,
                      const float* __restrict__ hfeat, const float* __restrict__ bias,
                      float* __restrict__ out) {
    int warp = (blockIdx.x * blockDim.x + threadIdx.x) >> 5;
    int lane = threadIdx.x & 31;
    if (warp >= NN) return;
    int dst = warp;
    int beg = rowptr[dst], end = rowptr[dst + 1];

    const float4* ad4 = reinterpret_cast<const float4*>(ad_) + (size_t)dst * 2;
    float4 adl = ad4[0], adh = ad4[1];
    float ad[8] = {adl.x, adl.y, adl.z, adl.w, adh.x, adh.y, adh.z, adh.w};

    const float4* as4 = reinterpret_cast<const float4*>(as_);

    // ---- sweep 1: online softmax for all 8 heads (unroll x2 for MLP) ----
    float m[8], s[8];
    #pragma unroll
    for (int h = 0; h < 8; h++) { m[h] = -INFINITY; s[h] = 0.f; }

    int i = beg + lane;
    for (; i + 32 < end; i += 64) {
        int s0 = col[i];
        int s1 = col[i + 32];
        float4 x0 = as4[(size_t)s0 * 2];
        float4 x1 = as4[(size_t)s0 * 2 + 1];
        float4 y0 = as4[(size_t)s1 * 2];
        float4 y1 = as4[(size_t)s1 * 2 + 1];
        float av0[8] = {x0.x, x0.y, x0.z, x0.w, x1.x, x1.y, x1.z, x1.w};
        float av1[8] = {y0.x, y0.y, y0.z, y0.w, y1.x, y1.y, y1.z, y1.w};
        #pragma unroll
        for (int h = 0; h < 8; h++) {
            float v0 = av0[h] + ad[h];
            v0 = v0 > 0.f ? v0 : 0.2f * v0;
            float v1 = av1[h] + ad[h];
            v1 = v1 > 0.f ? v1 : 0.2f * v1;
            float hi = fmaxf(v0, v1), lo = fminf(v0, v1);
            float pl = __expf(lo - hi) + 1.f;          // exp(lo-hi)+exp(0)
            float nm = fmaxf(m[h], hi);
            s[h] = s[h] * __expf(m[h] - nm) + pl * __expf(hi - nm);
            m[h] = nm;
        }
    }
    if (i < end) {
        int s0 = col[i];
        float4 x0 = as4[(size_t)s0 * 2];
        float4 x1 = as4[(size_t)s0 * 2 + 1];
        float av0[8] = {x0.x, x0.y, x0.z, x0.w, x1.x, x1.y, x1.z, x1.w};
        #pragma unroll
        for (int h = 0; h < 8; h++) {
            float v = av0[h] + ad[h];
            v = v > 0.f ? v : 0.2f * v;
            float nm = fmaxf(m[h], v);
            s[h] = s[h] * __expf(m[h] - nm) + __expf(v - nm);
            m[h] = nm;
        }
    }
    #pragma unroll
    for (int o = 16; o > 0; o >>= 1) {
        #pragma unroll
        for (int h = 0; h < 8; h++) {
            float om = __shfl_xor_sync(0xffffffffu, m[h], o);
            float os = __shfl_xor_sync(0xffffffffu, s[h], o);
            float nm = fmaxf(m[h], om);
            float e1 = (m[h] == nm) ? 1.f : __expf(m[h] - nm);
            float e2 = (om == nm)   ? 1.f : __expf(om - nm);
            s[h] = s[h] * e1 + os * e2;
            m[h] = nm;
        }
    }

    int myh = lane >> 2;
    float mh = m[0], sh = s[0], adhd = ad[0];
    #pragma unroll
    for (int h = 1; h < 8; h++)
        if (myh == h) { mh = m[h]; sh = s[h]; adhd = ad[h]; }
    float inv = 1.f / (sh + 1e-16f);

    // ---- sweep 2: weighted aggregate (unroll x4 for MLP) ----
    const float4* h4 = reinterpret_cast<const float4*>(hfeat);
    float4 acc = make_float4(0.f, 0.f, 0.f, 0.f);
    int j = beg;
    for (; j + 4 <= end; j += 4) {
        int s0 = col[j], s1 = col[j + 1], s2 = col[j + 2], s3 = col[j + 3];
        float a0 = as_[s0 * 8 + myh];
        float a1 = as_[s1 * 8 + myh];
        float a2 = as_[s2 * 8 + myh];
        float a3 = as_[s3 * 8 + myh];
        float4 h0 = h4[(size_t)s0 * 32 + lane];
        float4 h1 = h4[(size_t)s1 * 32 + lane];
        float4 h2 = h4[(size_t)s2 * 32 + lane];
        float4 h3 = h4[(size_t)s3 * 32 + lane];
        a0 += adhd; a0 = a0 > 0.f ? a0 : 0.2f * a0; float w0 = __expf(a0 - mh);
        a1 += adhd; a1 = a1 > 0.f ? a1 : 0.2f * a1; float w1 = __expf(a1 - mh);
        a2 += adhd; a2 = a2 > 0.f ? a2 : 0.2f * a2; float w2 = __expf(a2 - mh);
        a3 += adhd; a3 = a3 > 0.f ? a3 : 0.2f * a3; float w3 = __expf(a3 - mh);
        acc.x += w0 * h0.x + w1 * h1.x + w2 * h2.x + w3 * h3.x;
        acc.y += w0 * h0.y + w1 * h1.y + w2 * h2.y + w3 * h3.y;
        acc.z += w0 * h0.z + w1 * h1.z + w2 * h2.z + w3 * h3.z;
        acc.w += w0 * h0.w + w1 * h1.w + w2 * h2.w + w3 * h3.w;
    }
    for (; j < end; j++) {
        int src = col[j];
        float v = as_[src * 8 + myh] + adhd;
        v = v > 0.f ? v : 0.2f * v;
        float w = __expf(v - mh);
        float4 hv = h4[(size_t)src * 32 + lane];
        acc.x += w * hv.x; acc.y += w * hv.y; acc.z += w * hv.z; acc.w += w * hv.w;
    }
    const float4* b4 = reinterpret_cast<const float4*>(bias);
    float4 bb = b4[lane];
    float4 r;
    r.x = acc.x * inv + bb.x; r.y = acc.y * inv + bb.y;
    r.z = acc.z * inv + bb.z; r.w = acc.w * inv + bb.w;
    r.x = r.x > 0.f ? r.x : expm1f(r.x);
    r.y = r.y > 0.f ? r.y : expm1f(r.y);
    r.z = r.z > 0.f ? r.z : expm1f(r.z);
    r.w = r.w > 0.f ? r.w : expm1f(r.w);
    reinterpret_cast<float4*>(out)[(size_t)dst * 32 + lane] = r;
}

// ================= fused layer-2 GEMM + att2: C[M,16]=A[M,128]*W2[16,128]^T, as2/ad2 =================
__global__ __launch_bounds__(256)
void gemm2_att2(const float* __restrict__ A, const float* __restrict__ W2,
                const float* __restrict__ at2s, const float* __restrict__ at2d,
                float* __restrict__ h2, float* __restrict__ as2, float* __restrict__ ad2) {
    __shared__ float Ws[16][132];      // padded: rows 16B-aligned, ≤2-way conflicts
    __shared__ float Sv[16], Dv[16];
    int t = threadIdx.x;
    for (int i = t; i < 16 * 32; i += 256) {
        int rr = i >> 5, cc = i & 31;
        *reinterpret_cast<float4*>(&Ws[rr][cc * 4]) =
            *reinterpret_cast<const float4*>(&W2[rr * 128 + cc * 4]);
    }
    if (t < 16) { Sv[t] = at2s[t]; Dv[t] = at2d[t]; }
    __syncthreads();

    int warp = t >> 5, lane = t & 31;
    int half = lane >> 4, c = lane & 15;
    int m = blockIdx.x * 16 + warp * 2 + half;
    if (m >= NN) return;

    const float4* Ar = reinterpret_cast<const float4*>(A + (size_t)m * 128);
    float acc = 0.f;
    #pragma unroll
    for (int k = 0; k < 32; k++) {
        float4 a = Ar[k];
        float4 w = *reinterpret_cast<const float4*>(&Ws[c][k * 4]);
        acc += a.x * w.x + a.y * w.y + a.z * w.z + a.w * w.w;
    }
    h2[(size_t)m * 16 + c] = acc;

    float sv = acc * Sv[c], dv = acc * Dv[c];
    #pragma unroll
    for (int o = 8; o > 0; o >>= 1) {
        sv += __shfl_xor_sync(0xffffffffu, sv, o);
        dv += __shfl_xor_sync(0xffffffffu, dv, o);
    }
    if (c == 0) { as2[m] = sv; ad2[m] = dv; }
}

// ================= layer-2 aggregate fused with bias + log_softmax =================
__global__ __launch_bounds__(256)
void gat_aggregate_l2_lsm(const int* __restrict__ rowptr, const int* __restrict__ col,
                          const float* __restrict__ as_, const float* __restrict__ ad_,
                          const float* __restrict__ hfeat, const float* __restrict__ b2,
                          float* __restrict__ out) {
    int warp = (blockIdx.x * blockDim.x + threadIdx.x) >> 5;
    int lane = threadIdx.x & 31;
    if (warp >= NN) return;
    int dst = warp;
    int beg = rowptr[dst], end = rowptr[dst + 1];
    float adv = ad_[dst];

    // online softmax over incoming edges (unroll x2)
    float m = -INFINITY, s = 0.f;
    int i = beg + lane;
    for (; i + 32 < end; i += 64) {
        float v0 = as_[col[i]] + adv;
        float v1 = as_[col[i + 32]] + adv;
        v0 = v0 > 0.f ? v0 : 0.2f * v0;
        v1 = v1 > 0.f ? v1 : 0.2f * v1;
        float hi = fmaxf(v0, v1), lo = fminf(v0, v1);
        float pl = __expf(lo - hi) + 1.f;
        float nm = fmaxf(m, hi);
        s = s * __expf(m - nm) + pl * __expf(hi - nm);
        m = nm;
    }
    if (i < end) {
        float v = as_[col[i]] + adv;
        v = v > 0.f ? v : 0.2f * v;
        float nm = fmaxf(m, v);
        s = s * __expf(m - nm) + __expf(v - nm);
        m = nm;
    }
    #pragma unroll
    for (int o = 16; o > 0; o >>= 1) {
        float om = __shfl_xor_sync(0xffffffffu, m, o);
        float os = __shfl_xor_sync(0xffffffffu, s, o);
        float nm = fmaxf(m, om);
        float e1 = (m == nm) ? 1.f : __expf(m - nm);
        float e2 = (om == nm) ? 1.f : __expf(om - nm);
        s = s * e1 + os * e2;
        m = nm;
    }
    float inv = 1.f / (s + 1e-16f);

    // aggregate: 2 edges/iter, 16 channels (unroll x2 -> 4 edges in flight)
    int c = lane & 15;
    int sub = lane >> 4;
    float acc = 0.f;
    int j = beg + sub;
    for (; j + 2 < end; j += 4) {
        int s0 = col[j], s1 = col[j + 2];
        float v0 = as_[s0] + adv;
        float v1 = as_[s1] + adv;
        float f0 = hfeat[(size_t)s0 * 16 + c];
        float f1 = hfeat[(size_t)s1 * 16 + c];
        v0 = v0 > 0.f ? v0 : 0.2f * v0;
        v1 = v1 > 0.f ? v1 : 0.2f * v1;
        acc += __expf(v0 - m) * f0 + __expf(v1 - m) * f1;
    }
    if (j < end) {
        int src = col[j];
        float v = as_[src] + adv;
        v = v > 0.f ? v : 0.2f * v;
        acc += __expf(v - m) * hfeat[(size_t)src * 16 + c];
    }
    acc += __shfl_down_sync(0xffffffffu, acc, 16);

    // lanes 0-15 hold the 16 class logits -> bias + log_softmax in-warp
    float val = acc * inv + b2[c];
    float mx = val;
    #pragma unroll
    for (int o = 8; o > 0; o >>= 1) mx = fmaxf(mx, __shfl_xor_sync(0xffffffffu, mx, o));
    float se = __expf(val - mx);
    #pragma unroll
    for (int o = 8; o > 0; o >>= 1) se += __shfl_xor_sync(0xffffffffu, se, o);
    float ls = val - mx - __logf(se);
    if (lane < 16) out[(size_t)dst * 16 + c] = ls;
}

// ================= launch =================
extern "C" void kernel_launch(void* const* d_in, const int* in_sizes, int n_in,
                              void* d_out, int out_size) {
    const float* x    = (const float*)d_in[0];
    const int*   ei   = (const int*)d_in[1];
    const float* W1   = (const float*)d_in[2];
    const float* at1s = (const float*)d_in[3];
    const float* at1d = (const float*)d_in[4];
    const float* b1   = (const float*)d_in[5];
    const float* W2   = (const float*)d_in[6];
    const float* at2s = (const float*)d_in[7];
    const float* at2d = (const float*)d_in[8];
    const float* b2   = (const float*)d_in[9];
    float* out = (float*)d_out;

    int E = in_sizes[1] / 2;

    static float *p_h1 = nullptr, *p_as1, *p_ad1, *p_out1, *p_h2, *p_as2, *p_ad2;
    static int *p_cnt, *p_rowptr, *p_cursor, *p_col;
    static cudaStream_t s2 = nullptr;
    static cudaEvent_t evF = nullptr, evJ = nullptr;
    if (!p_h1) {
        cudaGetSymbolAddress((void**)&p_h1, g_h1);
        cudaGetSymbolAddress((void**)&p_as1, g_as1);
        cudaGetSymbolAddress((void**)&p_ad1, g_ad1);
        cudaGetSymbolAddress((void**)&p_out1, g_out1);
        cudaGetSymbolAddress((void**)&p_h2, g_h2);
        cudaGetSymbolAddress((void**)&p_as2, g_as2);
        cudaGetSymbolAddress((void**)&p_ad2, g_ad2);
        cudaGetSymbolAddress((void**)&p_cnt, g_cnt);
        cudaGetSymbolAddress((void**)&p_rowptr, g_rowptr);
        cudaGetSymbolAddress((void**)&p_cursor, g_cursor);
        cudaGetSymbolAddress((void**)&p_col, g_col);
        cudaStreamCreateWithFlags(&s2, cudaStreamNonBlocking);
        cudaEventCreateWithFlags(&evF, cudaEventDisableTiming);
        cudaEventCreateWithFlags(&evJ, cudaEventDisableTiming);
    }

    const int TB = 256;
    auto blocks = [](int n, int tb) { return (n + tb - 1) / tb; };

    // ---- fork: CSR build on side stream, concurrent with GEMM1/att1 ----
    cudaEventRecord(evF, 0);
    cudaStreamWaitEvent(s2, evF, 0);
    fill_int<<<blocks(NN, TB), TB, 0, s2>>>(p_cnt, 1, NN);
    count_dst<<<blocks(E, TB), TB, 0, s2>>>(ei, p_cnt, E);
    scan_rowptr<<<1, 1024, 0, s2>>>(p_cnt, p_rowptr, p_cursor);
    scatter_edges<<<blocks(E + NN, TB), TB, 0, s2>>>(ei, p_cursor, p_col, E);
    cudaEventRecord(evJ, s2);

    // ---- layer 1 GEMM (tensor, 3xTF32) + attention coefficients ----
    {
        dim3 grid(HC1 / 64, (NN + 127) / 128);
        gemm_tf32x3<<<grid, 256>>>(x, W1, p_h1, NN, NF);
    }
    att_kernel<H1><<<blocks(NN * H1, TB), TB>>>(p_h1, at1s, at1d, p_as1, p_ad1);

    // ---- join: aggregation needs the CSR ----
    cudaStreamWaitEvent(0, evJ, 0);
    gat_aggregate_l1<<<blocks(NN * 32, TB), TB>>>(p_rowptr, p_col, p_as1, p_ad1, p_h1, b1, p_out1);

    // ---- layer 2: fused GEMM+att, then fused aggregate+log_softmax ----
    gemm2_att2<<<blocks(NN, 16), 256>>>(p_out1, W2, at2s, at2d, p_h2, p_as2, p_ad2);
    gat_aggregate_l2_lsm<<<blocks(NN * 32, TB), TB>>>(p_rowptr, p_col, p_as2, p_ad2, p_h2, b2, out);
}

// round 14
// speedup vs baseline: 1.6667x; 1.1261x over previous
#include <cuda_runtime.h>
#include <cuda_fp16.h>
#include <math.h>
#include <stdint.h>

// ---------------- problem constants ----------------
#define NN   50000
#define NE   1600000
#define EPAD (NE + NN)
#define NF   512
#define H1   8
#define C1   16
#define HC1  128
#define C2   16

// ---------------- scratch (device globals) ----------------
__device__ float   g_h1[NN * HC1];
__device__ __half2 g_h1h[NN * 64];        // fp16 copy of h1 for aggregate gather
__device__ float   g_as1[NN * H1];
__device__ float   g_ad1[NN * H1];
__device__ float   g_out1[NN * HC1];
__device__ float   g_h2[NN * C2];
__device__ float   g_as2[NN];
__device__ float   g_ad2[NN];
__device__ int     g_cnt[NN];
__device__ int     g_rowptr[NN + 1];
__device__ int     g_cursor[NN];
__device__ int     g_col[EPAD];

// ================= CSR build =================
__global__ void fill_int(int* p, int v, int n) {
    int i = blockIdx.x * blockDim.x + threadIdx.x;
    if (i < n) p[i] = v;
}

__global__ void count_dst(const int* __restrict__ ei, int* __restrict__ cnt, int E) {
    int e = blockIdx.x * blockDim.x + threadIdx.x;
    if (e < E) atomicAdd(&cnt[ei[E + e]], 1);
}

__global__ void scan_rowptr(const int* __restrict__ cnt, int* __restrict__ rowptr,
                            int* __restrict__ cursor) {
    __shared__ int ssum[1024];
    const int T = 1024;
    const int PER = (NN + T - 1) / T;
    int tid = threadIdx.x;
    int start = tid * PER;
    int local = 0;
    for (int i = 0; i < PER; i++) {
        int idx = start + i;
        if (idx < NN) local += cnt[idx];
    }
    ssum[tid] = local;
    __syncthreads();
    for (int off = 1; off < T; off <<= 1) {
        int v = (tid >= off) ? ssum[tid - off] : 0;
        __syncthreads();
        ssum[tid] += v;
        __syncthreads();
    }
    int run = (tid == 0) ? 0 : ssum[tid - 1];
    for (int i = 0; i < PER; i++) {
        int idx = start + i;
        if (idx < NN) { rowptr[idx] = run; cursor[idx] = run; run += cnt[idx]; }
    }
    if (tid == T - 1) rowptr[NN] = ssum[T - 1];
}

__global__ void scatter_edges(const int* __restrict__ ei, int* __restrict__ cursor,
                              int* __restrict__ col, int E) {
    int i = blockIdx.x * blockDim.x + threadIdx.x;
    int tot = E + NN;
    if (i >= tot) return;
    int s, d;
    if (i < E) { s = ei[i]; d = ei[E + i]; } else { s = d = i - E; }
    int pos = atomicAdd(&cursor[d], 1);
    col[pos] = s;
}

// ================= 3xTF32 tensor-core GEMM (NT): C[M,128] = A[M,K]*B[128,K]^T =================
__device__ __forceinline__ void split_tf32(float x, uint32_t& hi, uint32_t& lo) {
    uint32_t h;
    asm("cvt.rna.tf32.f32 %0, %1;" : "=r"(h) : "f"(x));
    float r = x - __uint_as_float(h);
    uint32_t l;
    asm("cvt.rna.tf32.f32 %0, %1;" : "=r"(l) : "f"(r));
    hi = h; lo = l;
}

__device__ __forceinline__ void mma_tf32(float* d, const uint32_t* a, const uint32_t* b) {
    asm volatile(
        "mma.sync.aligned.m16n8k8.row.col.f32.tf32.tf32.f32 "
        "{%0,%1,%2,%3}, {%4,%5,%6,%7}, {%8,%9}, {%0,%1,%2,%3};"
        : "+f"(d[0]), "+f"(d[1]), "+f"(d[2]), "+f"(d[3])
        : "r"(a[0]), "r"(a[1]), "r"(a[2]), "r"(a[3]), "r"(b[0]), "r"(b[1]));
}

#define TSTRIDE 20

__global__ __launch_bounds__(256, 2)
void gemm_tf32x3(const float* __restrict__ A, const float* __restrict__ B,
                 float* __restrict__ C, __half2* __restrict__ Ch, int M, int K) {
    __shared__ float As[128][TSTRIDE];
    __shared__ float Bs[64][TSTRIDE];

    const int Nn = 128;
    int t = threadIdx.x;
    int lane = t & 31;
    int warp = t >> 5;
    int wm = warp & 3;
    int wn = warp >> 2;
    int g  = lane >> 2;
    int tg = lane & 3;

    int m0 = blockIdx.y * 128;
    int n0 = blockIdx.x * 64;

    int f2 = t + 256;
    int ar1 = t >> 2,  ac1 = (t & 3) * 4;
    int ar2 = f2 >> 2, ac2 = (f2 & 3) * 4;
    int br  = t >> 2,  bc  = (t & 3) * 4;

    bool a1ok = (m0 + ar1) < M;
    bool a2ok = (m0 + ar2) < M;
    const float4* Ap1 = a1ok ? reinterpret_cast<const float4*>(&A[(size_t)(m0 + ar1) * K + ac1]) : nullptr;
    const float4* Ap2 = a2ok ? reinterpret_cast<const float4*>(&A[(size_t)(m0 + ar2) * K + ac2]) : nullptr;
    const float4* Bp  = reinterpret_cast<const float4*>(&B[(size_t)(n0 + br) * K + bc]);

    float4 pa1 = a1ok ? Ap1[0] : make_float4(0, 0, 0, 0);
    float4 pa2 = a2ok ? Ap2[0] : make_float4(0, 0, 0, 0);
    float4 pb  = Bp[0];

    float d[2][4][4];
    #pragma unroll
    for (int i = 0; i < 2; i++)
        #pragma unroll
        for (int j = 0; j < 4; j++)
            #pragma unroll
            for (int q = 0; q < 4; q++) d[i][j][q] = 0.f;

    for (int k0 = 0; k0 < K; k0 += 16) {
        *reinterpret_cast<float4*>(&As[ar1][ac1]) = pa1;
        *reinterpret_cast<float4*>(&As[ar2][ac2]) = pa2;
        *reinterpret_cast<float4*>(&Bs[br][bc])   = pb;
        __syncthreads();

        if (k0 + 16 < K) {
            int idx = (k0 + 16) >> 2;
            pa1 = a1ok ? Ap1[idx] : make_float4(0, 0, 0, 0);
            pa2 = a2ok ? Ap2[idx] : make_float4(0, 0, 0, 0);
            pb  = Bp[idx];
        }

        #pragma unroll
        for (int ks = 0; ks < 2; ks++) {
            int kb = ks * 8;
            uint32_t ah[2][4], al[2][4], bh[4][2], bl[4][2];
            #pragma unroll
            for (int mt = 0; mt < 2; mt++) {
                int r0 = wm * 32 + mt * 16 + g;
                split_tf32(As[r0][kb + tg],          ah[mt][0], al[mt][0]);
                split_tf32(As[r0 + 8][kb + tg],      ah[mt][1], al[mt][1]);
                split_tf32(As[r0][kb + tg + 4],      ah[mt][2], al[mt][2]);
                split_tf32(As[r0 + 8][kb + tg + 4],  ah[mt][3], al[mt][3]);
            }
            #pragma unroll
            for (int nt = 0; nt < 4; nt++) {
                int n = wn * 32 + nt * 8 + g;
                split_tf32(Bs[n][kb + tg],     bh[nt][0], bl[nt][0]);
                split_tf32(Bs[n][kb + tg + 4], bh[nt][1], bl[nt][1]);
            }
            #pragma unroll
            for (int mt = 0; mt < 2; mt++)
                #pragma unroll
                for (int nt = 0; nt < 4; nt++) {
                    mma_tf32(d[mt][nt], ah[mt], bh[nt]);
                    mma_tf32(d[mt][nt], ah[mt], bl[nt]);
                    mma_tf32(d[mt][nt], al[mt], bh[nt]);
                }
        }
        __syncthreads();
    }

    #pragma unroll
    for (int mt = 0; mt < 2; mt++) {
        int r0 = m0 + wm * 32 + mt * 16 + g;
        #pragma unroll
        for (int nt = 0; nt < 4; nt++) {
            int c = n0 + wn * 32 + nt * 8 + tg * 2;
            if (r0 < M) {
                *reinterpret_cast<float2*>(&C[(size_t)r0 * Nn + c]) =
                    make_float2(d[mt][nt][0], d[mt][nt][1]);
                Ch[(size_t)r0 * 64 + (c >> 1)] = __floats2half2_rn(d[mt][nt][0], d[mt][nt][1]);
            }
            if (r0 + 8 < M) {
                *reinterpret_cast<float2*>(&C[(size_t)(r0 + 8) * Nn + c]) =
                    make_float2(d[mt][nt][2], d[mt][nt][3]);
                Ch[(size_t)(r0 + 8) * 64 + (c >> 1)] = __floats2half2_rn(d[mt][nt][2], d[mt][nt][3]);
            }
        }
    }
}

// ================= attention coefficients layer 1 (C=16, float4) =================
template<int H>
__global__ void att_kernel(const float* __restrict__ h, const float* __restrict__ att_s,
                           const float* __restrict__ att_d, float* __restrict__ as_,
                           float* __restrict__ ad_) {
    int idx = blockIdx.x * blockDim.x + threadIdx.x;
    if (idx >= NN * H) return;
    int hh = idx & (H - 1);
    const float4* hp = reinterpret_cast<const float4*>(h) + (size_t)idx * 4;
    const float4* sp = reinterpret_cast<const float4*>(att_s) + hh * 4;
    const float4* dp = reinterpret_cast<const float4*>(att_d) + hh * 4;
    float s = 0.f, d = 0.f;
    #pragma unroll
    for (int q = 0; q < 4; q++) {
        float4 v = hp[q], a = sp[q], b = dp[q];
        s += v.x * a.x + v.y * a.y + v.z * a.z + v.w * a.w;
        d += v.x * b.x + v.y * b.y + v.z * b.z + v.w * b.w;
    }
    as_[idx] = s;
    ad_[idx] = d;
}

// ================= layer-1 single-sweep aggregate (online rescale, fp16 gather) =================
// One warp per dst. Lane owns head (lane>>2), channels 4*(lane&3)..+3 via half2 pair.
__global__ __launch_bounds__(256)
void gat_aggregate_l1(const int* __restrict__ rowptr, const int* __restrict__ col,
                      const float* __restrict__ as_, const float* __restrict__ ad_,
                      const __half2* __restrict__ hfeat, const float* __restrict__ bias,
                      float* __restrict__ out) {
    int warp = (blockIdx.x * blockDim.x + threadIdx.x) >> 5;
    int lane = threadIdx.x & 31;
    if (warp >= NN) return;
    int dst = warp;
    int beg = rowptr[dst], end = rowptr[dst + 1];

    int myh = lane >> 2;
    float adhd = ad_[dst * 8 + myh];

    float m = -INFINITY, s = 0.f;
    float4 acc = make_float4(0.f, 0.f, 0.f, 0.f);

    const __half2* hp = hfeat + (size_t)0;
    int hoff = lane * 2;

    int j = beg;
    for (; j + 2 <= end; j += 2) {
        int s0 = col[j], s1 = col[j + 1];
        float a0 = as_[s0 * 8 + myh];
        float a1 = as_[s1 * 8 + myh];
        __half2 p00 = hp[(size_t)s0 * 64 + hoff];
        __half2 p01 = hp[(size_t)s0 * 64 + hoff + 1];
        __half2 p10 = hp[(size_t)s1 * 64 + hoff];
        __half2 p11 = hp[(size_t)s1 * 64 + hoff + 1];

        float v0 = a0 + adhd; v0 = v0 > 0.f ? v0 : 0.2f * v0;
        float v1 = a1 + adhd; v1 = v1 > 0.f ? v1 : 0.2f * v1;
        float hi2 = fmaxf(v0, v1);
        float nm = fmaxf(m, hi2);
        float sc = __expf(m - nm);           // 0 when m=-inf
        float w0 = __expf(v0 - nm);
        float w1 = __expf(v1 - nm);
        s = s * sc + w0 + w1;
        float2 f00 = __half22float2(p00), f01 = __half22float2(p01);
        float2 f10 = __half22float2(p10), f11 = __half22float2(p11);
        acc.x = acc.x * sc + w0 * f00.x + w1 * f10.x;
        acc.y = acc.y * sc + w0 * f00.y + w1 * f10.y;
        acc.z = acc.z * sc + w0 * f01.x + w1 * f11.x;
        acc.w = acc.w * sc + w0 * f01.y + w1 * f11.y;
        m = nm;
    }
    if (j < end) {
        int s0 = col[j];
        float a0 = as_[s0 * 8 + myh];
        __half2 p00 = hp[(size_t)s0 * 64 + hoff];
        __half2 p01 = hp[(size_t)s0 * 64 + hoff + 1];
        float v0 = a0 + adhd; v0 = v0 > 0.f ? v0 : 0.2f * v0;
        float nm = fmaxf(m, v0);
        float sc = __expf(m - nm);
        float w0 = __expf(v0 - nm);
        s = s * sc + w0;
        float2 f00 = __half22float2(p00), f01 = __half22float2(p01);
        acc.x = acc.x * sc + w0 * f00.x;
        acc.y = acc.y * sc + w0 * f00.y;
        acc.z = acc.z * sc + w0 * f01.x;
        acc.w = acc.w * sc + w0 * f01.y;
        m = nm;
    }

    float inv = 1.f / (s + 1e-16f);
    const float4* b4 = reinterpret_cast<const float4*>(bias);
    float4 bb = b4[lane];
    float4 r;
    r.x = acc.x * inv + bb.x; r.y = acc.y * inv + bb.y;
    r.z = acc.z * inv + bb.z; r.w = acc.w * inv + bb.w;
    r.x = r.x > 0.f ? r.x : expm1f(r.x);
    r.y = r.y > 0.f ? r.y : expm1f(r.y);
    r.z = r.z > 0.f ? r.z : expm1f(r.z);
    r.w = r.w > 0.f ? r.w : expm1f(r.w);
    reinterpret_cast<float4*>(out)[(size_t)dst * 32 + lane] = r;
}

// ================= fused layer-2 GEMM + att2 =================
__global__ __launch_bounds__(256)
void gemm2_att2(const float* __restrict__ A, const float* __restrict__ W2,
                const float* __restrict__ at2s, const float* __restrict__ at2d,
                float* __restrict__ h2, float* __restrict__ as2, float* __restrict__ ad2) {
    __shared__ float Ws[16][132];
    __shared__ float Sv[16], Dv[16];
    int t = threadIdx.x;
    for (int i = t; i < 16 * 32; i += 256) {
        int rr = i >> 5, cc = i & 31;
        *reinterpret_cast<float4*>(&Ws[rr][cc * 4]) =
            *reinterpret_cast<const float4*>(&W2[rr * 128 + cc * 4]);
    }
    if (t < 16) { Sv[t] = at2s[t]; Dv[t] = at2d[t]; }
    __syncthreads();

    int warp = t >> 5, lane = t & 31;
    int half = lane >> 4, c = lane & 15;
    int m = blockIdx.x * 16 + warp * 2 + half;
    if (m >= NN) return;

    const float4* Ar = reinterpret_cast<const float4*>(A + (size_t)m * 128);
    float acc = 0.f;
    #pragma unroll
    for (int k = 0; k < 32; k++) {
        float4 a = Ar[k];
        float4 w = *reinterpret_cast<const float4*>(&Ws[c][k * 4]);
        acc += a.x * w.x + a.y * w.y + a.z * w.z + a.w * w.w;
    }
    h2[(size_t)m * 16 + c] = acc;

    float sv = acc * Sv[c], dv = acc * Dv[c];
    #pragma unroll
    for (int o = 8; o > 0; o >>= 1) {
        sv += __shfl_xor_sync(0xffffffffu, sv, o);
        dv += __shfl_xor_sync(0xffffffffu, dv, o);
    }
    if (c == 0) { as2[m] = sv; ad2[m] = dv; }
}

// ================= layer-2 single-sweep aggregate + bias + log_softmax =================
__global__ __launch_bounds__(256)
void gat_aggregate_l2_lsm(const int* __restrict__ rowptr, const int* __restrict__ col,
                          const float* __restrict__ as_, const float* __restrict__ ad_,
                          const float* __restrict__ hfeat, const float* __restrict__ b2,
                          float* __restrict__ out) {
    int warp = (blockIdx.x * blockDim.x + threadIdx.x) >> 5;
    int lane = threadIdx.x & 31;
    if (warp >= NN) return;
    int dst = warp;
    int beg = rowptr[dst], end = rowptr[dst + 1];
    float adv = ad_[dst];

    int c = lane & 15;
    int sub = lane >> 4;

    // each 16-lane half processes alternate edges with online rescale
    float m = -INFINITY, s = 0.f, acc = 0.f;
    int j = beg + sub;
    for (; j + 2 < end; j += 4) {
        int s0 = col[j], s1 = col[j + 2];
        float a0 = as_[s0], a1 = as_[s1];
        float f0 = hfeat[(size_t)s0 * 16 + c];
        float f1 = hfeat[(size_t)s1 * 16 + c];
        float v0 = a0 + adv; v0 = v0 > 0.f ? v0 : 0.2f * v0;
        float v1 = a1 + adv; v1 = v1 > 0.f ? v1 : 0.2f * v1;
        float nm = fmaxf(m, fmaxf(v0, v1));
        float sc = __expf(m - nm);
        float w0 = __expf(v0 - nm);
        float w1 = __expf(v1 - nm);
        s = s * sc + w0 + w1;
        acc = acc * sc + w0 * f0 + w1 * f1;
        m = nm;
    }
    if (j < end) {
        int s0 = col[j];
        float v0 = as_[s0] + adv; v0 = v0 > 0.f ? v0 : 0.2f * v0;
        float f0 = hfeat[(size_t)s0 * 16 + c];
        float nm = fmaxf(m, v0);
        float sc = __expf(m - nm);
        float w0 = __expf(v0 - nm);
        s = s * sc + w0;
        acc = acc * sc + w0 * f0;
        m = nm;
    }

    // combine the two halves (sub0 always non-empty: self loop)
    float om = __shfl_xor_sync(0xffffffffu, m, 16);
    float os = __shfl_xor_sync(0xffffffffu, s, 16);
    float oa = __shfl_xor_sync(0xffffffffu, acc, 16);
    float nm = fmaxf(m, om);
    float e1 = __expf(m - nm);     // safe: nm finite, m may be -inf -> 0
    float e2 = __expf(om - nm);
    s = s * e1 + os * e2;
    acc = acc * e1 + oa * e2;

    float inv = 1.f / (s + 1e-16f);
    float val = acc * inv + b2[c];

    // in-warp log_softmax over 16 classes (lanes 0-15 and 16-31 hold identical values)
    float mx = val;
    #pragma unroll
    for (int o = 8; o > 0; o >>= 1) mx = fmaxf(mx, __shfl_xor_sync(0xffffffffu, mx, o));
    float se = __expf(val - mx);
    #pragma unroll
    for (int o = 8; o > 0; o >>= 1) se += __shfl_xor_sync(0xffffffffu, se, o);
    float ls = val - mx - __logf(se);
    if (lane < 16) out[(size_t)dst * 16 + c] = ls;
}

// ================= launch =================
extern "C" void kernel_launch(void* const* d_in, const int* in_sizes, int n_in,
                              void* d_out, int out_size) {
    const float* x    = (const float*)d_in[0];
    const int*   ei   = (const int*)d_in[1];
    const float* W1   = (const float*)d_in[2];
    const float* at1s = (const float*)d_in[3];
    const float* at1d = (const float*)d_in[4];
    const float* b1   = (const float*)d_in[5];
    const float* W2   = (const float*)d_in[6];
    const float* at2s = (const float*)d_in[7];
    const float* at2d = (const float*)d_in[8];
    const float* b2   = (const float*)d_in[9];
    float* out = (float*)d_out;

    int E = in_sizes[1] / 2;

    static float *p_h1 = nullptr, *p_as1, *p_ad1, *p_out1, *p_h2, *p_as2, *p_ad2;
    static __half2* p_h1h;
    static int *p_cnt, *p_rowptr, *p_cursor, *p_col;
    static cudaStream_t s2 = nullptr;
    static cudaEvent_t evF = nullptr, evJ = nullptr;
    if (!p_h1) {
        cudaGetSymbolAddress((void**)&p_h1, g_h1);
        cudaGetSymbolAddress((void**)&p_h1h, g_h1h);
        cudaGetSymbolAddress((void**)&p_as1, g_as1);
        cudaGetSymbolAddress((void**)&p_ad1, g_ad1);
        cudaGetSymbolAddress((void**)&p_out1, g_out1);
        cudaGetSymbolAddress((void**)&p_h2, g_h2);
        cudaGetSymbolAddress((void**)&p_as2, g_as2);
        cudaGetSymbolAddress((void**)&p_ad2, g_ad2);
        cudaGetSymbolAddress((void**)&p_cnt, g_cnt);
        cudaGetSymbolAddress((void**)&p_rowptr, g_rowptr);
        cudaGetSymbolAddress((void**)&p_cursor, g_cursor);
        cudaGetSymbolAddress((void**)&p_col, g_col);
        cudaStreamCreateWithFlags(&s2, cudaStreamNonBlocking);
        cudaEventCreateWithFlags(&evF, cudaEventDisableTiming);
        cudaEventCreateWithFlags(&evJ, cudaEventDisableTiming);
    }

    const int TB = 256;
    auto blocks = [](int n, int tb) { return (n + tb - 1) / tb; };

    // ---- fork: CSR build on side stream, concurrent with GEMM1/att1 ----
    cudaEventRecord(evF, 0);
    cudaStreamWaitEvent(s2, evF, 0);
    fill_int<<<blocks(NN, TB), TB, 0, s2>>>(p_cnt, 1, NN);
    count_dst<<<blocks(E, TB), TB, 0, s2>>>(ei, p_cnt, E);
    scan_rowptr<<<1, 1024, 0, s2>>>(p_cnt, p_rowptr, p_cursor);
    scatter_edges<<<blocks(E + NN, TB), TB, 0, s2>>>(ei, p_cursor, p_col, E);
    cudaEventRecord(evJ, s2);

    // ---- layer 1 GEMM (tensor, 3xTF32, dual fp32+fp16 output) + attention coefficients ----
    {
        dim3 grid(HC1 / 64, (NN + 127) / 128);
        gemm_tf32x3<<<grid, 256>>>(x, W1, p_h1, p_h1h, NN, NF);
    }
    att_kernel<H1><<<blocks(NN * H1, TB), TB>>>(p_h1, at1s, at1d, p_as1, p_ad1);

    // ---- join: aggregation needs the CSR ----
    cudaStreamWaitEvent(0, evJ, 0);
    gat_aggregate_l1<<<blocks(NN * 32, TB), TB>>>(p_rowptr, p_col, p_as1, p_ad1, p_h1h, b1, p_out1);

    // ---- layer 2: fused GEMM+att, then fused aggregate+log_softmax ----
    gemm2_att2<<<blocks(NN, 16), 256>>>(p_out1, W2, at2s, at2d, p_h2, p_as2, p_ad2);
    gat_aggregate_l2_lsm<<<blocks(NN * 32, TB), TB>>>(p_rowptr, p_col, p_as2, p_ad2, p_h2, b2, out);
}

// round 15
// speedup vs baseline: 1.7591x; 1.0555x over previous
#include <cuda_runtime.h>
#include <cuda_fp16.h>
#include <math.h>
#include <stdint.h>

// ---------------- problem constants ----------------
#define NN   50000
#define NE   1600000
#define EPAD (NE + NN)
#define NF   512
#define H1   8
#define C1   16
#define HC1  128
#define C2   16

// ---------------- scratch (device globals) ----------------
__device__ __half2 g_h1h[NN * 64];        // fp16 h1 (only copy)
__device__ float   g_w1t[HC1 * NF];       // W1 pre-rounded to tf32
__device__ float   g_as1[NN * H1];
__device__ float   g_ad1[NN * H1];
__device__ float   g_out1[NN * HC1];
__device__ __half  g_h2h[NN * C2];
__device__ float   g_as2[NN];
__device__ float   g_ad2[NN];
__device__ int     g_cnt[NN];
__device__ int     g_rowptr[NN + 1];
__device__ int     g_cursor[NN];
__device__ int     g_col[EPAD];

// ================= CSR build =================
__global__ void fill_int(int* p, int v, int n) {
    int i = blockIdx.x * blockDim.x + threadIdx.x;
    if (i < n) p[i] = v;
}

__global__ void count_dst(const int* __restrict__ ei, int* __restrict__ cnt, int E) {
    int e = blockIdx.x * blockDim.x + threadIdx.x;
    if (e < E) atomicAdd(&cnt[ei[E + e]], 1);
}

__global__ void scan_rowptr(const int* __restrict__ cnt, int* __restrict__ rowptr,
                            int* __restrict__ cursor) {
    __shared__ int ssum[1024];
    const int T = 1024;
    const int PER = (NN + T - 1) / T;
    int tid = threadIdx.x;
    int start = tid * PER;
    int local = 0;
    for (int i = 0; i < PER; i++) {
        int idx = start + i;
        if (idx < NN) local += cnt[idx];
    }
    ssum[tid] = local;
    __syncthreads();
    for (int off = 1; off < T; off <<= 1) {
        int v = (tid >= off) ? ssum[tid - off] : 0;
        __syncthreads();
        ssum[tid] += v;
        __syncthreads();
    }
    int run = (tid == 0) ? 0 : ssum[tid - 1];
    for (int i = 0; i < PER; i++) {
        int idx = start + i;
        if (idx < NN) { rowptr[idx] = run; cursor[idx] = run; run += cnt[idx]; }
    }
    if (tid == T - 1) rowptr[NN] = ssum[T - 1];
}

__global__ void scatter_edges(const int* __restrict__ ei, int* __restrict__ cursor,
                              int* __restrict__ col, int E) {
    int i = blockIdx.x * blockDim.x + threadIdx.x;
    int tot = E + NN;
    if (i >= tot) return;
    int s, d;
    if (i < E) { s = ei[i]; d = ei[E + i]; } else { s = d = i - E; }
    int pos = atomicAdd(&cursor[d], 1);
    col[pos] = s;
}

// ================= W1 -> tf32 pre-round =================
__global__ void w1_round(const float* __restrict__ W1, float* __restrict__ W1t, int n) {
    int i = blockIdx.x * blockDim.x + threadIdx.x;
    if (i >= n) return;
    uint32_t h;
    asm("cvt.rna.tf32.f32 %0, %1;" : "=r"(h) : "f"(W1[i]));
    W1t[i] = __uint_as_float(h);
}

// ================= 2-pass TF32 GEMM + fused att1 epilogue =================
// C_half[M,128] = A[M,K]*B[128,K]^T ; B pre-rounded tf32. Also emits as1/ad1.
__device__ __forceinline__ void split_tf32(float x, uint32_t& hi, uint32_t& lo) {
    uint32_t h;
    asm("cvt.rna.tf32.f32 %0, %1;" : "=r"(h) : "f"(x));
    float r = x - __uint_as_float(h);
    uint32_t l;
    asm("cvt.rna.tf32.f32 %0, %1;" : "=r"(l) : "f"(r));
    hi = h; lo = l;
}

__device__ __forceinline__ void mma_tf32(float* d, const uint32_t* a, const uint32_t* b) {
    asm volatile(
        "mma.sync.aligned.m16n8k8.row.col.f32.tf32.tf32.f32 "
        "{%0,%1,%2,%3}, {%4,%5,%6,%7}, {%8,%9}, {%0,%1,%2,%3};"
        : "+f"(d[0]), "+f"(d[1]), "+f"(d[2]), "+f"(d[3])
        : "r"(a[0]), "r"(a[1]), "r"(a[2]), "r"(a[3]), "r"(b[0]), "r"(b[1]));
}

#define TSTRIDE 20

__global__ __launch_bounds__(256, 2)
void gemm_tf32x2_att(const float* __restrict__ A, const float* __restrict__ B,
                     __half2* __restrict__ Ch,
                     const float* __restrict__ att_s, const float* __restrict__ att_d,
                     float* __restrict__ as_, float* __restrict__ ad_,
                     int M, int K) {
    __shared__ float As[128][TSTRIDE];
    __shared__ float Bs[64][TSTRIDE];

    int t = threadIdx.x;
    int lane = t & 31;
    int warp = t >> 5;
    int wm = warp & 3;
    int wn = warp >> 2;
    int g  = lane >> 2;
    int tg = lane & 3;

    int m0 = blockIdx.y * 128;
    int n0 = blockIdx.x * 64;

    int f2 = t + 256;
    int ar1 = t >> 2,  ac1 = (t & 3) * 4;
    int ar2 = f2 >> 2, ac2 = (f2 & 3) * 4;
    int br  = t >> 2,  bc  = (t & 3) * 4;

    bool a1ok = (m0 + ar1) < M;
    bool a2ok = (m0 + ar2) < M;
    const float4* Ap1 = a1ok ? reinterpret_cast<const float4*>(&A[(size_t)(m0 + ar1) * K + ac1]) : nullptr;
    const float4* Ap2 = a2ok ? reinterpret_cast<const float4*>(&A[(size_t)(m0 + ar2) * K + ac2]) : nullptr;
    const float4* Bp  = reinterpret_cast<const float4*>(&B[(size_t)(n0 + br) * K + bc]);

    float4 pa1 = a1ok ? Ap1[0] : make_float4(0, 0, 0, 0);
    float4 pa2 = a2ok ? Ap2[0] : make_float4(0, 0, 0, 0);
    float4 pb  = Bp[0];

    float d[2][4][4];
    #pragma unroll
    for (int i = 0; i < 2; i++)
        #pragma unroll
        for (int j = 0; j < 4; j++)
            #pragma unroll
            for (int q = 0; q < 4; q++) d[i][j][q] = 0.f;

    for (int k0 = 0; k0 < K; k0 += 16) {
        *reinterpret_cast<float4*>(&As[ar1][ac1]) = pa1;
        *reinterpret_cast<float4*>(&As[ar2][ac2]) = pa2;
        *reinterpret_cast<float4*>(&Bs[br][bc])   = pb;
        __syncthreads();

        if (k0 + 16 < K) {
            int idx = (k0 + 16) >> 2;
            pa1 = a1ok ? Ap1[idx] : make_float4(0, 0, 0, 0);
            pa2 = a2ok ? Ap2[idx] : make_float4(0, 0, 0, 0);
            pb  = Bp[idx];
        }

        #pragma unroll
        for (int ks = 0; ks < 2; ks++) {
            int kb = ks * 8;
            uint32_t ah[2][4], al[2][4], bh[4][2];
            #pragma unroll
            for (int mt = 0; mt < 2; mt++) {
                int r0 = wm * 32 + mt * 16 + g;
                split_tf32(As[r0][kb + tg],          ah[mt][0], al[mt][0]);
                split_tf32(As[r0 + 8][kb + tg],      ah[mt][1], al[mt][1]);
                split_tf32(As[r0][kb + tg + 4],      ah[mt][2], al[mt][2]);
                split_tf32(As[r0 + 8][kb + tg + 4],  ah[mt][3], al[mt][3]);
            }
            #pragma unroll
            for (int nt = 0; nt < 4; nt++) {
                int n = wn * 32 + nt * 8 + g;
                bh[nt][0] = __float_as_uint(Bs[n][kb + tg]);       // pre-rounded tf32
                bh[nt][1] = __float_as_uint(Bs[n][kb + tg + 4]);
            }
            #pragma unroll
            for (int mt = 0; mt < 2; mt++)
                #pragma unroll
                for (int nt = 0; nt < 4; nt++) {
                    mma_tf32(d[mt][nt], ah[mt], bh[nt]);
                    mma_tf32(d[mt][nt], al[mt], bh[nt]);
                }
        }
        __syncthreads();
    }

    // ---- epilogue: write fp16 h1 and fused attention coefficients ----
    int baseHead = (n0 + wn * 32) >> 4;           // 2 heads per warp: baseHead, baseHead+1

    float ps[2][2][2], pd[2][2][2];               // [mt][rowhalf][headidx]
    #pragma unroll
    for (int a = 0; a < 2; a++)
        #pragma unroll
        for (int b = 0; b < 2; b++)
            #pragma unroll
            for (int cdx = 0; cdx < 2; cdx++) { ps[a][b][cdx] = 0.f; pd[a][b][cdx] = 0.f; }

    #pragma unroll
    for (int mt = 0; mt < 2; mt++) {
        int r0 = m0 + wm * 32 + mt * 16 + g;
        #pragma unroll
        for (int nt = 0; nt < 4; nt++) {
            int c = n0 + wn * 32 + nt * 8 + tg * 2;
            int head = baseHead + (nt >> 1);
            int ch0 = c & 15;
            float ws0 = att_s[head * 16 + ch0], ws1 = att_s[head * 16 + ch0 + 1];
            float wd0 = att_d[head * 16 + ch0], wd1 = att_d[head * 16 + ch0 + 1];
            int hi = nt >> 1;
            ps[mt][0][hi] += d[mt][nt][0] * ws0 + d[mt][nt][1] * ws1;
            ps[mt][1][hi] += d[mt][nt][2] * ws0 + d[mt][nt][3] * ws1;
            pd[mt][0][hi] += d[mt][nt][0] * wd0 + d[mt][nt][1] * wd1;
            pd[mt][1][hi] += d[mt][nt][2] * wd0 + d[mt][nt][3] * wd1;

            if (r0 < M)
                Ch[(size_t)r0 * 64 + (c >> 1)] = __floats2half2_rn(d[mt][nt][0], d[mt][nt][1]);
            if (r0 + 8 < M)
                Ch[(size_t)(r0 + 8) * 64 + (c >> 1)] = __floats2half2_rn(d[mt][nt][2], d[mt][nt][3]);
        }
    }

    // reduce over the 4 tg lanes (quad)
    #pragma unroll
    for (int a = 0; a < 2; a++)
        #pragma unroll
        for (int b = 0; b < 2; b++)
            #pragma unroll
            for (int cdx = 0; cdx < 2; cdx++) {
                float vs = ps[a][b][cdx], vd = pd[a][b][cdx];
                vs += __shfl_xor_sync(0xffffffffu, vs, 1);
                vs += __shfl_xor_sync(0xffffffffu, vs, 2);
                vd += __shfl_xor_sync(0xffffffffu, vd, 1);
                vd += __shfl_xor_sync(0xffffffffu, vd, 2);
                ps[a][b][cdx] = vs; pd[a][b][cdx] = vd;
            }

    if (tg == 0) {
        #pragma unroll
        for (int mt = 0; mt < 2; mt++) {
            #pragma unroll
            for (int rh = 0; rh < 2; rh++) {
                int row = m0 + wm * 32 + mt * 16 + g + rh * 8;
                if (row < M) {
                    #pragma unroll
                    for (int hi = 0; hi < 2; hi++) {
                        as_[row * 8 + baseHead + hi] = ps[mt][rh][hi];
                        ad_[row * 8 + baseHead + hi] = pd[mt][rh][hi];
                    }
                }
            }
        }
    }
}

// ================= layer-1 single-sweep aggregate (online rescale, fp16 gather) =================
__global__ __launch_bounds__(256)
void gat_aggregate_l1(const int* __restrict__ rowptr, const int* __restrict__ col,
                      const float* __restrict__ as_, const float* __restrict__ ad_,
                      const __half2* __restrict__ hfeat, const float* __restrict__ bias,
                      float* __restrict__ out) {
    int warp = (blockIdx.x * blockDim.x + threadIdx.x) >> 5;
    int lane = threadIdx.x & 31;
    if (warp >= NN) return;
    int dst = warp;
    int beg = rowptr[dst], end = rowptr[dst + 1];

    int myh = lane >> 2;
    float adhd = ad_[dst * 8 + myh];

    float m = -INFINITY, s = 0.f;
    float4 acc = make_float4(0.f, 0.f, 0.f, 0.f);

    const uint2* hp = reinterpret_cast<const uint2*>(hfeat);   // 8B = 4 halves per lane

    int j = beg;
    for (; j + 2 <= end; j += 2) {
        int s0 = col[j], s1 = col[j + 1];
        float a0 = as_[s0 * 8 + myh];
        float a1 = as_[s1 * 8 + myh];
        uint2 u0 = hp[(size_t)s0 * 32 + lane];
        uint2 u1 = hp[(size_t)s1 * 32 + lane];

        float v0 = a0 + adhd; v0 = v0 > 0.f ? v0 : 0.2f * v0;
        float v1 = a1 + adhd; v1 = v1 > 0.f ? v1 : 0.2f * v1;
        float nm = fmaxf(m, fmaxf(v0, v1));
        float sc = __expf(m - nm);
        float w0 = __expf(v0 - nm);
        float w1 = __expf(v1 - nm);
        s = s * sc + w0 + w1;
        float2 f00 = __half22float2(*reinterpret_cast<__half2*>(&u0.x));
        float2 f01 = __half22float2(*reinterpret_cast<__half2*>(&u0.y));
        float2 f10 = __half22float2(*reinterpret_cast<__half2*>(&u1.x));
        float2 f11 = __half22float2(*reinterpret_cast<__half2*>(&u1.y));
        acc.x = acc.x * sc + w0 * f00.x + w1 * f10.x;
        acc.y = acc.y * sc + w0 * f00.y + w1 * f10.y;
        acc.z = acc.z * sc + w0 * f01.x + w1 * f11.x;
        acc.w = acc.w * sc + w0 * f01.y + w1 * f11.y;
        m = nm;
    }
    if (j < end) {
        int s0 = col[j];
        float a0 = as_[s0 * 8 + myh];
        uint2 u0 = hp[(size_t)s0 * 32 + lane];
        float v0 = a0 + adhd; v0 = v0 > 0.f ? v0 : 0.2f * v0;
        float nm = fmaxf(m, v0);
        float sc = __expf(m - nm);
        float w0 = __expf(v0 - nm);
        s = s * sc + w0;
        float2 f00 = __half22float2(*reinterpret_cast<__half2*>(&u0.x));
        float2 f01 = __half22float2(*reinterpret_cast<__half2*>(&u0.y));
        acc.x = acc.x * sc + w0 * f00.x;
        acc.y = acc.y * sc + w0 * f00.y;
        acc.z = acc.z * sc + w0 * f01.x;
        acc.w = acc.w * sc + w0 * f01.y;
        m = nm;
    }

    float inv = 1.f / (s + 1e-16f);
    const float4* b4 = reinterpret_cast<const float4*>(bias);
    float4 bb = b4[lane];
    float4 r;
    r.x = acc.x * inv + bb.x; r.y = acc.y * inv + bb.y;
    r.z = acc.z * inv + bb.z; r.w = acc.w * inv + bb.w;
    r.x = r.x > 0.f ? r.x : expm1f(r.x);
    r.y = r.y > 0.f ? r.y : expm1f(r.y);
    r.z = r.z > 0.f ? r.z : expm1f(r.z);
    r.w = r.w > 0.f ? r.w : expm1f(r.w);
    reinterpret_cast<float4*>(out)[(size_t)dst * 32 + lane] = r;
}

// ================= fused layer-2 GEMM + att2 (fp16 h2 out) =================
__global__ __launch_bounds__(256)
void gemm2_att2(const float* __restrict__ A, const float* __restrict__ W2,
                const float* __restrict__ at2s, const float* __restrict__ at2d,
                __half* __restrict__ h2h, float* __restrict__ as2, float* __restrict__ ad2) {
    __shared__ float Ws[16][132];
    __shared__ float Sv[16], Dv[16];
    int t = threadIdx.x;
    for (int i = t; i < 16 * 32; i += 256) {
        int rr = i >> 5, cc = i & 31;
        *reinterpret_cast<float4*>(&Ws[rr][cc * 4]) =
            *reinterpret_cast<const float4*>(&W2[rr * 128 + cc * 4]);
    }
    if (t < 16) { Sv[t] = at2s[t]; Dv[t] = at2d[t]; }
    __syncthreads();

    int warp = t >> 5, lane = t & 31;
    int half = lane >> 4, c = lane & 15;
    int m = blockIdx.x * 16 + warp * 2 + half;
    if (m >= NN) return;

    const float4* Ar = reinterpret_cast<const float4*>(A + (size_t)m * 128);
    float acc = 0.f;
    #pragma unroll
    for (int k = 0; k < 32; k++) {
        float4 a = Ar[k];
        float4 w = *reinterpret_cast<const float4*>(&Ws[c][k * 4]);
        acc += a.x * w.x + a.y * w.y + a.z * w.z + a.w * w.w;
    }
    h2h[(size_t)m * 16 + c] = __float2half_rn(acc);

    float sv = acc * Sv[c], dv = acc * Dv[c];
    #pragma unroll
    for (int o = 8; o > 0; o >>= 1) {
        sv += __shfl_xor_sync(0xffffffffu, sv, o);
        dv += __shfl_xor_sync(0xffffffffu, dv, o);
    }
    if (c == 0) { as2[m] = sv; ad2[m] = dv; }
}

// ================= layer-2 single-sweep aggregate + bias + log_softmax =================
__global__ __launch_bounds__(256)
void gat_aggregate_l2_lsm(const int* __restrict__ rowptr, const int* __restrict__ col,
                          const float* __restrict__ as_, const float* __restrict__ ad_,
                          const __half* __restrict__ hfeat, const float* __restrict__ b2,
                          float* __restrict__ out) {
    int warp = (blockIdx.x * blockDim.x + threadIdx.x) >> 5;
    int lane = threadIdx.x & 31;
    if (warp >= NN) return;
    int dst = warp;
    int beg = rowptr[dst], end = rowptr[dst + 1];
    float adv = ad_[dst];

    int c = lane & 15;
    int sub = lane >> 4;

    float m = -INFINITY, s = 0.f, acc = 0.f;
    int j = beg + sub;
    for (; j + 2 < end; j += 4) {
        int s0 = col[j], s1 = col[j + 2];
        float a0 = as_[s0], a1 = as_[s1];
        float f0 = __half2float(hfeat[(size_t)s0 * 16 + c]);
        float f1 = __half2float(hfeat[(size_t)s1 * 16 + c]);
        float v0 = a0 + adv; v0 = v0 > 0.f ? v0 : 0.2f * v0;
        float v1 = a1 + adv; v1 = v1 > 0.f ? v1 : 0.2f * v1;
        float nm = fmaxf(m, fmaxf(v0, v1));
        float sc = __expf(m - nm);
        float w0 = __expf(v0 - nm);
        float w1 = __expf(v1 - nm);
        s = s * sc + w0 + w1;
        acc = acc * sc + w0 * f0 + w1 * f1;
        m = nm;
    }
    if (j < end) {
        int s0 = col[j];
        float v0 = as_[s0] + adv; v0 = v0 > 0.f ? v0 : 0.2f * v0;
        float f0 = __half2float(hfeat[(size_t)s0 * 16 + c]);
        float nm = fmaxf(m, v0);
        float sc = __expf(m - nm);
        float w0 = __expf(v0 - nm);
        s = s * sc + w0;
        acc = acc * sc + w0 * f0;
        m = nm;
    }

    float om = __shfl_xor_sync(0xffffffffu, m, 16);
    float os = __shfl_xor_sync(0xffffffffu, s, 16);
    float oa = __shfl_xor_sync(0xffffffffu, acc, 16);
    float nm = fmaxf(m, om);
    float e1 = __expf(m - nm);
    float e2 = __expf(om - nm);
    s = s * e1 + os * e2;
    acc = acc * e1 + oa * e2;

    float inv = 1.f / (s + 1e-16f);
    float val = acc * inv + b2[c];

    float mx = val;
    #pragma unroll
    for (int o = 8; o > 0; o >>= 1) mx = fmaxf(mx, __shfl_xor_sync(0xffffffffu, mx, o));
    float se = __expf(val - mx);
    #pragma unroll
    for (int o = 8; o > 0; o >>= 1) se += __shfl_xor_sync(0xffffffffu, se, o);
    float ls = val - mx - __logf(se);
    if (lane < 16) out[(size_t)dst * 16 + c] = ls;
}

// ================= launch =================
extern "C" void kernel_launch(void* const* d_in, const int* in_sizes, int n_in,
                              void* d_out, int out_size) {
    const float* x    = (const float*)d_in[0];
    const int*   ei   = (const int*)d_in[1];
    const float* W1   = (const float*)d_in[2];
    const float* at1s = (const float*)d_in[3];
    const float* at1d = (const float*)d_in[4];
    const float* b1   = (const float*)d_in[5];
    const float* W2   = (const float*)d_in[6];
    const float* at2s = (const float*)d_in[7];
    const float* at2d = (const float*)d_in[8];
    const float* b2   = (const float*)d_in[9];
    float* out = (float*)d_out;

    int E = in_sizes[1] / 2;

    static float *p_w1t = nullptr, *p_as1, *p_ad1, *p_out1, *p_as2, *p_ad2;
    static __half2* p_h1h;
    static __half* p_h2h;
    static int *p_cnt, *p_rowptr, *p_cursor, *p_col;
    static cudaStream_t s2 = nullptr;
    static cudaEvent_t evF = nullptr, evJ = nullptr;
    if (!p_w1t) {
        cudaGetSymbolAddress((void**)&p_w1t, g_w1t);
        cudaGetSymbolAddress((void**)&p_h1h, g_h1h);
        cudaGetSymbolAddress((void**)&p_as1, g_as1);
        cudaGetSymbolAddress((void**)&p_ad1, g_ad1);
        cudaGetSymbolAddress((void**)&p_out1, g_out1);
        cudaGetSymbolAddress((void**)&p_h2h, g_h2h);
        cudaGetSymbolAddress((void**)&p_as2, g_as2);
        cudaGetSymbolAddress((void**)&p_ad2, g_ad2);
        cudaGetSymbolAddress((void**)&p_cnt, g_cnt);
        cudaGetSymbolAddress((void**)&p_rowptr, g_rowptr);
        cudaGetSymbolAddress((void**)&p_cursor, g_cursor);
        cudaGetSymbolAddress((void**)&p_col, g_col);
        cudaStreamCreateWithFlags(&s2, cudaStreamNonBlocking);
        cudaEventCreateWithFlags(&evF, cudaEventDisableTiming);
        cudaEventCreateWithFlags(&evJ, cudaEventDisableTiming);
    }

    const int TB = 256;
    auto blocks = [](int n, int tb) { return (n + tb - 1) / tb; };

    // ---- fork: CSR build on side stream ----
    cudaEventRecord(evF, 0);
    cudaStreamWaitEvent(s2, evF, 0);
    fill_int<<<blocks(NN, TB), TB, 0, s2>>>(p_cnt, 1, NN);
    count_dst<<<blocks(E, TB), TB, 0, s2>>>(ei, p_cnt, E);
    scan_rowptr<<<1, 1024, 0, s2>>>(p_cnt, p_rowptr, p_cursor);
    scatter_edges<<<blocks(E + NN, TB), TB, 0, s2>>>(ei, p_cursor, p_col, E);
    cudaEventRecord(evJ, s2);

    // ---- layer 1: W1 pre-round, 2-pass TF32 GEMM with fused att epilogue ----
    w1_round<<<blocks(HC1 * NF, TB), TB>>>(W1, p_w1t, HC1 * NF);
    {
        dim3 grid(HC1 / 64, (NN + 127) / 128);
        gemm_tf32x2_att<<<grid, 256>>>(x, p_w1t, p_h1h, at1s, at1d, p_as1, p_ad1, NN, NF);
    }

    // ---- join: aggregation needs the CSR ----
    cudaStreamWaitEvent(0, evJ, 0);
    gat_aggregate_l1<<<blocks(NN * 32, TB), TB>>>(p_rowptr, p_col, p_as1, p_ad1, p_h1h, b1, p_out1);

    // ---- layer 2: fused GEMM+att, then fused aggregate+log_softmax ----
    gemm2_att2<<<blocks(NN, 16), 256>>>(p_out1, W2, at2s, at2d, p_h2h, p_as2, p_ad2);
    gat_aggregate_l2_lsm<<<blocks(NN * 32, TB), TB>>>(p_rowptr, p_col, p_as2, p_ad2, p_h2h, b2, out);
}

// round 16
// speedup vs baseline: 2.0472x; 1.1637x over previous
#include <cuda_runtime.h>
#include <cuda_fp16.h>
#include <math.h>
#include <stdint.h>

// ---------------- problem constants ----------------
#define NN   50000
#define NE   1600000
#define EPAD (NE + NN)
#define NF   512
#define H1   8
#define C1   16
#define HC1  128
#define C2   16

// ---------------- scratch (device globals) ----------------
__device__ __half2 g_h1h[NN * 64];        // fp16 h1 (only copy)
__device__ float   g_as1[NN * H1];
__device__ float   g_ad1[NN * H1];
__device__ float   g_out1[NN * HC1];
__device__ __half  g_h2h[NN * C2];
__device__ float   g_as2[NN];
__device__ float   g_ad2[NN];
__device__ int     g_cnt[NN];
__device__ int     g_rowptr[NN + 1];
__device__ int     g_cursor[NN];
__device__ int     g_col[EPAD];

// ================= CSR build =================
__global__ void fill_int(int* p, int v, int n) {
    int i = blockIdx.x * blockDim.x + threadIdx.x;
    if (i < n) p[i] = v;
}

__global__ void count_dst(const int* __restrict__ ei, int* __restrict__ cnt, int E) {
    int e = blockIdx.x * blockDim.x + threadIdx.x;
    if (e < E) atomicAdd(&cnt[ei[E + e]], 1);
}

__global__ void scan_rowptr(const int* __restrict__ cnt, int* __restrict__ rowptr,
                            int* __restrict__ cursor) {
    __shared__ int ssum[1024];
    const int T = 1024;
    const int PER = (NN + T - 1) / T;
    int tid = threadIdx.x;
    int start = tid * PER;
    int local = 0;
    for (int i = 0; i < PER; i++) {
        int idx = start + i;
        if (idx < NN) local += cnt[idx];
    }
    ssum[tid] = local;
    __syncthreads();
    for (int off = 1; off < T; off <<= 1) {
        int v = (tid >= off) ? ssum[tid - off] : 0;
        __syncthreads();
        ssum[tid] += v;
        __syncthreads();
    }
    int run = (tid == 0) ? 0 : ssum[tid - 1];
    for (int i = 0; i < PER; i++) {
        int idx = start + i;
        if (idx < NN) { rowptr[idx] = run; cursor[idx] = run; run += cnt[idx]; }
    }
    if (tid == T - 1) rowptr[NN] = ssum[T - 1];
}

__global__ void scatter_edges(const int* __restrict__ ei, int* __restrict__ cursor,
                              int* __restrict__ col, int E) {
    int i = blockIdx.x * blockDim.x + threadIdx.x;
    int tot = E + NN;
    if (i >= tot) return;
    int s, d;
    if (i < E) { s = ei[i]; d = ei[E + i]; } else { s = d = i - E; }
    int pos = atomicAdd(&cursor[d], 1);
    col[pos] = s;
}

// ================= fp16 HMMA GEMM (NT) + fused att1 epilogue =================
// C_half[M,128] = fp16(A[M,K]) * fp16(B[128,K])^T, fp32 accumulate.
// Inline fp32->fp16 conversion during smem staging. Emits as1/ad1.

__device__ __forceinline__ void mma_f16(float* d, const uint32_t* a, const uint32_t* b) {
    asm volatile(
        "mma.sync.aligned.m16n8k16.row.col.f32.f16.f16.f32 "
        "{%0,%1,%2,%3}, {%4,%5,%6,%7}, {%8,%9}, {%0,%1,%2,%3};"
        : "+f"(d[0]), "+f"(d[1]), "+f"(d[2]), "+f"(d[3])
        : "r"(a[0]), "r"(a[1]), "r"(a[2]), "r"(a[3]), "r"(b[0]), "r"(b[1]));
}

#define HSTR 40   // halves per smem row (=20 b32 banks: conflict-free fragment loads)

__global__ __launch_bounds__(256, 2)
void gemm_f16_att(const float* __restrict__ A, const float* __restrict__ B,
                  __half2* __restrict__ Ch,
                  const float* __restrict__ att_s, const float* __restrict__ att_d,
                  float* __restrict__ as_, float* __restrict__ ad_,
                  int M, int K) {
    __shared__ __half As[128][HSTR];
    __shared__ __half Bs[64][HSTR];

    int t = threadIdx.x;
    int lane = t & 31;
    int warp = t >> 5;
    int wm = warp & 3;
    int wn = warp >> 2;
    int g  = lane >> 2;
    int tg = lane & 3;

    int m0 = blockIdx.y * 128;
    int n0 = blockIdx.x * 64;

    // staging map: k-tile = 32 floats = 8 float4-cols per row
    // A tile 128x32: 1024 float4 -> 4/thread ; B tile 64x32: 512 -> 2/thread
    int arow[4], acq[4];
    bool aok[4];
    const float4* Apf[4];
    #pragma unroll
    for (int i = 0; i < 4; i++) {
        int idx = t + i * 256;
        arow[i] = idx >> 3; acq[i] = idx & 7;
        aok[i] = (m0 + arow[i]) < M;
        Apf[i] = aok[i] ? reinterpret_cast<const float4*>(&A[(size_t)(m0 + arow[i]) * K + acq[i] * 4])
                        : nullptr;
    }
    int brow[2], bcq[2];
    const float4* Bpf[2];
    #pragma unroll
    for (int i = 0; i < 2; i++) {
        int idx = t + i * 256;
        brow[i] = idx >> 3; bcq[i] = idx & 7;
        Bpf[i] = reinterpret_cast<const float4*>(&B[(size_t)(n0 + brow[i]) * K + bcq[i] * 4]);
    }

    float4 pa[4], pb[2];
    #pragma unroll
    for (int i = 0; i < 4; i++) pa[i] = aok[i] ? Apf[i][0] : make_float4(0, 0, 0, 0);
    #pragma unroll
    for (int i = 0; i < 2; i++) pb[i] = Bpf[i][0];

    float d[2][4][4];
    #pragma unroll
    for (int i = 0; i < 2; i++)
        #pragma unroll
        for (int j = 0; j < 4; j++)
            #pragma unroll
            for (int q = 0; q < 4; q++) d[i][j][q] = 0.f;

    for (int k0 = 0; k0 < K; k0 += 32) {
        #pragma unroll
        for (int i = 0; i < 4; i++) {
            __half2 h0 = __floats2half2_rn(pa[i].x, pa[i].y);
            __half2 h1 = __floats2half2_rn(pa[i].z, pa[i].w);
            *reinterpret_cast<__half2*>(&As[arow[i]][acq[i] * 4])     = h0;
            *reinterpret_cast<__half2*>(&As[arow[i]][acq[i] * 4 + 2]) = h1;
        }
        #pragma unroll
        for (int i = 0; i < 2; i++) {
            __half2 h0 = __floats2half2_rn(pb[i].x, pb[i].y);
            __half2 h1 = __floats2half2_rn(pb[i].z, pb[i].w);
            *reinterpret_cast<__half2*>(&Bs[brow[i]][bcq[i] * 4])     = h0;
            *reinterpret_cast<__half2*>(&Bs[brow[i]][bcq[i] * 4 + 2]) = h1;
        }
        __syncthreads();

        if (k0 + 32 < K) {
            int idx = (k0 + 32) >> 2;
            #pragma unroll
            for (int i = 0; i < 4; i++) pa[i] = aok[i] ? Apf[i][idx] : make_float4(0, 0, 0, 0);
            #pragma unroll
            for (int i = 0; i < 2; i++) pb[i] = Bpf[i][idx];
        }

        #pragma unroll
        for (int ks = 0; ks < 2; ks++) {
            int kb = ks * 16;
            uint32_t af[2][4], bf[4][2];
            #pragma unroll
            for (int mt = 0; mt < 2; mt++) {
                int r0 = wm * 32 + mt * 16 + g;
                af[mt][0] = *reinterpret_cast<const uint32_t*>(&As[r0][kb + tg * 2]);
                af[mt][1] = *reinterpret_cast<const uint32_t*>(&As[r0 + 8][kb + tg * 2]);
                af[mt][2] = *reinterpret_cast<const uint32_t*>(&As[r0][kb + tg * 2 + 8]);
                af[mt][3] = *reinterpret_cast<const uint32_t*>(&As[r0 + 8][kb + tg * 2 + 8]);
            }
            #pragma unroll
            for (int nt = 0; nt < 4; nt++) {
                int n = wn * 32 + nt * 8 + g;
                bf[nt][0] = *reinterpret_cast<const uint32_t*>(&Bs[n][kb + tg * 2]);
                bf[nt][1] = *reinterpret_cast<const uint32_t*>(&Bs[n][kb + tg * 2 + 8]);
            }
            #pragma unroll
            for (int mt = 0; mt < 2; mt++)
                #pragma unroll
                for (int nt = 0; nt < 4; nt++)
                    mma_f16(d[mt][nt], af[mt], bf[nt]);
        }
        __syncthreads();
    }

    // ---- epilogue: write fp16 h1 and fused attention coefficients ----
    int baseHead = (n0 + wn * 32) >> 4;

    float ps[2][2][2], pd[2][2][2];
    #pragma unroll
    for (int a = 0; a < 2; a++)
        #pragma unroll
        for (int b = 0; b < 2; b++)
            #pragma unroll
            for (int cdx = 0; cdx < 2; cdx++) { ps[a][b][cdx] = 0.f; pd[a][b][cdx] = 0.f; }

    #pragma unroll
    for (int mt = 0; mt < 2; mt++) {
        int r0 = m0 + wm * 32 + mt * 16 + g;
        #pragma unroll
        for (int nt = 0; nt < 4; nt++) {
            int c = n0 + wn * 32 + nt * 8 + tg * 2;
            int head = baseHead + (nt >> 1);
            int ch0 = c & 15;
            float ws0 = att_s[head * 16 + ch0], ws1 = att_s[head * 16 + ch0 + 1];
            float wd0 = att_d[head * 16 + ch0], wd1 = att_d[head * 16 + ch0 + 1];
            int hi = nt >> 1;
            ps[mt][0][hi] += d[mt][nt][0] * ws0 + d[mt][nt][1] * ws1;
            ps[mt][1][hi] += d[mt][nt][2] * ws0 + d[mt][nt][3] * ws1;
            pd[mt][0][hi] += d[mt][nt][0] * wd0 + d[mt][nt][1] * wd1;
            pd[mt][1][hi] += d[mt][nt][2] * wd0 + d[mt][nt][3] * wd1;

            if (r0 < M)
                Ch[(size_t)r0 * 64 + (c >> 1)] = __floats2half2_rn(d[mt][nt][0], d[mt][nt][1]);
            if (r0 + 8 < M)
                Ch[(size_t)(r0 + 8) * 64 + (c >> 1)] = __floats2half2_rn(d[mt][nt][2], d[mt][nt][3]);
        }
    }

    #pragma unroll
    for (int a = 0; a < 2; a++)
        #pragma unroll
        for (int b = 0; b < 2; b++)
            #pragma unroll
            for (int cdx = 0; cdx < 2; cdx++) {
                float vs = ps[a][b][cdx], vd = pd[a][b][cdx];
                vs += __shfl_xor_sync(0xffffffffu, vs, 1);
                vs += __shfl_xor_sync(0xffffffffu, vs, 2);
                vd += __shfl_xor_sync(0xffffffffu, vd, 1);
                vd += __shfl_xor_sync(0xffffffffu, vd, 2);
                ps[a][b][cdx] = vs; pd[a][b][cdx] = vd;
            }

    if (tg == 0) {
        #pragma unroll
        for (int mt = 0; mt < 2; mt++) {
            #pragma unroll
            for (int rh = 0; rh < 2; rh++) {
                int row = m0 + wm * 32 + mt * 16 + g + rh * 8;
                if (row < M) {
                    #pragma unroll
                    for (int hi = 0; hi < 2; hi++) {
                        as_[row * 8 + baseHead + hi] = ps[mt][rh][hi];
                        ad_[row * 8 + baseHead + hi] = pd[mt][rh][hi];
                    }
                }
            }
        }
    }
}

// ================= layer-1 single-sweep aggregate (online rescale, fp16 gather) =================
__global__ __launch_bounds__(256)
void gat_aggregate_l1(const int* __restrict__ rowptr, const int* __restrict__ col,
                      const float* __restrict__ as_, const float* __restrict__ ad_,
                      const __half2* __restrict__ hfeat, const float* __restrict__ bias,
                      float* __restrict__ out) {
    int warp = (blockIdx.x * blockDim.x + threadIdx.x) >> 5;
    int lane = threadIdx.x & 31;
    if (warp >= NN) return;
    int dst = warp;
    int beg = rowptr[dst], end = rowptr[dst + 1];

    int myh = lane >> 2;
    float adhd = ad_[dst * 8 + myh];

    float m = -INFINITY, s = 0.f;
    float4 acc = make_float4(0.f, 0.f, 0.f, 0.f);

    const uint2* hp = reinterpret_cast<const uint2*>(hfeat);

    int j = beg;
    for (; j + 2 <= end; j += 2) {
        int s0 = col[j], s1 = col[j + 1];
        float a0 = as_[s0 * 8 + myh];
        float a1 = as_[s1 * 8 + myh];
        uint2 u0 = hp[(size_t)s0 * 32 + lane];
        uint2 u1 = hp[(size_t)s1 * 32 + lane];

        float v0 = a0 + adhd; v0 = v0 > 0.f ? v0 : 0.2f * v0;
        float v1 = a1 + adhd; v1 = v1 > 0.f ? v1 : 0.2f * v1;
        float nm = fmaxf(m, fmaxf(v0, v1));
        float sc = __expf(m - nm);
        float w0 = __expf(v0 - nm);
        float w1 = __expf(v1 - nm);
        s = s * sc + w0 + w1;
        float2 f00 = __half22float2(*reinterpret_cast<__half2*>(&u0.x));
        float2 f01 = __half22float2(*reinterpret_cast<__half2*>(&u0.y));
        float2 f10 = __half22float2(*reinterpret_cast<__half2*>(&u1.x));
        float2 f11 = __half22float2(*reinterpret_cast<__half2*>(&u1.y));
        acc.x = acc.x * sc + w0 * f00.x + w1 * f10.x;
        acc.y = acc.y * sc + w0 * f00.y + w1 * f10.y;
        acc.z = acc.z * sc + w0 * f01.x + w1 * f11.x;
        acc.w = acc.w * sc + w0 * f01.y + w1 * f11.y;
        m = nm;
    }
    if (j < end) {
        int s0 = col[j];
        float a0 = as_[s0 * 8 + myh];
        uint2 u0 = hp[(size_t)s0 * 32 + lane];
        float v0 = a0 + adhd; v0 = v0 > 0.f ? v0 : 0.2f * v0;
        float nm = fmaxf(m, v0);
        float sc = __expf(m - nm);
        float w0 = __expf(v0 - nm);
        s = s * sc + w0;
        float2 f00 = __half22float2(*reinterpret_cast<__half2*>(&u0.x));
        float2 f01 = __half22float2(*reinterpret_cast<__half2*>(&u0.y));
        acc.x = acc.x * sc + w0 * f00.x;
        acc.y = acc.y * sc + w0 * f00.y;
        acc.z = acc.z * sc + w0 * f01.x;
        acc.w = acc.w * sc + w0 * f01.y;
        m = nm;
    }

    float inv = 1.f / (s + 1e-16f);
    const float4* b4 = reinterpret_cast<const float4*>(bias);
    float4 bb = b4[lane];
    float4 r;
    r.x = acc.x * inv + bb.x; r.y = acc.y * inv + bb.y;
    r.z = acc.z * inv + bb.z; r.w = acc.w * inv + bb.w;
    r.x = r.x > 0.f ? r.x : expm1f(r.x);
    r.y = r.y > 0.f ? r.y : expm1f(r.y);
    r.z = r.z > 0.f ? r.z : expm1f(r.z);
    r.w = r.w > 0.f ? r.w : expm1f(r.w);
    reinterpret_cast<float4*>(out)[(size_t)dst * 32 + lane] = r;
}

// ================= fused layer-2 GEMM + att2 (fp16 h2 out) =================
__global__ __launch_bounds__(256)
void gemm2_att2(const float* __restrict__ A, const float* __restrict__ W2,
                const float* __restrict__ at2s, const float* __restrict__ at2d,
                __half* __restrict__ h2h, float* __restrict__ as2, float* __restrict__ ad2) {
    __shared__ float Ws[16][132];
    __shared__ float Sv[16], Dv[16];
    int t = threadIdx.x;
    for (int i = t; i < 16 * 32; i += 256) {
        int rr = i >> 5, cc = i & 31;
        *reinterpret_cast<float4*>(&Ws[rr][cc * 4]) =
            *reinterpret_cast<const float4*>(&W2[rr * 128 + cc * 4]);
    }
    if (t < 16) { Sv[t] = at2s[t]; Dv[t] = at2d[t]; }
    __syncthreads();

    int warp = t >> 5, lane = t & 31;
    int half = lane >> 4, c = lane & 15;
    int m = blockIdx.x * 16 + warp * 2 + half;
    if (m >= NN) return;

    const float4* Ar = reinterpret_cast<const float4*>(A + (size_t)m * 128);
    float acc = 0.f;
    #pragma unroll
    for (int k = 0; k < 32; k++) {
        float4 a = Ar[k];
        float4 w = *reinterpret_cast<const float4*>(&Ws[c][k * 4]);
        acc += a.x * w.x + a.y * w.y + a.z * w.z + a.w * w.w;
    }
    h2h[(size_t)m * 16 + c] = __float2half_rn(acc);

    float sv = acc * Sv[c], dv = acc * Dv[c];
    #pragma unroll
    for (int o = 8; o > 0; o >>= 1) {
        sv += __shfl_xor_sync(0xffffffffu, sv, o);
        dv += __shfl_xor_sync(0xffffffffu, dv, o);
    }
    if (c == 0) { as2[m] = sv; ad2[m] = dv; }
}

// ================= layer-2 single-sweep aggregate + bias + log_softmax =================
__global__ __launch_bounds__(256)
void gat_aggregate_l2_lsm(const int* __restrict__ rowptr, const int* __restrict__ col,
                          const float* __restrict__ as_, const float* __restrict__ ad_,
                          const __half* __restrict__ hfeat, const float* __restrict__ b2,
                          float* __restrict__ out) {
    int warp = (blockIdx.x * blockDim.x + threadIdx.x) >> 5;
    int lane = threadIdx.x & 31;
    if (warp >= NN) return;
    int dst = warp;
    int beg = rowptr[dst], end = rowptr[dst + 1];
    float adv = ad_[dst];

    int c = lane & 15;
    int sub = lane >> 4;

    float m = -INFINITY, s = 0.f, acc = 0.f;
    int j = beg + sub;
    // 4 edges per half per iteration (MLP depth 4)
    for (; j + 6 < end; j += 8) {
        int s0 = col[j], s1 = col[j + 2], s2 = col[j + 4], s3 = col[j + 6];
        float a0 = as_[s0], a1 = as_[s1], a2 = as_[s2], a3 = as_[s3];
        float f0 = __half2float(hfeat[(size_t)s0 * 16 + c]);
        float f1 = __half2float(hfeat[(size_t)s1 * 16 + c]);
        float f2 = __half2float(hfeat[(size_t)s2 * 16 + c]);
        float f3 = __half2float(hfeat[(size_t)s3 * 16 + c]);
        float v0 = a0 + adv; v0 = v0 > 0.f ? v0 : 0.2f * v0;
        float v1 = a1 + adv; v1 = v1 > 0.f ? v1 : 0.2f * v1;
        float v2 = a2 + adv; v2 = v2 > 0.f ? v2 : 0.2f * v2;
        float v3 = a3 + adv; v3 = v3 > 0.f ? v3 : 0.2f * v3;
        float nm = fmaxf(fmaxf(m, fmaxf(v0, v1)), fmaxf(v2, v3));
        float sc = __expf(m - nm);
        float w0 = __expf(v0 - nm), w1 = __expf(v1 - nm);
        float w2 = __expf(v2 - nm), w3 = __expf(v3 - nm);
        s = s * sc + w0 + w1 + w2 + w3;
        acc = acc * sc + w0 * f0 + w1 * f1 + w2 * f2 + w3 * f3;
        m = nm;
    }
    for (; j + 2 < end; j += 4) {
        int s0 = col[j], s1 = col[j + 2];
        float a0 = as_[s0], a1 = as_[s1];
        float f0 = __half2float(hfeat[(size_t)s0 * 16 + c]);
        float f1 = __half2float(hfeat[(size_t)s1 * 16 + c]);
        float v0 = a0 + adv; v0 = v0 > 0.f ? v0 : 0.2f * v0;
        float v1 = a1 + adv; v1 = v1 > 0.f ? v1 : 0.2f * v1;
        float nm = fmaxf(m, fmaxf(v0, v1));
        float sc = __expf(m - nm);
        float w0 = __expf(v0 - nm);
        float w1 = __expf(v1 - nm);
        s = s * sc + w0 + w1;
        acc = acc * sc + w0 * f0 + w1 * f1;
        m = nm;
    }
    if (j < end) {
        int s0 = col[j];
        float v0 = as_[s0] + adv; v0 = v0 > 0.f ? v0 : 0.2f * v0;
        float f0 = __half2float(hfeat[(size_t)s0 * 16 + c]);
        float nm = fmaxf(m, v0);
        float sc = __expf(m - nm);
        float w0 = __expf(v0 - nm);
        s = s * sc + w0;
        acc = acc * sc + w0 * f0;
        m = nm;
    }

    float om = __shfl_xor_sync(0xffffffffu, m, 16);
    float os = __shfl_xor_sync(0xffffffffu, s, 16);
    float oa = __shfl_xor_sync(0xffffffffu, acc, 16);
    float nm = fmaxf(m, om);
    float e1 = __expf(m - nm);
    float e2 = __expf(om - nm);
    s = s * e1 + os * e2;
    acc = acc * e1 + oa * e2;

    float inv = 1.f / (s + 1e-16f);
    float val = acc * inv + b2[c];

    float mx = val;
    #pragma unroll
    for (int o = 8; o > 0; o >>= 1) mx = fmaxf(mx, __shfl_xor_sync(0xffffffffu, mx, o));
    float se = __expf(val - mx);
    #pragma unroll
    for (int o = 8; o > 0; o >>= 1) se += __shfl_xor_sync(0xffffffffu, se, o);
    float ls = val - mx - __logf(se);
    if (lane < 16) out[(size_t)dst * 16 + c] = ls;
}

// ================= launch =================
extern "C" void kernel_launch(void* const* d_in, const int* in_sizes, int n_in,
                              void* d_out, int out_size) {
    const float* x    = (const float*)d_in[0];
    const int*   ei   = (const int*)d_in[1];
    const float* W1   = (const float*)d_in[2];
    const float* at1s = (const float*)d_in[3];
    const float* at1d = (const float*)d_in[4];
    const float* b1   = (const float*)d_in[5];
    const float* W2   = (const float*)d_in[6];
    const float* at2s = (const float*)d_in[7];
    const float* at2d = (const float*)d_in[8];
    const float* b2   = (const float*)d_in[9];
    float* out = (float*)d_out;

    int E = in_sizes[1] / 2;

    static float *p_as1 = nullptr, *p_ad1, *p_out1, *p_as2, *p_ad2;
    static __half2* p_h1h;
    static __half* p_h2h;
    static int *p_cnt, *p_rowptr, *p_cursor, *p_col;
    static cudaStream_t s2 = nullptr;
    static cudaEvent_t evF = nullptr, evJ = nullptr;
    if (!p_as1) {
        cudaGetSymbolAddress((void**)&p_h1h, g_h1h);
        cudaGetSymbolAddress((void**)&p_as1, g_as1);
        cudaGetSymbolAddress((void**)&p_ad1, g_ad1);
        cudaGetSymbolAddress((void**)&p_out1, g_out1);
        cudaGetSymbolAddress((void**)&p_h2h, g_h2h);
        cudaGetSymbolAddress((void**)&p_as2, g_as2);
        cudaGetSymbolAddress((void**)&p_ad2, g_ad2);
        cudaGetSymbolAddress((void**)&p_cnt, g_cnt);
        cudaGetSymbolAddress((void**)&p_rowptr, g_rowptr);
        cudaGetSymbolAddress((void**)&p_cursor, g_cursor);
        cudaGetSymbolAddress((void**)&p_col, g_col);
        cudaStreamCreateWithFlags(&s2, cudaStreamNonBlocking);
        cudaEventCreateWithFlags(&evF, cudaEventDisableTiming);
        cudaEventCreateWithFlags(&evJ, cudaEventDisableTiming);
    }

    const int TB = 256;
    auto blocks = [](int n, int tb) { return (n + tb - 1) / tb; };

    // ---- fork: CSR build on side stream ----
    cudaEventRecord(evF, 0);
    cudaStreamWaitEvent(s2, evF, 0);
    fill_int<<<blocks(NN, TB), TB, 0, s2>>>(p_cnt, 1, NN);
    count_dst<<<blocks(E, TB), TB, 0, s2>>>(ei, p_cnt, E);
    scan_rowptr<<<1, 1024, 0, s2>>>(p_cnt, p_rowptr, p_cursor);
    scatter_edges<<<blocks(E + NN, TB), TB, 0, s2>>>(ei, p_cursor, p_col, E);
    cudaEventRecord(evJ, s2);

    // ---- layer 1: fp16 HMMA GEMM with fused att epilogue ----
    {
        dim3 grid(HC1 / 64, (NN + 127) / 128);
        gemm_f16_att<<<grid, 256>>>(x, W1, p_h1h, at1s, at1d, p_as1, p_ad1, NN, NF);
    }

    // ---- join: aggregation needs the CSR ----
    cudaStreamWaitEvent(0, evJ, 0);
    gat_aggregate_l1<<<blocks(NN * 32, TB), TB>>>(p_rowptr, p_col, p_as1, p_ad1, p_h1h, b1, p_out1);

    // ---- layer 2: fused GEMM+att, then fused aggregate+log_softmax ----
    gemm2_att2<<<blocks(NN, 16), 256>>>(p_out1, W2, at2s, at2d, p_h2h, p_as2, p_ad2);
    gat_aggregate_l2_lsm<<<blocks(NN * 32, TB), TB>>>(p_rowptr, p_col, p_as2, p_ad2, p_h2h, b2, out);
}

// round 17
// speedup vs baseline: 2.0763x; 1.0142x over previous
#include <cuda_runtime.h>
#include <cuda_fp16.h>
#include <math.h>
#include <stdint.h>

// ---------------- problem constants ----------------
#define NN   50000
#define NE   1600000
#define EPAD (NE + NN)
#define NF   512
#define H1   8
#define C1   16
#define HC1  128
#define C2   16

// ---------------- scratch (device globals) ----------------
__device__ __half2 g_h1h[NN * 64];        // fp16 h1 (only copy)
__device__ float   g_as1[NN * H1];
__device__ float   g_ad1[NN * H1];
__device__ float   g_out1[NN * HC1];
__device__ __half  g_h2h[NN * C2];
__device__ float   g_as2[NN];
__device__ float   g_ad2[NN];
__device__ int     g_cnt[NN];
__device__ int     g_rowptr[NN + 1];
__device__ int     g_cursor[NN];
__device__ int     g_col[EPAD];

// ================= CSR build =================
__global__ void fill_int(int* p, int v, int n) {
    int i = blockIdx.x * blockDim.x + threadIdx.x;
    if (i < n) p[i] = v;
}

// 2 edges per thread (split halves, both coalesced)
__global__ void count_dst(const int* __restrict__ ei, int* __restrict__ cnt, int E) {
    int half = (E + 1) >> 1;
    int i = blockIdx.x * blockDim.x + threadIdx.x;
    if (i < half) {
        atomicAdd(&cnt[ei[E + i]], 1);
        int i2 = i + half;
        if (i2 < E) atomicAdd(&cnt[ei[E + i2]], 1);
    }
}

__global__ void scan_rowptr(const int* __restrict__ cnt, int* __restrict__ rowptr,
                            int* __restrict__ cursor) {
    __shared__ int ssum[1024];
    const int T = 1024;
    const int PER = (NN + T - 1) / T;
    int tid = threadIdx.x;
    int start = tid * PER;
    int local = 0;
    for (int i = 0; i < PER; i++) {
        int idx = start + i;
        if (idx < NN) local += cnt[idx];
    }
    ssum[tid] = local;
    __syncthreads();
    for (int off = 1; off < T; off <<= 1) {
        int v = (tid >= off) ? ssum[tid - off] : 0;
        __syncthreads();
        ssum[tid] += v;
        __syncthreads();
    }
    int run = (tid == 0) ? 0 : ssum[tid - 1];
    for (int i = 0; i < PER; i++) {
        int idx = start + i;
        if (idx < NN) { rowptr[idx] = run; cursor[idx] = run; run += cnt[idx]; }
    }
    if (tid == T - 1) rowptr[NN] = ssum[T - 1];
}

// 2 edges per thread (split halves)
__global__ void scatter_edges(const int* __restrict__ ei, int* __restrict__ cursor,
                              int* __restrict__ col, int E) {
    int tot = E + NN;
    int half = (tot + 1) >> 1;
    int i = blockIdx.x * blockDim.x + threadIdx.x;
    if (i >= half) return;

    int s0, d0;
    if (i < E) { s0 = ei[i]; d0 = ei[E + i]; } else { s0 = d0 = i - E; }
    int i2 = i + half;
    int s1 = -1, d1 = -1;
    if (i2 < tot) {
        if (i2 < E) { s1 = ei[i2]; d1 = ei[E + i2]; } else { s1 = d1 = i2 - E; }
    }
    int p0 = atomicAdd(&cursor[d0], 1);
    int p1 = (d1 >= 0) ? atomicAdd(&cursor[d1], 1) : -1;
    col[p0] = s0;
    if (p1 >= 0) col[p1] = s1;
}

// ================= fp16 HMMA GEMM (NT) + fused att1 epilogue =================
__device__ __forceinline__ void mma_f16(float* d, const uint32_t* a, const uint32_t* b) {
    asm volatile(
        "mma.sync.aligned.m16n8k16.row.col.f32.f16.f16.f32 "
        "{%0,%1,%2,%3}, {%4,%5,%6,%7}, {%8,%9}, {%0,%1,%2,%3};"
        : "+f"(d[0]), "+f"(d[1]), "+f"(d[2]), "+f"(d[3])
        : "r"(a[0]), "r"(a[1]), "r"(a[2]), "r"(a[3]), "r"(b[0]), "r"(b[1]));
}

#define HSTR 40   // halves per smem row

__global__ __launch_bounds__(256, 2)
void gemm_f16_att(const float* __restrict__ A, const float* __restrict__ B,
                  __half2* __restrict__ Ch,
                  const float* __restrict__ att_s, const float* __restrict__ att_d,
                  float* __restrict__ as_, float* __restrict__ ad_,
                  int M, int K) {
    __shared__ __half As[128][HSTR];
    __shared__ __half Bs[64][HSTR];

    int t = threadIdx.x;
    int lane = t & 31;
    int warp = t >> 5;
    int wm = warp & 3;
    int wn = warp >> 2;
    int g  = lane >> 2;
    int tg = lane & 3;

    int m0 = blockIdx.y * 128;
    int n0 = blockIdx.x * 64;

    int arow[4], acq[4];
    bool aok[4];
    const float4* Apf[4];
    #pragma unroll
    for (int i = 0; i < 4; i++) {
        int idx = t + i * 256;
        arow[i] = idx >> 3; acq[i] = idx & 7;
        aok[i] = (m0 + arow[i]) < M;
        Apf[i] = aok[i] ? reinterpret_cast<const float4*>(&A[(size_t)(m0 + arow[i]) * K + acq[i] * 4])
                        : nullptr;
    }
    int brow[2], bcq[2];
    const float4* Bpf[2];
    #pragma unroll
    for (int i = 0; i < 2; i++) {
        int idx = t + i * 256;
        brow[i] = idx >> 3; bcq[i] = idx & 7;
        Bpf[i] = reinterpret_cast<const float4*>(&B[(size_t)(n0 + brow[i]) * K + bcq[i] * 4]);
    }

    float4 pa[4], pb[2];
    #pragma unroll
    for (int i = 0; i < 4; i++) pa[i] = aok[i] ? Apf[i][0] : make_float4(0, 0, 0, 0);
    #pragma unroll
    for (int i = 0; i < 2; i++) pb[i] = Bpf[i][0];

    float d[2][4][4];
    #pragma unroll
    for (int i = 0; i < 2; i++)
        #pragma unroll
        for (int j = 0; j < 4; j++)
            #pragma unroll
            for (int q = 0; q < 4; q++) d[i][j][q] = 0.f;

    for (int k0 = 0; k0 < K; k0 += 32) {
        #pragma unroll
        for (int i = 0; i < 4; i++) {
            __half2 h0 = __floats2half2_rn(pa[i].x, pa[i].y);
            __half2 h1 = __floats2half2_rn(pa[i].z, pa[i].w);
            *reinterpret_cast<__half2*>(&As[arow[i]][acq[i] * 4])     = h0;
            *reinterpret_cast<__half2*>(&As[arow[i]][acq[i] * 4 + 2]) = h1;
        }
        #pragma unroll
        for (int i = 0; i < 2; i++) {
            __half2 h0 = __floats2half2_rn(pb[i].x, pb[i].y);
            __half2 h1 = __floats2half2_rn(pb[i].z, pb[i].w);
            *reinterpret_cast<__half2*>(&Bs[brow[i]][bcq[i] * 4])     = h0;
            *reinterpret_cast<__half2*>(&Bs[brow[i]][bcq[i] * 4 + 2]) = h1;
        }
        __syncthreads();

        if (k0 + 32 < K) {
            int idx = (k0 + 32) >> 2;
            #pragma unroll
            for (int i = 0; i < 4; i++) pa[i] = aok[i] ? Apf[i][idx] : make_float4(0, 0, 0, 0);
            #pragma unroll
            for (int i = 0; i < 2; i++) pb[i] = Bpf[i][idx];
        }

        #pragma unroll
        for (int ks = 0; ks < 2; ks++) {
            int kb = ks * 16;
            uint32_t af[2][4], bf[4][2];
            #pragma unroll
            for (int mt = 0; mt < 2; mt++) {
                int r0 = wm * 32 + mt * 16 + g;
                af[mt][0] = *reinterpret_cast<const uint32_t*>(&As[r0][kb + tg * 2]);
                af[mt][1] = *reinterpret_cast<const uint32_t*>(&As[r0 + 8][kb + tg * 2]);
                af[mt][2] = *reinterpret_cast<const uint32_t*>(&As[r0][kb + tg * 2 + 8]);
                af[mt][3] = *reinterpret_cast<const uint32_t*>(&As[r0 + 8][kb + tg * 2 + 8]);
            }
            #pragma unroll
            for (int nt = 0; nt < 4; nt++) {
                int n = wn * 32 + nt * 8 + g;
                bf[nt][0] = *reinterpret_cast<const uint32_t*>(&Bs[n][kb + tg * 2]);
                bf[nt][1] = *reinterpret_cast<const uint32_t*>(&Bs[n][kb + tg * 2 + 8]);
            }
            #pragma unroll
            for (int mt = 0; mt < 2; mt++)
                #pragma unroll
                for (int nt = 0; nt < 4; nt++)
                    mma_f16(d[mt][nt], af[mt], bf[nt]);
        }
        __syncthreads();
    }

    // ---- epilogue: fp16 h1 + fused attention coefficients ----
    int baseHead = (n0 + wn * 32) >> 4;

    float ps[2][2][2], pd[2][2][2];
    #pragma unroll
    for (int a = 0; a < 2; a++)
        #pragma unroll
        for (int b = 0; b < 2; b++)
            #pragma unroll
            for (int cdx = 0; cdx < 2; cdx++) { ps[a][b][cdx] = 0.f; pd[a][b][cdx] = 0.f; }

    #pragma unroll
    for (int mt = 0; mt < 2; mt++) {
        int r0 = m0 + wm * 32 + mt * 16 + g;
        #pragma unroll
        for (int nt = 0; nt < 4; nt++) {
            int c = n0 + wn * 32 + nt * 8 + tg * 2;
            int head = baseHead + (nt >> 1);
            int ch0 = c & 15;
            float ws0 = att_s[head * 16 + ch0], ws1 = att_s[head * 16 + ch0 + 1];
            float wd0 = att_d[head * 16 + ch0], wd1 = att_d[head * 16 + ch0 + 1];
            int hi = nt >> 1;
            ps[mt][0][hi] += d[mt][nt][0] * ws0 + d[mt][nt][1] * ws1;
            ps[mt][1][hi] += d[mt][nt][2] * ws0 + d[mt][nt][3] * ws1;
            pd[mt][0][hi] += d[mt][nt][0] * wd0 + d[mt][nt][1] * wd1;
            pd[mt][1][hi] += d[mt][nt][2] * wd0 + d[mt][nt][3] * wd1;

            if (r0 < M)
                Ch[(size_t)r0 * 64 + (c >> 1)] = __floats2half2_rn(d[mt][nt][0], d[mt][nt][1]);
            if (r0 + 8 < M)
                Ch[(size_t)(r0 + 8) * 64 + (c >> 1)] = __floats2half2_rn(d[mt][nt][2], d[mt][nt][3]);
        }
    }

    #pragma unroll
    for (int a = 0; a < 2; a++)
        #pragma unroll
        for (int b = 0; b < 2; b++)
            #pragma unroll
            for (int cdx = 0; cdx < 2; cdx++) {
                float vs = ps[a][b][cdx], vd = pd[a][b][cdx];
                vs += __shfl_xor_sync(0xffffffffu, vs, 1);
                vs += __shfl_xor_sync(0xffffffffu, vs, 2);
                vd += __shfl_xor_sync(0xffffffffu, vd, 1);
                vd += __shfl_xor_sync(0xffffffffu, vd, 2);
                ps[a][b][cdx] = vs; pd[a][b][cdx] = vd;
            }

    if (tg == 0) {
        #pragma unroll
        for (int mt = 0; mt < 2; mt++) {
            #pragma unroll
            for (int rh = 0; rh < 2; rh++) {
                int row = m0 + wm * 32 + mt * 16 + g + rh * 8;
                if (row < M) {
                    #pragma unroll
                    for (int hi = 0; hi < 2; hi++) {
                        as_[row * 8 + baseHead + hi] = ps[mt][rh][hi];
                        ad_[row * 8 + baseHead + hi] = pd[mt][rh][hi];
                    }
                }
            }
        }
    }
}

// ================= layer-1 single-sweep aggregate (4-edge MLP, fp16 gather) =================
__global__ __launch_bounds__(256)
void gat_aggregate_l1(const int* __restrict__ rowptr, const int* __restrict__ col,
                      const float* __restrict__ as_, const float* __restrict__ ad_,
                      const __half2* __restrict__ hfeat, const float* __restrict__ bias,
                      float* __restrict__ out) {
    int warp = (blockIdx.x * blockDim.x + threadIdx.x) >> 5;
    int lane = threadIdx.x & 31;
    if (warp >= NN) return;
    int dst = warp;
    int beg = rowptr[dst], end = rowptr[dst + 1];

    int myh = lane >> 2;
    float adhd = ad_[dst * 8 + myh];

    float m = -INFINITY, s = 0.f;
    float4 acc = make_float4(0.f, 0.f, 0.f, 0.f);

    const uint2* hp = reinterpret_cast<const uint2*>(hfeat);

    int j = beg;
    // 4 edges per iteration: 4 independent col->gather chains in flight
    for (; j + 4 <= end; j += 4) {
        int s0 = col[j], s1 = col[j + 1], s2 = col[j + 2], s3 = col[j + 3];
        float a0 = as_[s0 * 8 + myh];
        float a1 = as_[s1 * 8 + myh];
        float a2 = as_[s2 * 8 + myh];
        float a3 = as_[s3 * 8 + myh];
        uint2 u0 = hp[(size_t)s0 * 32 + lane];
        uint2 u1 = hp[(size_t)s1 * 32 + lane];
        uint2 u2 = hp[(size_t)s2 * 32 + lane];
        uint2 u3 = hp[(size_t)s3 * 32 + lane];

        float v0 = a0 + adhd; v0 = v0 > 0.f ? v0 : 0.2f * v0;
        float v1 = a1 + adhd; v1 = v1 > 0.f ? v1 : 0.2f * v1;
        float v2 = a2 + adhd; v2 = v2 > 0.f ? v2 : 0.2f * v2;
        float v3 = a3 + adhd; v3 = v3 > 0.f ? v3 : 0.2f * v3;
        float nm = fmaxf(fmaxf(m, fmaxf(v0, v1)), fmaxf(v2, v3));
        float sc = __expf(m - nm);
        float w0 = __expf(v0 - nm), w1 = __expf(v1 - nm);
        float w2 = __expf(v2 - nm), w3 = __expf(v3 - nm);
        s = s * sc + w0 + w1 + w2 + w3;
        float2 f00 = __half22float2(*reinterpret_cast<__half2*>(&u0.x));
        float2 f01 = __half22float2(*reinterpret_cast<__half2*>(&u0.y));
        float2 f10 = __half22float2(*reinterpret_cast<__half2*>(&u1.x));
        float2 f11 = __half22float2(*reinterpret_cast<__half2*>(&u1.y));
        float2 f20 = __half22float2(*reinterpret_cast<__half2*>(&u2.x));
        float2 f21 = __half22float2(*reinterpret_cast<__half2*>(&u2.y));
        float2 f30 = __half22float2(*reinterpret_cast<__half2*>(&u3.x));
        float2 f31 = __half22float2(*reinterpret_cast<__half2*>(&u3.y));
        acc.x = acc.x * sc + w0 * f00.x + w1 * f10.x + w2 * f20.x + w3 * f30.x;
        acc.y = acc.y * sc + w0 * f00.y + w1 * f10.y + w2 * f20.y + w3 * f30.y;
        acc.z = acc.z * sc + w0 * f01.x + w1 * f11.x + w2 * f21.x + w3 * f31.x;
        acc.w = acc.w * sc + w0 * f01.y + w1 * f11.y + w2 * f21.y + w3 * f31.y;
        m = nm;
    }
    for (; j + 2 <= end; j += 2) {
        int s0 = col[j], s1 = col[j + 1];
        float a0 = as_[s0 * 8 + myh];
        float a1 = as_[s1 * 8 + myh];
        uint2 u0 = hp[(size_t)s0 * 32 + lane];
        uint2 u1 = hp[(size_t)s1 * 32 + lane];
        float v0 = a0 + adhd; v0 = v0 > 0.f ? v0 : 0.2f * v0;
        float v1 = a1 + adhd; v1 = v1 > 0.f ? v1 : 0.2f * v1;
        float nm = fmaxf(m, fmaxf(v0, v1));
        float sc = __expf(m - nm);
        float w0 = __expf(v0 - nm);
        float w1 = __expf(v1 - nm);
        s = s * sc + w0 + w1;
        float2 f00 = __half22float2(*reinterpret_cast<__half2*>(&u0.x));
        float2 f01 = __half22float2(*reinterpret_cast<__half2*>(&u0.y));
        float2 f10 = __half22float2(*reinterpret_cast<__half2*>(&u1.x));
        float2 f11 = __half22float2(*reinterpret_cast<__half2*>(&u1.y));
        acc.x = acc.x * sc + w0 * f00.x + w1 * f10.x;
        acc.y = acc.y * sc + w0 * f00.y + w1 * f10.y;
        acc.z = acc.z * sc + w0 * f01.x + w1 * f11.x;
        acc.w = acc.w * sc + w0 * f01.y + w1 * f11.y;
        m = nm;
    }
    if (j < end) {
        int s0 = col[j];
        float a0 = as_[s0 * 8 + myh];
        uint2 u0 = hp[(size_t)s0 * 32 + lane];
        float v0 = a0 + adhd; v0 = v0 > 0.f ? v0 : 0.2f * v0;
        float nm = fmaxf(m, v0);
        float sc = __expf(m - nm);
        float w0 = __expf(v0 - nm);
        s = s * sc + w0;
        float2 f00 = __half22float2(*reinterpret_cast<__half2*>(&u0.x));
        float2 f01 = __half22float2(*reinterpret_cast<__half2*>(&u0.y));
        acc.x = acc.x * sc + w0 * f00.x;
        acc.y = acc.y * sc + w0 * f00.y;
        acc.z = acc.z * sc + w0 * f01.x;
        acc.w = acc.w * sc + w0 * f01.y;
        m = nm;
    }

    float inv = 1.f / (s + 1e-16f);
    const float4* b4 = reinterpret_cast<const float4*>(bias);
    float4 bb = b4[lane];
    float4 r;
    r.x = acc.x * inv + bb.x; r.y = acc.y * inv + bb.y;
    r.z = acc.z * inv + bb.z; r.w = acc.w * inv + bb.w;
    r.x = r.x > 0.f ? r.x : expm1f(r.x);
    r.y = r.y > 0.f ? r.y : expm1f(r.y);
    r.z = r.z > 0.f ? r.z : expm1f(r.z);
    r.w = r.w > 0.f ? r.w : expm1f(r.w);
    reinterpret_cast<float4*>(out)[(size_t)dst * 32 + lane] = r;
}

// ================= fused layer-2 GEMM + att2 (fp16 h2 out) =================
__global__ __launch_bounds__(256)
void gemm2_att2(const float* __restrict__ A, const float* __restrict__ W2,
                const float* __restrict__ at2s, const float* __restrict__ at2d,
                __half* __restrict__ h2h, float* __restrict__ as2, float* __restrict__ ad2) {
    __shared__ float Ws[16][132];
    __shared__ float Sv[16], Dv[16];
    int t = threadIdx.x;
    for (int i = t; i < 16 * 32; i += 256) {
        int rr = i >> 5, cc = i & 31;
        *reinterpret_cast<float4*>(&Ws[rr][cc * 4]) =
            *reinterpret_cast<const float4*>(&W2[rr * 128 + cc * 4]);
    }
    if (t < 16) { Sv[t] = at2s[t]; Dv[t] = at2d[t]; }
    __syncthreads();

    int warp = t >> 5, lane = t & 31;
    int half = lane >> 4, c = lane & 15;
    int m = blockIdx.x * 16 + warp * 2 + half;
    if (m >= NN) return;

    const float4* Ar = reinterpret_cast<const float4*>(A + (size_t)m * 128);
    float acc = 0.f;
    #pragma unroll
    for (int k = 0; k < 32; k++) {
        float4 a = Ar[k];
        float4 w = *reinterpret_cast<const float4*>(&Ws[c][k * 4]);
        acc += a.x * w.x + a.y * w.y + a.z * w.z + a.w * w.w;
    }
    h2h[(size_t)m * 16 + c] = __float2half_rn(acc);

    float sv = acc * Sv[c], dv = acc * Dv[c];
    #pragma unroll
    for (int o = 8; o > 0; o >>= 1) {
        sv += __shfl_xor_sync(0xffffffffu, sv, o);
        dv += __shfl_xor_sync(0xffffffffu, dv, o);
    }
    if (c == 0) { as2[m] = sv; ad2[m] = dv; }
}

// ================= layer-2 single-sweep aggregate + bias + log_softmax =================
__global__ __launch_bounds__(256)
void gat_aggregate_l2_lsm(const int* __restrict__ rowptr, const int* __restrict__ col,
                          const float* __restrict__ as_, const float* __restrict__ ad_,
                          const __half* __restrict__ hfeat, const float* __restrict__ b2,
                          float* __restrict__ out) {
    int warp = (blockIdx.x * blockDim.x + threadIdx.x) >> 5;
    int lane = threadIdx.x & 31;
    if (warp >= NN) return;
    int dst = warp;
    int beg = rowptr[dst], end = rowptr[dst + 1];
    float adv = ad_[dst];

    int c = lane & 15;
    int sub = lane >> 4;

    float m = -INFINITY, s = 0.f, acc = 0.f;
    int j = beg + sub;
    for (; j + 6 < end; j += 8) {
        int s0 = col[j], s1 = col[j + 2], s2 = col[j + 4], s3 = col[j + 6];
        float a0 = as_[s0], a1 = as_[s1], a2 = as_[s2], a3 = as_[s3];
        float f0 = __half2float(hfeat[(size_t)s0 * 16 + c]);
        float f1 = __half2float(hfeat[(size_t)s1 * 16 + c]);
        float f2 = __half2float(hfeat[(size_t)s2 * 16 + c]);
        float f3 = __half2float(hfeat[(size_t)s3 * 16 + c]);
        float v0 = a0 + adv; v0 = v0 > 0.f ? v0 : 0.2f * v0;
        float v1 = a1 + adv; v1 = v1 > 0.f ? v1 : 0.2f * v1;
        float v2 = a2 + adv; v2 = v2 > 0.f ? v2 : 0.2f * v2;
        float v3 = a3 + adv; v3 = v3 > 0.f ? v3 : 0.2f * v3;
        float nm = fmaxf(fmaxf(m, fmaxf(v0, v1)), fmaxf(v2, v3));
        float sc = __expf(m - nm);
        float w0 = __expf(v0 - nm), w1 = __expf(v1 - nm);
        float w2 = __expf(v2 - nm), w3 = __expf(v3 - nm);
        s = s * sc + w0 + w1 + w2 + w3;
        acc = acc * sc + w0 * f0 + w1 * f1 + w2 * f2 + w3 * f3;
        m = nm;
    }
    for (; j + 2 < end; j += 4) {
        int s0 = col[j], s1 = col[j + 2];
        float a0 = as_[s0], a1 = as_[s1];
        float f0 = __half2float(hfeat[(size_t)s0 * 16 + c]);
        float f1 = __half2float(hfeat[(size_t)s1 * 16 + c]);
        float v0 = a0 + adv; v0 = v0 > 0.f ? v0 : 0.2f * v0;
        float v1 = a1 + adv; v1 = v1 > 0.f ? v1 : 0.2f * v1;
        float nm = fmaxf(m, fmaxf(v0, v1));
        float sc = __expf(m - nm);
        float w0 = __expf(v0 - nm);
        float w1 = __expf(v1 - nm);
        s = s * sc + w0 + w1;
        acc = acc * sc + w0 * f0 + w1 * f1;
        m = nm;
    }
    if (j < end) {
        int s0 = col[j];
        float v0 = as_[s0] + adv; v0 = v0 > 0.f ? v0 : 0.2f * v0;
        float f0 = __half2float(hfeat[(size_t)s0 * 16 + c]);
        float nm = fmaxf(m, v0);
        float sc = __expf(m - nm);
        float w0 = __expf(v0 - nm);
        s = s * sc + w0;
        acc = acc * sc + w0 * f0;
        m = nm;
    }

    float om = __shfl_xor_sync(0xffffffffu, m, 16);
    float os = __shfl_xor_sync(0xffffffffu, s, 16);
    float oa = __shfl_xor_sync(0xffffffffu, acc, 16);
    float nm = fmaxf(m, om);
    float e1 = __expf(m - nm);
    float e2 = __expf(om - nm);
    s = s * e1 + os * e2;
    acc = acc * e1 + oa * e2;

    float inv = 1.f / (s + 1e-16f);
    float val = acc * inv + b2[c];

    float mx = val;
    #pragma unroll
    for (int o = 8; o > 0; o >>= 1) mx = fmaxf(mx, __shfl_xor_sync(0xffffffffu, mx, o));
    float se = __expf(val - mx);
    #pragma unroll
    for (int o = 8; o > 0; o >>= 1) se += __shfl_xor_sync(0xffffffffu, se, o);
    float ls = val - mx - __logf(se);
    if (lane < 16) out[(size_t)dst * 16 + c] = ls;
}

// ================= launch =================
extern "C" void kernel_launch(void* const* d_in, const int* in_sizes, int n_in,
                              void* d_out, int out_size) {
    const float* x    = (const float*)d_in[0];
    const int*   ei   = (const int*)d_in[1];
    const float* W1   = (const float*)d_in[2];
    const float* at1s = (const float*)d_in[3];
    const float* at1d = (const float*)d_in[4];
    const float* b1   = (const float*)d_in[5];
    const float* W2   = (const float*)d_in[6];
    const float* at2s = (const float*)d_in[7];
    const float* at2d = (const float*)d_in[8];
    const float* b2   = (const float*)d_in[9];
    float* out = (float*)d_out;

    int E = in_sizes[1] / 2;

    static float *p_as1 = nullptr, *p_ad1, *p_out1, *p_as2, *p_ad2;
    static __half2* p_h1h;
    static __half* p_h2h;
    static int *p_cnt, *p_rowptr, *p_cursor, *p_col;
    static cudaStream_t s2 = nullptr;
    static cudaEvent_t evF = nullptr, evJ = nullptr;
    if (!p_as1) {
        cudaGetSymbolAddress((void**)&p_h1h, g_h1h);
        cudaGetSymbolAddress((void**)&p_as1, g_as1);
        cudaGetSymbolAddress((void**)&p_ad1, g_ad1);
        cudaGetSymbolAddress((void**)&p_out1, g_out1);
        cudaGetSymbolAddress((void**)&p_h2h, g_h2h);
        cudaGetSymbolAddress((void**)&p_as2, g_as2);
        cudaGetSymbolAddress((void**)&p_ad2, g_ad2);
        cudaGetSymbolAddress((void**)&p_cnt, g_cnt);
        cudaGetSymbolAddress((void**)&p_rowptr, g_rowptr);
        cudaGetSymbolAddress((void**)&p_cursor, g_cursor);
        cudaGetSymbolAddress((void**)&p_col, g_col);
        cudaStreamCreateWithFlags(&s2, cudaStreamNonBlocking);
        cudaEventCreateWithFlags(&evF, cudaEventDisableTiming);
        cudaEventCreateWithFlags(&evJ, cudaEventDisableTiming);
    }

    const int TB = 256;
    auto blocks = [](int n, int tb) { return (n + tb - 1) / tb; };

    // ---- fork: CSR build on side stream ----
    cudaEventRecord(evF, 0);
    cudaStreamWaitEvent(s2, evF, 0);
    fill_int<<<blocks(NN, TB), TB, 0, s2>>>(p_cnt, 1, NN);
    count_dst<<<blocks((E + 1) / 2, TB), TB, 0, s2>>>(ei, p_cnt, E);
    scan_rowptr<<<1, 1024, 0, s2>>>(p_cnt, p_rowptr, p_cursor);
    scatter_edges<<<blocks((E + NN + 1) / 2, TB), TB, 0, s2>>>(ei, p_cursor, p_col, E);
    cudaEventRecord(evJ, s2);

    // ---- layer 1: fp16 HMMA GEMM with fused att epilogue ----
    {
        dim3 grid(HC1 / 64, (NN + 127) / 128);
        gemm_f16_att<<<grid, 256>>>(x, W1, p_h1h, at1s, at1d, p_as1, p_ad1, NN, NF);
    }

    // ---- join: aggregation needs the CSR ----
    cudaStreamWaitEvent(0, evJ, 0);
    gat_aggregate_l1<<<blocks(NN * 32, TB), TB>>>(p_rowptr, p_col, p_as1, p_ad1, p_h1h, b1, p_out1);

    // ---- layer 2: fused GEMM+att, then fused aggregate+log_softmax ----
    gemm2_att2<<<blocks(NN, 16), 256>>>(p_out1, W2, at2s, at2d, p_h2h, p_as2, p_ad2);
    gat_aggregate_l2_lsm<<<blocks(NN * 32, TB), TB>>>(p_rowptr, p_col, p_as2, p_ad2, p_h2h, b2, out);
}